// round 8
// baseline (speedup 1.0000x reference)
#include <cuda_runtime.h>
#include <math.h>

// ---------------------------------------------------------------------------
// SoftCluster_adaptiveK — round 8 (round 7 + count fix)
//  * 512-thread blocks (16 warps/SM) with capped regs: TLP hides latency
//  * single-row mainloop, group-transpose reduction
//  * log-tree warp combine (4 rounds)
//  * FIX: per-cluster counts taken from lane jl directly (no cross-group sum;
//    groups replicate rv, the R7 cross-sum overcounted counts 4x -> rel_err .75)
// ---------------------------------------------------------------------------

#define D      256
#define KMAX   6
#define GRID1  148
#define T1     512
#define NW1    16
#define TOT_W  (GRID1 * NW1)
#define TOLV   1e-5

typedef unsigned long long u64;

// ---- device scratch (static; no allocation anywhere) ----
__device__ float  g_centers[KMAX * D];
__device__ float  g_prev[KMAX * D];
__device__ float  g_csq[KMAX];
__device__ float  g_w[KMAX];
__device__ float  g_P[GRID1 * KMAX * D];
__device__ float  g_Pc[GRID1 * KMAX];
__device__ double g_shiftp[KMAX];
__device__ float  g_dmin[131072];
__device__ float  g_xsq[131072];
__device__ double g_bsum[GRID1];
__device__ int    g_maxiters;
__device__ int    g_bar_count;
__device__ int    g_bar_phase;

// ---- helpers ----
__device__ __forceinline__ u64 pk2(float lo, float hi) {
    u64 r; asm("mov.b64 %0,{%1,%2};" : "=l"(r) : "f"(lo), "f"(hi)); return r;
}
__device__ __forceinline__ void upk2(u64 v, float& lo, float& hi) {
    asm("mov.b64 {%0,%1},%2;" : "=f"(lo), "=f"(hi) : "l"(v));
}
__device__ __forceinline__ u64 fma2(u64 a, u64 b, u64 c) {
    u64 r; asm("fma.rn.f32x2 %0,%1,%2,%3;" : "=l"(r) : "l"(a), "l"(b), "l"(c)); return r;
}
__device__ __forceinline__ u64 mul2(u64 a, u64 b) {
    u64 r; asm("mul.rn.f32x2 %0,%1,%2;" : "=l"(r) : "l"(a), "l"(b)); return r;
}
__device__ __forceinline__ float wsum(float v) {
    #pragma unroll
    for (int m = 16; m; m >>= 1) v += __shfl_xor_sync(0xffffffffu, v, m);
    return v;
}
__device__ __forceinline__ float wsum8(float v) {
    v += __shfl_xor_sync(0xffffffffu, v, 1);
    v += __shfl_xor_sync(0xffffffffu, v, 2);
    v += __shfl_xor_sync(0xffffffffu, v, 4);
    return v;
}
__device__ __forceinline__ float wmin8(float v) {
    v = fminf(v, __shfl_xor_sync(0xffffffffu, v, 1));
    v = fminf(v, __shfl_xor_sync(0xffffffffu, v, 2));
    v = fminf(v, __shfl_xor_sync(0xffffffffu, v, 4));
    return v;
}
__device__ __forceinline__ float dot4(float4 a, float4 b) {
    return a.x * b.x + a.y * b.y + a.z * b.z + a.w * b.w;
}

// grid barrier: atomic arrival, volatile-load polling with backoff
__device__ __forceinline__ void grid_sync() {
    __syncthreads();
    if (threadIdx.x == 0) {
        __threadfence();
        volatile int* vp = &g_bar_phase;
        int ph = *vp;
        if (atomicAdd(&g_bar_count, 1) == (int)gridDim.x - 1) {
            atomicExch(&g_bar_count, 0);
            __threadfence();
            *vp = ph + 1;
        } else {
            while (*vp == ph) { __nanosleep(32); }
            __threadfence();
        }
    }
    __syncthreads();
}

// ---------------------------------------------------------------------------
// The one kernel.
// ---------------------------------------------------------------------------
template <int K>
__global__ void __launch_bounds__(T1, 1) k_all(
        const float* __restrict__ x,
        const float* __restrict__ logits,
        const float* __restrict__ gumbel,
        const float* __restrict__ uinit,
        const int*   __restrict__ maxit_p,
        float* __restrict__ out_r,
        float* __restrict__ out_c,
        int N) {
    constexpr int NSLOT = (K <= 5) ? 8 : 1;
    __shared__ float4 s_slot[NSLOT][K * 64];
    __shared__ float  s_cntw[NW1][8];
    __shared__ double s_red[T1];
    __shared__ double s_base;
    __shared__ int    s_pick;

    int tid  = threadIdx.x;
    int lane = tid & 31;
    int warp = tid >> 5;
    int bid  = blockIdx.x;
    int jl   = lane & 7;

    // ================= phase 0: block 0 computes weights + center 0 ========
    if (bid == 0) {
        if (tid == 0) {
            g_maxiters = maxit_p[0];
            float l[KMAX]; float m = -3.4e38f;
            for (int j = 0; j < KMAX; j++) { l[j] = logits[j] + gumbel[j]; m = fmaxf(m, l[j]); }
            float s = 0.f, e[KMAX];
            for (int j = 0; j < KMAX; j++) { e[j] = expf(l[j] - m); s += e[j]; }
            for (int j = 0; j < KMAX; j++) g_w[j] = e[j] / s;
        }
        for (int i = tid; i < KMAX * D; i += T1) g_prev[i] = 0.f;
        float f = uinit[0] * (float)N;
        int idx = (int)f;
        if (idx > N - 1) idx = N - 1;
        if (idx < 0) idx = 0;
        if (tid < D) {
            float v = x[(size_t)idx * D + tid];
            g_centers[tid] = v;
            s_red[tid] = (double)v * (double)v;
        }
        __syncthreads();
        for (int s = 128; s; s >>= 1) {
            if (tid < s) s_red[tid] += s_red[tid + s];
            __syncthreads();
        }
        if (tid == 0) g_csq[0] = (float)s_red[0];
    }
    grid_sync();
    int maxit = __ldcg(&g_maxiters);

    // ================= phase 1: xsq + k-means++ init ========================
    int chunk = (N + GRID1 - 1) / GRID1;
    int st = bid * chunk;
    int en = min(st + chunk, N);

    if (K >= 2) {
        for (int i = 1; i < K; i++) {
            const float4* cb = (const float4*)(g_centers + (size_t)(i - 1) * D);
            float4 c0 = __ldcg(cb + lane), c1 = __ldcg(cb + lane + 32);
            float  cs = __ldcg(&g_csq[i - 1]);
            double wsumd = 0.0;
            for (int row = st + warp; row < en; row += NW1) {
                const float4* xr = (const float4*)x + (size_t)row * (D / 4);
                float4 a0 = __ldg(xr + lane);
                float4 a1 = __ldg(xr + lane + 32);
                float dp = dot4(a0, c0) + dot4(a1, c1);
                if (i == 1) {
                    float xs = dot4(a0, a0) + dot4(a1, a1);
                    #pragma unroll
                    for (int m = 16; m; m >>= 1) {
                        dp += __shfl_xor_sync(0xffffffffu, dp, m);
                        xs += __shfl_xor_sync(0xffffffffu, xs, m);
                    }
                    if (lane == 0) {
                        g_xsq[row] = xs;
                        float d = sqrtf(fmaxf(xs + cs - 2.f * dp, 1e-12f));
                        g_dmin[row] = d;
                        wsumd += (double)d;
                    }
                } else {
                    dp = wsum(dp);
                    if (lane == 0) {
                        float d = sqrtf(fmaxf(g_xsq[row] + cs - 2.f * dp, 1e-12f));
                        float nd = fminf(g_dmin[row], d);
                        g_dmin[row] = nd;
                        wsumd += (double)nd;
                    }
                }
            }
            if (lane == 0) s_red[warp] = wsumd;
            __syncthreads();
            if (tid == 0) {
                double s = 0.0;
                #pragma unroll
                for (int w = 0; w < NW1; w++) s += s_red[w];
                g_bsum[bid] = s;
            }
            grid_sync();

            // ---- select (block 0 only) ----
            if (bid == 0) {
                // level 1: scan 148 block sums (pad to 256)
                double v = (tid < GRID1) ? __ldcg(&g_bsum[tid]) : 0.0;
                if (tid < 256) s_red[tid] = v;
                __syncthreads();
                for (int off = 1; off < 256; off <<= 1) {
                    double u = (tid >= off && tid < 256) ? s_red[tid - off] : 0.0;
                    __syncthreads();
                    if (tid < 256) s_red[tid] += u;
                    __syncthreads();
                }
                double total  = s_red[255];
                double target = (double)uinit[i] * total;
                if (tid == 0) {
                    s_pick = GRID1 - 1;
                    s_base = total - __ldcg(&g_bsum[GRID1 - 1]);
                }
                __syncthreads();
                if (tid < GRID1) {
                    double incl = s_red[tid], excl = incl - v;
                    if (excl < target && target <= incl) { s_pick = tid; s_base = excl; }
                }
                __syncthreads();
                int    tb    = s_pick;
                double resid = target - s_base;
                int sst = tb * chunk;
                int sen = min(sst + chunk, N);
                __syncthreads();
                // level 2: 2 rows/thread, Hillis-Steele over T1 (covers 1024 rows)
                int r0 = sst + 2 * tid, r1 = r0 + 1;
                double d0 = (r0 < sen) ? (double)__ldcg(&g_dmin[r0]) : 0.0;
                double d1 = (r1 < sen) ? (double)__ldcg(&g_dmin[r1]) : 0.0;
                double pv = d0 + d1;
                s_red[tid] = pv;
                __syncthreads();
                for (int off = 1; off < T1; off <<= 1) {
                    double u = (tid >= off) ? s_red[tid - off] : 0.0;
                    __syncthreads();
                    s_red[tid] += u;
                    __syncthreads();
                }
                if (tid == 0) s_pick = sen - 1 - sst;
                __syncthreads();
                {
                    double incl = s_red[tid], excl = incl - pv;
                    if (excl < resid && resid <= incl) {
                        double c = excl + d0;
                        int f = (c >= resid && r0 < sen) ? r0 : r1;
                        s_pick = f - sst;
                    }
                }
                __syncthreads();
                int idx = sst + s_pick;
                if (idx > N - 1) idx = N - 1;
                if (tid < D) {
                    float cv = __ldg(&x[(size_t)idx * D + tid]);
                    g_centers[i * D + tid] = cv;
                    s_red[tid] = (double)cv * (double)cv;
                }
                __syncthreads();
                for (int s = 128; s; s >>= 1) {
                    if (tid < s) s_red[tid] += s_red[tid + s];
                    __syncthreads();
                }
                if (tid == 0) g_csq[i] = (float)s_red[0];
            }
            grid_sync();
        }
    } else {
        for (int row = st + warp; row < en; row += NW1) {
            const float4* xr = (const float4*)x + (size_t)row * (D / 4);
            float4 a0 = __ldg(xr + lane);
            float4 a1 = __ldg(xr + lane + 32);
            float xs = wsum(dot4(a0, a0) + dot4(a1, a1));
            if (lane == 0) g_xsq[row] = xs;
        }
        grid_sync();
    }

    // ================= maxit < 1 ============================================
    if (maxit < 1) {
        size_t tot = (size_t)N * K;
        for (size_t ii = (size_t)bid * T1 + tid; ii < tot; ii += (size_t)GRID1 * T1)
            out_r[ii] = 0.f;
        if (bid == 0)
            for (int ii = tid; ii < K * D; ii += T1) out_c[ii] = __ldcg(&g_centers[ii]);
        return;
    }

    // ================= phase 2: soft k-means iterations ======================
    float w_l = (jl < K) ? __ldg(&g_w[jl]) : 0.f;

    for (int t = 0; t < maxit; t++) {
        float csq_l = (jl < K) ? __ldcg(&g_csq[jl]) : 0.f;
        u64 c_pk[K][4];
        const float4* cb = (const float4*)g_centers;
        #pragma unroll
        for (int j = 0; j < K; j++) {
            float4 c0 = __ldcg(cb + j * 64 + lane);
            float4 c1 = __ldcg(cb + j * 64 + 32 + lane);
            c_pk[j][0] = pk2(c0.x, c0.y); c_pk[j][1] = pk2(c0.z, c0.w);
            c_pk[j][2] = pk2(c1.x, c1.y); c_pk[j][3] = pk2(c1.z, c1.w);
        }
        u64 acc2[K][4];
        #pragma unroll
        for (int j = 0; j < K; j++) {
            #pragma unroll
            for (int u = 0; u < 4; u++) acc2[j][u] = 0ull;
        }
        float cnt_l = 0.f;

        // ---- single-row mainloop ----
        for (int row = bid * NW1 + warp; row < N; row += TOT_W) {
            const float4* xr = (const float4*)x + (size_t)row * (D / 4);
            float4 a0 = __ldg(xr + lane);
            float4 a1 = __ldg(xr + lane + 32);
            float  xs = __ldg(g_xsq + row);
            u64 p0 = pk2(a0.x, a0.y), p1 = pk2(a0.z, a0.w);
            u64 p2 = pk2(a1.x, a1.y), p3 = pk2(a1.z, a1.w);
            float dp[K];
            #pragma unroll
            for (int j = 0; j < K; j++) {
                u64 tt = mul2(p0, c_pk[j][0]);
                tt = fma2(p1, c_pk[j][1], tt);
                tt = fma2(p2, c_pk[j][2], tt);
                tt = fma2(p3, c_pk[j][3], tt);
                float lo, hi; upk2(tt, lo, hi);
                dp[j] = lo + hi;
            }
            // reduce within 8-lane groups, select own cluster, 2 cross rounds
            #pragma unroll
            for (int m = 4; m; m >>= 1) {
                #pragma unroll
                for (int j = 0; j < K; j++)
                    dp[j] += __shfl_xor_sync(0xffffffffu, dp[j], m);
            }
            float myv = dp[0];
            #pragma unroll
            for (int j = 1; j < K; j++) myv = (jl == j) ? dp[j] : myv;
            myv += __shfl_xor_sync(0xffffffffu, myv, 8);
            myv += __shfl_xor_sync(0xffffffffu, myv, 16);

            float dval = sqrtf(fmaxf(xs + csq_l - 2.f * myv, 1e-12f));
            float dmn  = wmin8((jl < K) ? dval : 3.4e38f);
            float ev   = w_l * __expf(dmn - dval);
            float ssum = wsum8(ev);
            float rv   = __fdividef(ev, ssum);
            if (lane < K) out_r[(size_t)row * K + lane] = rv;
            cnt_l += rv;   // lane j (j<8) accumulates cluster j's count for this warp
            #pragma unroll
            for (int j = 0; j < K; j++) {
                float rb = __shfl_sync(0xffffffffu, rv, j);
                u64 r2 = pk2(rb, rb);
                acc2[j][0] = fma2(r2, p0, acc2[j][0]);
                acc2[j][1] = fma2(r2, p1, acc2[j][1]);
                acc2[j][2] = fma2(r2, p2, acc2[j][2]);
                acc2[j][3] = fma2(r2, p3, acc2[j][3]);
            }
        }

        // ---- per-cluster count partials: lane jl holds the full warp count
        //      (groups 8/16/24 replicate it; take group 0 only — NO cross sum)
        if (lane < 8) s_cntw[warp][lane] = cnt_l;

        // ---- unpack accumulators to floats ----
        float a[K][8];
        #pragma unroll
        for (int j = 0; j < K; j++) {
            upk2(acc2[j][0], a[j][0], a[j][1]);
            upk2(acc2[j][1], a[j][2], a[j][3]);
            upk2(acc2[j][2], a[j][4], a[j][5]);
            upk2(acc2[j][3], a[j][6], a[j][7]);
        }

        // ---- combine warps ----
        if (K <= 5) {
            // log-tree: 16 -> 8 -> 4 -> 2 -> 1 (deterministic pairing)
            #pragma unroll
            for (int step = 8; step >= 1; step >>= 1) {
                if (warp >= step && warp < 2 * step) {
                    float4* dst = s_slot[warp - step];
                    #pragma unroll
                    for (int j = 0; j < K; j++) {
                        dst[j * 64 + lane]      = make_float4(a[j][0], a[j][1], a[j][2], a[j][3]);
                        dst[j * 64 + 32 + lane] = make_float4(a[j][4], a[j][5], a[j][6], a[j][7]);
                    }
                }
                __syncthreads();
                if (warp < step) {
                    const float4* src = s_slot[warp];
                    #pragma unroll
                    for (int j = 0; j < K; j++) {
                        float4 v0 = src[j * 64 + lane];
                        float4 v1 = src[j * 64 + 32 + lane];
                        a[j][0] += v0.x; a[j][1] += v0.y; a[j][2] += v0.z; a[j][3] += v0.w;
                        a[j][4] += v1.x; a[j][5] += v1.y; a[j][6] += v1.z; a[j][7] += v1.w;
                    }
                }
                __syncthreads();
            }
            if (warp == 0) {
                float4* Pb = (float4*)(g_P + (size_t)bid * (KMAX * D));
                #pragma unroll
                for (int j = 0; j < K; j++) {
                    Pb[j * 64 + lane]      = make_float4(a[j][0], a[j][1], a[j][2], a[j][3]);
                    Pb[j * 64 + 32 + lane] = make_float4(a[j][4], a[j][5], a[j][6], a[j][7]);
                }
            }
        } else {
            // sequential fallback (K == 6)
            for (int i = tid; i < K * 64; i += T1)
                s_slot[0][i] = make_float4(0.f, 0.f, 0.f, 0.f);
            __syncthreads();
            for (int w = 0; w < NW1; w++) {
                if (warp == w) {
                    #pragma unroll
                    for (int j = 0; j < K; j++) {
                        float4 v = s_slot[0][j * 64 + lane];
                        v.x += a[j][0]; v.y += a[j][1]; v.z += a[j][2]; v.w += a[j][3];
                        s_slot[0][j * 64 + lane] = v;
                        v = s_slot[0][j * 64 + 32 + lane];
                        v.x += a[j][4]; v.y += a[j][5]; v.z += a[j][6]; v.w += a[j][7];
                        s_slot[0][j * 64 + 32 + lane] = v;
                    }
                }
                __syncthreads();
            }
            float4* Pb = (float4*)(g_P + (size_t)bid * (KMAX * D));
            for (int i = tid; i < K * 64; i += T1) Pb[i] = s_slot[0][i];
        }
        if (tid < K) {
            float s = 0.f;
            #pragma unroll
            for (int w = 0; w < NW1; w++) s += s_cntw[w][tid];
            g_Pc[bid * KMAX + tid] = s;
        }

        grid_sync();

        // ---- center update: block j < K owns cluster j (2-way split) ----
        if (bid < K) {
            int j = bid;
            double c = (tid < GRID1) ? (double)__ldcg(&g_Pc[tid * KMAX + j]) : 0.0;
            s_red[tid] = c;
            __syncthreads();
            for (int s = 256; s; s >>= 1) {
                if (tid < s) s_red[tid] += s_red[tid + s];
                __syncthreads();
            }
            double cnt = s_red[0];
            __syncthreads();

            int el = tid & 255, half = tid >> 8;
            int e  = j * D + el;
            int pst = half * 74, pen = min(GRID1, pst + 74);
            double su[8];
            #pragma unroll
            for (int u = 0; u < 8; u++) su[u] = 0.0;
            int p = pst;
            for (; p + 8 <= pen; p += 8) {
                #pragma unroll
                for (int u = 0; u < 8; u++)
                    su[u] += (double)__ldcg(&g_P[(size_t)(p + u) * (KMAX * D) + e]);
            }
            for (int u = 0; p < pen; p++, u++)
                su[u] += (double)__ldcg(&g_P[(size_t)p * (KMAX * D) + e]);
            s_red[tid] = ((su[0] + su[1]) + (su[2] + su[3]))
                       + ((su[4] + su[5]) + (su[6] + su[7]));
            __syncthreads();
            double v0 = 0.0, v1 = 0.0;
            if (tid < 256) {
                double sum = s_red[tid] + s_red[tid + 256];
                float ncf = (float)(sum / cnt);
                g_centers[e] = ncf;
                float pvv = g_prev[e];
                g_prev[e] = ncf;
                double df = (double)(ncf - pvv);
                v0 = df * df;
                v1 = (double)ncf * (double)ncf;
            }
            __syncthreads();
            s_red[tid] = v0;
            __syncthreads();
            for (int s = 256; s; s >>= 1) {
                if (tid < s) s_red[tid] += s_red[tid + s];
                __syncthreads();
            }
            if (tid == 0) g_shiftp[j] = s_red[0];
            __syncthreads();
            s_red[tid] = v1;
            __syncthreads();
            for (int s = 256; s; s >>= 1) {
                if (tid < s) s_red[tid] += s_red[tid + s];
                __syncthreads();
            }
            if (tid == 0) g_csq[j] = (float)s_red[0];
        }

        grid_sync();

        double sh = 0.0;
        #pragma unroll
        for (int j = 0; j < K; j++) sh += __ldcg(&g_shiftp[j]);
        if (sqrt(sh) < TOLV) break;
    }

    if (bid == 0)
        for (int i = tid; i < K * D; i += T1) out_c[i] = __ldcg(&g_centers[i]);
}

// ---------------------------------------------------------------------------
extern "C" void kernel_launch(void* const* d_in, const int* in_sizes, int n_in,
                              void* d_out, int out_size) {
    const float* x      = (const float*)d_in[0];
    const float* logits = (const float*)d_in[1];
    const float* gumbel = (const float*)d_in[2];
    const float* uinit  = (const float*)d_in[3];
    const int*   maxit  = (const int*)d_in[4];

    int N = in_sizes[0] / D;
    int k = out_size / (N + D);
    if (k < 1) k = 1;
    if (k > KMAX) k = KMAX;

    float* out_c = (float*)d_out;
    float* out_r = out_c + (size_t)k * D;

    switch (k) {
        case 1: k_all<1><<<GRID1, T1>>>(x, logits, gumbel, uinit, maxit, out_r, out_c, N); break;
        case 2: k_all<2><<<GRID1, T1>>>(x, logits, gumbel, uinit, maxit, out_r, out_c, N); break;
        case 3: k_all<3><<<GRID1, T1>>>(x, logits, gumbel, uinit, maxit, out_r, out_c, N); break;
        case 4: k_all<4><<<GRID1, T1>>>(x, logits, gumbel, uinit, maxit, out_r, out_c, N); break;
        case 5: k_all<5><<<GRID1, T1>>>(x, logits, gumbel, uinit, maxit, out_r, out_c, N); break;
        default: k_all<6><<<GRID1, T1>>>(x, logits, gumbel, uinit, maxit, out_r, out_c, N); break;
    }
}

// round 9
// speedup vs baseline: 1.3299x; 1.3299x over previous
#include <cuda_runtime.h>
#include <math.h>

// ---------------------------------------------------------------------------
// SoftCluster_adaptiveK — round 9
//  = R5's iteration loop (384 thr, 2-row interleave, full butterfly,
//    sequential warp combine, atomic-poll barrier w/ nanosleep)  [498us]
//  + R6's in-kernel init fusion (weights, xsq, kmeans++ dmin/select) [-80us]
//  - R6's tight-spin volatile barrier (caused L2 contention, +85us)
//  - R8's register cap (caused spills, +200us)
// ---------------------------------------------------------------------------

#define D      256
#define KMAX   6
#define GRID1  148
#define T1     384
#define NW1    12
#define TOT_W  (GRID1 * NW1)
#define TOLV   1e-5

typedef unsigned long long u64;

// ---- device scratch (static; no allocation anywhere) ----
__device__ float  g_centers[KMAX * D];
__device__ float  g_prev[KMAX * D];
__device__ float  g_csq[KMAX];
__device__ float  g_w[KMAX];
__device__ float  g_P[GRID1 * KMAX * D];
__device__ float  g_Pc[GRID1 * KMAX];
__device__ double g_shiftp[KMAX];
__device__ float  g_dmin[131072];
__device__ float  g_xsq[131072];
__device__ double g_bsum[GRID1];
__device__ int    g_maxiters;
__device__ int    g_bar_count;
__device__ int    g_bar_phase;

// ---- helpers ----
__device__ __forceinline__ u64 pk2(float lo, float hi) {
    u64 r; asm("mov.b64 %0,{%1,%2};" : "=l"(r) : "f"(lo), "f"(hi)); return r;
}
__device__ __forceinline__ void upk2(u64 v, float& lo, float& hi) {
    asm("mov.b64 {%0,%1},%2;" : "=f"(lo), "=f"(hi) : "l"(v));
}
__device__ __forceinline__ u64 fma2(u64 a, u64 b, u64 c) {
    u64 r; asm("fma.rn.f32x2 %0,%1,%2,%3;" : "=l"(r) : "l"(a), "l"(b), "l"(c)); return r;
}
__device__ __forceinline__ u64 mul2(u64 a, u64 b) {
    u64 r; asm("mul.rn.f32x2 %0,%1,%2;" : "=l"(r) : "l"(a), "l"(b)); return r;
}
__device__ __forceinline__ float wsum(float v) {
    #pragma unroll
    for (int m = 16; m; m >>= 1) v += __shfl_xor_sync(0xffffffffu, v, m);
    return v;
}
__device__ __forceinline__ float wsum8(float v) {
    v += __shfl_xor_sync(0xffffffffu, v, 1);
    v += __shfl_xor_sync(0xffffffffu, v, 2);
    v += __shfl_xor_sync(0xffffffffu, v, 4);
    return v;
}
__device__ __forceinline__ float wmin8(float v) {
    v = fminf(v, __shfl_xor_sync(0xffffffffu, v, 1));
    v = fminf(v, __shfl_xor_sync(0xffffffffu, v, 2));
    v = fminf(v, __shfl_xor_sync(0xffffffffu, v, 4));
    return v;
}
__device__ __forceinline__ float dot4(float4 a, float4 b) {
    return a.x * b.x + a.y * b.y + a.z * b.z + a.w * b.w;
}

// grid barrier — R5's proven version: atomicAdd polling with nanosleep backoff
__device__ __forceinline__ void grid_sync() {
    __syncthreads();
    if (threadIdx.x == 0) {
        __threadfence();
        int ph = atomicAdd(&g_bar_phase, 0);
        if (atomicAdd(&g_bar_count, 1) == (int)gridDim.x - 1) {
            atomicExch(&g_bar_count, 0);
            __threadfence();
            atomicExch(&g_bar_phase, ph + 1);
        } else {
            while (atomicAdd(&g_bar_phase, 0) == ph) { __nanosleep(64); }
            __threadfence();
        }
    }
    __syncthreads();
}

// ---------------------------------------------------------------------------
// The one kernel.
// ---------------------------------------------------------------------------
template <int K>
__global__ void __launch_bounds__(T1, 1) k_all(
        const float* __restrict__ x,
        const float* __restrict__ logits,
        const float* __restrict__ gumbel,
        const float* __restrict__ uinit,
        const int*   __restrict__ maxit_p,
        float* __restrict__ out_r,
        float* __restrict__ out_c,
        int N) {
    __shared__ float4 s_acc4[K * 64];
    __shared__ float  s_cnt[K];
    __shared__ double s_red[T1];
    __shared__ double s_base;
    __shared__ int    s_pick;

    int tid  = threadIdx.x;
    int lane = tid & 31;
    int warp = tid >> 5;
    int bid  = blockIdx.x;

    // ================= phase 0: block 0 computes weights + center 0 ========
    if (bid == 0) {
        if (tid == 0) {
            g_maxiters = maxit_p[0];
            float l[KMAX]; float m = -3.4e38f;
            for (int j = 0; j < KMAX; j++) { l[j] = logits[j] + gumbel[j]; m = fmaxf(m, l[j]); }
            float s = 0.f, e[KMAX];
            for (int j = 0; j < KMAX; j++) { e[j] = expf(l[j] - m); s += e[j]; }
            for (int j = 0; j < KMAX; j++) g_w[j] = e[j] / s;
        }
        for (int i = tid; i < KMAX * D; i += T1) g_prev[i] = 0.f;
        float f = uinit[0] * (float)N;
        int idx = (int)f;
        if (idx > N - 1) idx = N - 1;
        if (idx < 0) idx = 0;
        if (tid < D) {
            float v = x[(size_t)idx * D + tid];
            g_centers[tid] = v;
            s_red[tid] = (double)v * (double)v;
        }
        __syncthreads();
        for (int s = 128; s; s >>= 1) {
            if (tid < s) s_red[tid] += s_red[tid + s];
            __syncthreads();
        }
        if (tid == 0) g_csq[0] = (float)s_red[0];
    }
    grid_sync();
    int maxit = __ldcg(&g_maxiters);

    // ================= phase 1: xsq + k-means++ init ========================
    int chunk = (N + GRID1 - 1) / GRID1;
    int st = bid * chunk;
    int en = min(st + chunk, N);

    if (K >= 2) {
        for (int i = 1; i < K; i++) {
            const float4* cb = (const float4*)(g_centers + (size_t)(i - 1) * D);
            float4 c0 = __ldcg(cb + lane), c1 = __ldcg(cb + lane + 32);
            float  cs = __ldcg(&g_csq[i - 1]);
            double wsumd = 0.0;
            for (int row = st + warp; row < en; row += NW1) {
                const float4* xr = (const float4*)x + (size_t)row * (D / 4);
                float4 a0 = __ldg(xr + lane);
                float4 a1 = __ldg(xr + lane + 32);
                float dp = dot4(a0, c0) + dot4(a1, c1);
                if (i == 1) {
                    float xs = dot4(a0, a0) + dot4(a1, a1);
                    #pragma unroll
                    for (int m = 16; m; m >>= 1) {
                        dp += __shfl_xor_sync(0xffffffffu, dp, m);
                        xs += __shfl_xor_sync(0xffffffffu, xs, m);
                    }
                    if (lane == 0) {
                        g_xsq[row] = xs;
                        float d = sqrtf(fmaxf(xs + cs - 2.f * dp, 1e-12f));
                        g_dmin[row] = d;
                        wsumd += (double)d;
                    }
                } else {
                    dp = wsum(dp);
                    if (lane == 0) {
                        float d = sqrtf(fmaxf(g_xsq[row] + cs - 2.f * dp, 1e-12f));
                        float nd = fminf(g_dmin[row], d);
                        g_dmin[row] = nd;
                        wsumd += (double)nd;
                    }
                }
            }
            if (lane == 0) s_red[warp] = wsumd;
            __syncthreads();
            if (tid == 0) {
                double s = 0.0;
                #pragma unroll
                for (int w = 0; w < NW1; w++) s += s_red[w];
                g_bsum[bid] = s;
            }
            grid_sync();

            // ---- select (block 0 only) ----
            if (bid == 0) {
                // level 1: scan 148 block sums (pad to 256)
                double v = (tid < GRID1) ? __ldcg(&g_bsum[tid]) : 0.0;
                if (tid < 256) s_red[tid] = v;
                __syncthreads();
                for (int off = 1; off < 256; off <<= 1) {
                    double u = (tid >= off && tid < 256) ? s_red[tid - off] : 0.0;
                    __syncthreads();
                    if (tid < 256) s_red[tid] += u;
                    __syncthreads();
                }
                double total  = s_red[255];
                double target = (double)uinit[i] * total;
                if (tid == 0) {
                    s_pick = GRID1 - 1;
                    s_base = total - __ldcg(&g_bsum[GRID1 - 1]);
                }
                __syncthreads();
                if (tid < GRID1) {
                    double incl = s_red[tid], excl = incl - v;
                    if (excl < target && target <= incl) { s_pick = tid; s_base = excl; }
                }
                __syncthreads();
                int    tb    = s_pick;
                double resid = target - s_base;
                int sst = tb * chunk;
                int sen = min(sst + chunk, N);
                __syncthreads();
                // level 2: 2 rows/thread, Hillis-Steele over T1 (covers 768 >= 541)
                int r0 = sst + 2 * tid, r1 = r0 + 1;
                double d0 = (r0 < sen) ? (double)__ldcg(&g_dmin[r0]) : 0.0;
                double d1 = (r1 < sen) ? (double)__ldcg(&g_dmin[r1]) : 0.0;
                double pv = d0 + d1;
                s_red[tid] = pv;
                __syncthreads();
                for (int off = 1; off < T1; off <<= 1) {
                    double u = (tid >= off) ? s_red[tid - off] : 0.0;
                    __syncthreads();
                    s_red[tid] += u;
                    __syncthreads();
                }
                if (tid == 0) s_pick = sen - 1 - sst;
                __syncthreads();
                {
                    double incl = s_red[tid], excl = incl - pv;
                    if (excl < resid && resid <= incl) {
                        double c = excl + d0;
                        int f = (c >= resid && r0 < sen) ? r0 : r1;
                        s_pick = f - sst;
                    }
                }
                __syncthreads();
                int idx = sst + s_pick;
                if (idx > N - 1) idx = N - 1;
                if (tid < D) {
                    float cv = __ldg(&x[(size_t)idx * D + tid]);
                    g_centers[i * D + tid] = cv;
                    s_red[tid] = (double)cv * (double)cv;
                }
                __syncthreads();
                for (int s = 128; s; s >>= 1) {
                    if (tid < s) s_red[tid] += s_red[tid + s];
                    __syncthreads();
                }
                if (tid == 0) g_csq[i] = (float)s_red[0];
            }
            grid_sync();
        }
    } else {
        for (int row = st + warp; row < en; row += NW1) {
            const float4* xr = (const float4*)x + (size_t)row * (D / 4);
            float4 a0 = __ldg(xr + lane);
            float4 a1 = __ldg(xr + lane + 32);
            float xs = wsum(dot4(a0, a0) + dot4(a1, a1));
            if (lane == 0) g_xsq[row] = xs;
        }
        grid_sync();
    }

    // ================= maxit < 1 ============================================
    if (maxit < 1) {
        size_t tot = (size_t)N * K;
        for (size_t ii = (size_t)bid * T1 + tid; ii < tot; ii += (size_t)GRID1 * T1)
            out_r[ii] = 0.f;
        if (bid == 0)
            for (int ii = tid; ii < K * D; ii += T1) out_c[ii] = __ldcg(&g_centers[ii]);
        return;
    }

    // ================= phase 2: soft k-means iterations (R5 loop verbatim) ==
    float w_l = (lane < K) ? __ldg(&g_w[lane]) : 0.f;

    for (int t = 0; t < maxit; t++) {
        float csq_l = (lane < K) ? __ldcg(&g_csq[lane]) : 0.f;
        u64 c_pk[K][4];
        const float4* cb = (const float4*)g_centers;
        #pragma unroll
        for (int j = 0; j < K; j++) {
            float4 c0 = __ldcg(cb + j * 64 + lane);
            float4 c1 = __ldcg(cb + j * 64 + 32 + lane);
            c_pk[j][0] = pk2(c0.x, c0.y); c_pk[j][1] = pk2(c0.z, c0.w);
            c_pk[j][2] = pk2(c1.x, c1.y); c_pk[j][3] = pk2(c1.z, c1.w);
        }
        for (int i = tid; i < K * 64; i += T1) s_acc4[i] = make_float4(0.f, 0.f, 0.f, 0.f);
        if (tid < K) s_cnt[tid] = 0.f;
        __syncthreads();

        u64 acc2[K][4];
        #pragma unroll
        for (int j = 0; j < K; j++) {
            #pragma unroll
            for (int u = 0; u < 4; u++) acc2[j][u] = 0ull;
        }
        float cnt_l = 0.f;

        // ---- main pass: two interleaved rows per step ----
        int row = bid * NW1 + warp;
        while (row + TOT_W < N) {
            int rA = row, rB = row + TOT_W;
            const float4* xA = (const float4*)x + (size_t)rA * (D / 4);
            const float4* xB = (const float4*)x + (size_t)rB * (D / 4);
            float4 a0A = __ldg(xA + lane);
            float4 a0B = __ldg(xB + lane);
            float4 a1A = __ldg(xA + lane + 32);
            float4 a1B = __ldg(xB + lane + 32);
            float  xsA = __ldg(g_xsq + rA);
            float  xsB = __ldg(g_xsq + rB);
            u64 pA0 = pk2(a0A.x, a0A.y), pA1 = pk2(a0A.z, a0A.w);
            u64 pA2 = pk2(a1A.x, a1A.y), pA3 = pk2(a1A.z, a1A.w);
            u64 pB0 = pk2(a0B.x, a0B.y), pB1 = pk2(a0B.z, a0B.w);
            u64 pB2 = pk2(a1B.x, a1B.y), pB3 = pk2(a1B.z, a1B.w);
            float dpA[K], dpB[K];
            #pragma unroll
            for (int j = 0; j < K; j++) {
                u64 tA = mul2(pA0, c_pk[j][0]);
                u64 tB = mul2(pB0, c_pk[j][0]);
                tA = fma2(pA1, c_pk[j][1], tA);
                tB = fma2(pB1, c_pk[j][1], tB);
                tA = fma2(pA2, c_pk[j][2], tA);
                tB = fma2(pB2, c_pk[j][2], tB);
                tA = fma2(pA3, c_pk[j][3], tA);
                tB = fma2(pB3, c_pk[j][3], tB);
                float loA, hiA, loB, hiB;
                upk2(tA, loA, hiA); upk2(tB, loB, hiB);
                dpA[j] = loA + hiA; dpB[j] = loB + hiB;
            }
            #pragma unroll
            for (int m = 16; m; m >>= 1) {
                #pragma unroll
                for (int j = 0; j < K; j++) {
                    dpA[j] += __shfl_xor_sync(0xffffffffu, dpA[j], m);
                    dpB[j] += __shfl_xor_sync(0xffffffffu, dpB[j], m);
                }
            }
            float myA = dpA[0], myB = dpB[0];
            #pragma unroll
            for (int j = 1; j < K; j++) {
                myA = (lane == j) ? dpA[j] : myA;
                myB = (lane == j) ? dpB[j] : myB;
            }
            float dA = sqrtf(fmaxf(xsA + csq_l - 2.f * myA, 1e-12f));
            float dB = sqrtf(fmaxf(xsB + csq_l - 2.f * myB, 1e-12f));
            float mnA = wmin8((lane < K) ? dA : 3.4e38f);
            float mnB = wmin8((lane < K) ? dB : 3.4e38f);
            float eA = w_l * __expf(mnA - dA);
            float eB = w_l * __expf(mnB - dB);
            float sA = wsum8(eA);
            float sB = wsum8(eB);
            float rvA = __fdividef(eA, sA);
            float rvB = __fdividef(eB, sB);
            if (lane < K) {
                out_r[(size_t)rA * K + lane] = rvA;
                out_r[(size_t)rB * K + lane] = rvB;
            }
            cnt_l += rvA + rvB;
            #pragma unroll
            for (int j = 0; j < K; j++) {
                float rbA = __shfl_sync(0xffffffffu, rvA, j);
                float rbB = __shfl_sync(0xffffffffu, rvB, j);
                u64 r2A = pk2(rbA, rbA);
                u64 r2B = pk2(rbB, rbB);
                acc2[j][0] = fma2(r2A, pA0, acc2[j][0]);
                acc2[j][1] = fma2(r2A, pA1, acc2[j][1]);
                acc2[j][2] = fma2(r2A, pA2, acc2[j][2]);
                acc2[j][3] = fma2(r2A, pA3, acc2[j][3]);
                acc2[j][0] = fma2(r2B, pB0, acc2[j][0]);
                acc2[j][1] = fma2(r2B, pB1, acc2[j][1]);
                acc2[j][2] = fma2(r2B, pB2, acc2[j][2]);
                acc2[j][3] = fma2(r2B, pB3, acc2[j][3]);
            }
            row += 2 * TOT_W;
        }
        if (row < N) {  // single-row tail
            const float4* xr = (const float4*)x + (size_t)row * (D / 4);
            float4 a0 = __ldg(xr + lane);
            float4 a1 = __ldg(xr + lane + 32);
            float  xs = __ldg(g_xsq + row);
            u64 p0 = pk2(a0.x, a0.y), p1 = pk2(a0.z, a0.w);
            u64 p2 = pk2(a1.x, a1.y), p3 = pk2(a1.z, a1.w);
            float dp[K];
            #pragma unroll
            for (int j = 0; j < K; j++) {
                u64 tt = mul2(p0, c_pk[j][0]);
                tt = fma2(p1, c_pk[j][1], tt);
                tt = fma2(p2, c_pk[j][2], tt);
                tt = fma2(p3, c_pk[j][3], tt);
                float lo, hi; upk2(tt, lo, hi);
                dp[j] = lo + hi;
            }
            #pragma unroll
            for (int j = 0; j < K; j++) dp[j] = wsum(dp[j]);
            float mydp = dp[0];
            #pragma unroll
            for (int j = 1; j < K; j++) mydp = (lane == j) ? dp[j] : mydp;
            float dval = sqrtf(fmaxf(xs + csq_l - 2.f * mydp, 1e-12f));
            float dmn  = wmin8((lane < K) ? dval : 3.4e38f);
            float ev   = w_l * __expf(dmn - dval);
            float ssum = wsum8(ev);
            float rv   = __fdividef(ev, ssum);
            if (lane < K) out_r[(size_t)row * K + lane] = rv;
            cnt_l += rv;
            #pragma unroll
            for (int j = 0; j < K; j++) {
                float rb = __shfl_sync(0xffffffffu, rv, j);
                u64 r2 = pk2(rb, rb);
                acc2[j][0] = fma2(r2, p0, acc2[j][0]);
                acc2[j][1] = fma2(r2, p1, acc2[j][1]);
                acc2[j][2] = fma2(r2, p2, acc2[j][2]);
                acc2[j][3] = fma2(r2, p3, acc2[j][3]);
            }
        }

        // ---- deterministic sequential warp combine ----
        for (int w = 0; w < NW1; w++) {
            if (warp == w) {
                #pragma unroll
                for (int j = 0; j < K; j++) {
                    float lo0, hi0, lo1, hi1;
                    float4 v = s_acc4[j * 64 + lane];
                    upk2(acc2[j][0], lo0, hi0);
                    upk2(acc2[j][1], lo1, hi1);
                    v.x += lo0; v.y += hi0; v.z += lo1; v.w += hi1;
                    s_acc4[j * 64 + lane] = v;
                    v = s_acc4[j * 64 + 32 + lane];
                    upk2(acc2[j][2], lo0, hi0);
                    upk2(acc2[j][3], lo1, hi1);
                    v.x += lo0; v.y += hi0; v.z += lo1; v.w += hi1;
                    s_acc4[j * 64 + 32 + lane] = v;
                }
                if (lane < K) s_cnt[lane] += cnt_l;
            }
            __syncthreads();
        }
        {
            float4* Pb = (float4*)(g_P + (size_t)bid * (KMAX * D));
            for (int i = tid; i < K * 64; i += T1) Pb[i] = s_acc4[i];
            if (tid < K) g_Pc[bid * KMAX + tid] = s_cnt[tid];
        }

        grid_sync();

        // ---- center update: block j < K owns cluster j ----
        if (bid < K) {
            int j = bid;
            double c = (tid < GRID1) ? (double)__ldcg(&g_Pc[tid * KMAX + j]) : 0.0;
            s_red[tid] = c;
            __syncthreads();
            for (int s = 256; s; s >>= 1) {
                if (tid < s && tid + s < T1) s_red[tid] += s_red[tid + s];
                __syncthreads();
            }
            double cnt = s_red[0];
            __syncthreads();

            double v0 = 0.0, v1 = 0.0;
            if (tid < 256) {
                int e = j * D + tid;
                double su[8];
                #pragma unroll
                for (int u = 0; u < 8; u++) su[u] = 0.0;
                int p = 0;
                for (; p + 8 <= GRID1; p += 8) {
                    #pragma unroll
                    for (int u = 0; u < 8; u++)
                        su[u] += (double)__ldcg(&g_P[(size_t)(p + u) * (KMAX * D) + e]);
                }
                for (int u = 0; p < GRID1; p++, u++)
                    su[u] += (double)__ldcg(&g_P[(size_t)p * (KMAX * D) + e]);
                double sum = ((su[0] + su[1]) + (su[2] + su[3]))
                           + ((su[4] + su[5]) + (su[6] + su[7]));
                float ncf = (float)(sum / cnt);
                g_centers[e] = ncf;
                float pvv = g_prev[e];
                g_prev[e] = ncf;
                double df = (double)(ncf - pvv);
                v0 = df * df;
                v1 = (double)ncf * (double)ncf;
            }
            s_red[tid] = v0;
            __syncthreads();
            for (int s = 256; s; s >>= 1) {
                if (tid < s && tid + s < T1) s_red[tid] += s_red[tid + s];
                __syncthreads();
            }
            if (tid == 0) g_shiftp[j] = s_red[0];
            __syncthreads();
            s_red[tid] = v1;
            __syncthreads();
            for (int s = 256; s; s >>= 1) {
                if (tid < s && tid + s < T1) s_red[tid] += s_red[tid + s];
                __syncthreads();
            }
            if (tid == 0) g_csq[j] = (float)s_red[0];
        }

        grid_sync();

        double sh = 0.0;
        #pragma unroll
        for (int j = 0; j < K; j++) sh += __ldcg(&g_shiftp[j]);
        if (sqrt(sh) < TOLV) break;
    }

    if (bid == 0)
        for (int i = tid; i < K * D; i += T1) out_c[i] = __ldcg(&g_centers[i]);
}

// ---------------------------------------------------------------------------
extern "C" void kernel_launch(void* const* d_in, const int* in_sizes, int n_in,
                              void* d_out, int out_size) {
    const float* x      = (const float*)d_in[0];
    const float* logits = (const float*)d_in[1];
    const float* gumbel = (const float*)d_in[2];
    const float* uinit  = (const float*)d_in[3];
    const int*   maxit  = (const int*)d_in[4];

    int N = in_sizes[0] / D;
    int k = out_size / (N + D);
    if (k < 1) k = 1;
    if (k > KMAX) k = KMAX;

    float* out_c = (float*)d_out;
    float* out_r = out_c + (size_t)k * D;

    switch (k) {
        case 1: k_all<1><<<GRID1, T1>>>(x, logits, gumbel, uinit, maxit, out_r, out_c, N); break;
        case 2: k_all<2><<<GRID1, T1>>>(x, logits, gumbel, uinit, maxit, out_r, out_c, N); break;
        case 3: k_all<3><<<GRID1, T1>>>(x, logits, gumbel, uinit, maxit, out_r, out_c, N); break;
        case 4: k_all<4><<<GRID1, T1>>>(x, logits, gumbel, uinit, maxit, out_r, out_c, N); break;
        case 5: k_all<5><<<GRID1, T1>>>(x, logits, gumbel, uinit, maxit, out_r, out_c, N); break;
        default: k_all<6><<<GRID1, T1>>>(x, logits, gumbel, uinit, maxit, out_r, out_c, N); break;
    }
}

// round 10
// speedup vs baseline: 1.5187x; 1.1420x over previous
#include <cuda_runtime.h>
#include <math.h>

// ---------------------------------------------------------------------------
// SoftCluster_adaptiveK — round 10 (= R5 structure + 3 targeted deltas)
//  * separate wide-grid init launches (592x256) + persistent iteration kernel
//  * iteration mainloop: 2-row interleave + GROUP-TRANSPOSE reduction
//    (R6-vs-R9 isolated this as a win; R8's count fix applied)
//  * k_select: warp-shuffle scans (3 syncs, was ~40)   17.7us -> ~5us
//  * xsq folded into dmin pass 1 (k_xsq launch only for k==1)
// ---------------------------------------------------------------------------

#define D      256
#define KMAX   6
#define GRID1  148
#define T1     384
#define NW1    (T1 / 32)
#define TOT_W  (GRID1 * NW1)
#define DB     592
#define TM     256
#define TOLV   1e-5

typedef unsigned long long u64;

// ---- device scratch (static; no allocation anywhere) ----
__device__ float  g_centers[KMAX * D];
__device__ float  g_prev[KMAX * D];
__device__ float  g_csq[KMAX];
__device__ float  g_w[KMAX];
__device__ float  g_P[GRID1 * KMAX * D];
__device__ float  g_Pc[GRID1 * KMAX];
__device__ double g_shiftp[KMAX];
__device__ float  g_dmin[131072];
__device__ float  g_xsq[131072];
__device__ double g_bsum[DB];
__device__ int    g_maxiters;
__device__ int    g_idx;
__device__ int    g_bar_count;
__device__ int    g_bar_phase;

// ---- helpers ----
__device__ __forceinline__ u64 pk2(float lo, float hi) {
    u64 r; asm("mov.b64 %0,{%1,%2};" : "=l"(r) : "f"(lo), "f"(hi)); return r;
}
__device__ __forceinline__ void upk2(u64 v, float& lo, float& hi) {
    asm("mov.b64 {%0,%1},%2;" : "=f"(lo), "=f"(hi) : "l"(v));
}
__device__ __forceinline__ u64 fma2(u64 a, u64 b, u64 c) {
    u64 r; asm("fma.rn.f32x2 %0,%1,%2,%3;" : "=l"(r) : "l"(a), "l"(b), "l"(c)); return r;
}
__device__ __forceinline__ u64 mul2(u64 a, u64 b) {
    u64 r; asm("mul.rn.f32x2 %0,%1,%2;" : "=l"(r) : "l"(a), "l"(b)); return r;
}
__device__ __forceinline__ float wsum(float v) {
    #pragma unroll
    for (int m = 16; m; m >>= 1) v += __shfl_xor_sync(0xffffffffu, v, m);
    return v;
}
__device__ __forceinline__ float wsum8(float v) {
    v += __shfl_xor_sync(0xffffffffu, v, 1);
    v += __shfl_xor_sync(0xffffffffu, v, 2);
    v += __shfl_xor_sync(0xffffffffu, v, 4);
    return v;
}
__device__ __forceinline__ float wmin8(float v) {
    v = fminf(v, __shfl_xor_sync(0xffffffffu, v, 1));
    v = fminf(v, __shfl_xor_sync(0xffffffffu, v, 2));
    v = fminf(v, __shfl_xor_sync(0xffffffffu, v, 4));
    return v;
}
__device__ __forceinline__ float dot4(float4 a, float4 b) {
    return a.x * b.x + a.y * b.y + a.z * b.z + a.w * b.w;
}

// grid barrier — R5's proven version: atomicAdd polling with nanosleep backoff
__device__ __forceinline__ void grid_sync() {
    __syncthreads();
    if (threadIdx.x == 0) {
        __threadfence();
        int ph = atomicAdd(&g_bar_phase, 0);
        if (atomicAdd(&g_bar_count, 1) == (int)gridDim.x - 1) {
            atomicExch(&g_bar_count, 0);
            __threadfence();
            atomicExch(&g_bar_phase, ph + 1);
        } else {
            while (atomicAdd(&g_bar_phase, 0) == ph) { __nanosleep(64); }
            __threadfence();
        }
    }
    __syncthreads();
}

// ---------------------------------------------------------------------------
__global__ void k_init(const float* __restrict__ x,
                       const float* __restrict__ logits,
                       const float* __restrict__ gumbel,
                       const float* __restrict__ uinit,
                       const int*   __restrict__ maxit,
                       int N) {
    __shared__ double s_sq[256];
    int tid = threadIdx.x;
    if (tid == 0) {
        g_maxiters = maxit[0];
        g_bar_count = 0;
        g_bar_phase = 0;
        float l[KMAX]; float m = -3.4e38f;
        for (int j = 0; j < KMAX; j++) { l[j] = logits[j] + gumbel[j]; m = fmaxf(m, l[j]); }
        float s = 0.f, e[KMAX];
        for (int j = 0; j < KMAX; j++) { e[j] = expf(l[j] - m); s += e[j]; }
        for (int j = 0; j < KMAX; j++) g_w[j] = e[j] / s;
        float f = uinit[0] * (float)N;
        int idx = (int)f;
        if (idx > N - 1) idx = N - 1;
        if (idx < 0) idx = 0;
        g_idx = idx;
    }
    for (int i = tid; i < KMAX * D; i += blockDim.x) g_prev[i] = 0.f;
    __syncthreads();
    int idx = g_idx;
    float v = x[(size_t)idx * D + tid];
    g_centers[tid] = v;
    s_sq[tid] = (double)v * (double)v;
    __syncthreads();
    for (int s = 128; s; s >>= 1) {
        if (tid < s) s_sq[tid] += s_sq[tid + s];
        __syncthreads();
    }
    if (tid == 0) g_csq[0] = (float)s_sq[0];
}

// ---------------------------------------------------------------------------
// xsq only (used when k == 1; for k >= 2 it's folded into dmin pass 1)
// ---------------------------------------------------------------------------
__global__ void __launch_bounds__(TM) k_xsq(const float* __restrict__ x, int N) {
    int tid = threadIdx.x;
    int lane = tid & 31;
    int gwarp = blockIdx.x * (TM / 32) + (tid >> 5);
    int tot = DB * (TM / 32);
    for (int row = gwarp; row < N; row += tot) {
        const float4* xr = (const float4*)x + (size_t)row * (D / 4);
        float4 a0 = __ldg(xr + lane);
        float4 a1 = __ldg(xr + lane + 32);
        float xs = wsum(dot4(a0, a0) + dot4(a1, a1));
        if (lane == 0) g_xsq[row] = xs;
    }
}

// ---------------------------------------------------------------------------
// k-means++ pass over CONTIGUOUS chunk: dmin update + per-block double sum.
// Pass 1 (i==1) also computes and stores xsq.
// ---------------------------------------------------------------------------
__global__ void __launch_bounds__(TM) k_dmin(const float* __restrict__ x, int N, int i) {
    __shared__ float  s_c[D];
    __shared__ float  s_cs;
    __shared__ double s_ws[TM / 32];
    int tid = threadIdx.x;
    if (tid < D) s_c[tid] = g_centers[(i - 1) * D + tid];
    if (tid == 0) s_cs = g_csq[i - 1];
    if (tid < TM / 32) s_ws[tid] = 0.0;
    __syncthreads();
    int lane = tid & 31;
    int warp = tid >> 5;
    int chunk = (N + DB - 1) / DB;
    int st = blockIdx.x * chunk;
    int en = min(st + chunk, N);
    const float4* c4 = (const float4*)s_c;
    float4 c0 = c4[lane], c1 = c4[lane + 32];
    double wsumd = 0.0;
    for (int row = st + warp; row < en; row += TM / 32) {
        const float4* xr = (const float4*)x + (size_t)row * (D / 4);
        float4 a0 = __ldg(xr + lane);
        float4 a1 = __ldg(xr + lane + 32);
        float dp = dot4(a0, c0) + dot4(a1, c1);
        if (i == 1) {
            float xs = dot4(a0, a0) + dot4(a1, a1);
            #pragma unroll
            for (int m = 16; m; m >>= 1) {
                dp += __shfl_xor_sync(0xffffffffu, dp, m);
                xs += __shfl_xor_sync(0xffffffffu, xs, m);
            }
            if (lane == 0) {
                g_xsq[row] = xs;
                float d = sqrtf(fmaxf(xs + s_cs - 2.f * dp, 1e-12f));
                g_dmin[row] = d;
                wsumd += (double)d;
            }
        } else {
            dp = wsum(dp);
            if (lane == 0) {
                float d = sqrtf(fmaxf(g_xsq[row] + s_cs - 2.f * dp, 1e-12f));
                float nd = fminf(g_dmin[row], d);
                g_dmin[row] = nd;
                wsumd += (double)nd;
            }
        }
    }
    if (lane == 0) s_ws[warp] = wsumd;
    __syncthreads();
    if (tid == 0) {
        double s = 0.0;
        #pragma unroll
        for (int w = 0; w < TM / 32; w++) s += s_ws[w];
        g_bsum[blockIdx.x] = s;
    }
}

// ---------------------------------------------------------------------------
// k-means++ select: two-level warp-shuffle scans (3 syncs per level).
// 1024 threads = exactly 32 warps.
// ---------------------------------------------------------------------------
__global__ void k_select(const float* __restrict__ x,
                         const float* __restrict__ uinit,
                         int N, int i) {
    __shared__ double s_wtot[32];
    __shared__ double s_sq[256];
    __shared__ double s_base;
    __shared__ int    s_pick;
    int tid  = threadIdx.x;
    int lane = tid & 31;
    int warp = tid >> 5;
    int chunk = (N + DB - 1) / DB;

    // ---- level 1: inclusive scan of 592 block sums (warp scans) ----
    double v = (tid < DB) ? g_bsum[tid] : 0.0;
    double s = v;
    #pragma unroll
    for (int off = 1; off < 32; off <<= 1) {
        double n = __shfl_up_sync(0xffffffffu, s, off);
        if (lane >= off) s += n;
    }
    if (lane == 31) s_wtot[warp] = s;
    __syncthreads();
    if (warp == 0) {
        double t = s_wtot[lane];
        #pragma unroll
        for (int off = 1; off < 32; off <<= 1) {
            double n = __shfl_up_sync(0xffffffffu, t, off);
            if (lane >= off) t += n;
        }
        s_wtot[lane] = t;
    }
    __syncthreads();
    double incl  = s + (warp ? s_wtot[warp - 1] : 0.0);
    double total = s_wtot[31];
    double target = (double)uinit[i] * total;
    if (tid == 0) { s_pick = DB - 1; s_base = total - g_bsum[DB - 1]; }  // fallback
    __syncthreads();
    if (tid < DB) {
        double excl = incl - v;
        if (excl < target && target <= incl) { s_pick = tid; s_base = excl; }
    }
    __syncthreads();
    int    tb    = s_pick;
    double resid = target - s_base;
    int sst = tb * chunk;
    int sen = min(sst + chunk, N);
    int cnt = sen - sst;
    __syncthreads();

    // ---- level 2: scan rows of target chunk (cnt <= 136 <= 1024) ----
    double dv = (tid < cnt) ? (double)g_dmin[sst + tid] : 0.0;
    double s2 = dv;
    #pragma unroll
    for (int off = 1; off < 32; off <<= 1) {
        double n = __shfl_up_sync(0xffffffffu, s2, off);
        if (lane >= off) s2 += n;
    }
    if (lane == 31) s_wtot[warp] = s2;
    __syncthreads();
    if (warp == 0) {
        double t = s_wtot[lane];
        #pragma unroll
        for (int off = 1; off < 32; off <<= 1) {
            double n = __shfl_up_sync(0xffffffffu, t, off);
            if (lane >= off) t += n;
        }
        s_wtot[lane] = t;
    }
    __syncthreads();
    double incl2 = s2 + (warp ? s_wtot[warp - 1] : 0.0);
    if (tid == 0) s_pick = cnt - 1;   // fallback
    __syncthreads();
    if (tid < cnt) {
        double excl2 = incl2 - dv;
        if (excl2 < resid && resid <= incl2) s_pick = tid;
    }
    __syncthreads();
    int idx = sst + s_pick;
    if (idx > N - 1) idx = N - 1;

    // copy chosen row -> centers[i], compute csq[i]
    if (tid < D) {
        float cv = x[(size_t)idx * D + tid];
        g_centers[i * D + tid] = cv;
        s_sq[tid] = (double)cv * (double)cv;
    }
    __syncthreads();
    for (int sft = 128; sft; sft >>= 1) {
        if (tid < sft) s_sq[tid] += s_sq[tid + sft];
        __syncthreads();
    }
    if (tid == 0) g_csq[i] = (float)s_sq[0];
}

// ---------------------------------------------------------------------------
// Persistent iteration kernel (R5 frame, group-transpose reduction).
// ---------------------------------------------------------------------------
template <int K>
__global__ void __launch_bounds__(T1) k_iter(const float* __restrict__ x,
                                             float* __restrict__ out_r,
                                             float* __restrict__ out_c,
                                             int N) {
    __shared__ float4 s_acc4[K * 64];
    __shared__ float  s_cnt[K];
    __shared__ double s_red[T1];

    int tid  = threadIdx.x;
    int lane = tid & 31;
    int warp = tid >> 5;
    int bid  = blockIdx.x;
    int jl   = lane & 7;
    int maxit = g_maxiters;

    if (maxit < 1) {
        size_t tot = (size_t)N * K;
        for (size_t i = (size_t)bid * T1 + tid; i < tot; i += (size_t)GRID1 * T1)
            out_r[i] = 0.f;
        if (bid == 0)
            for (int i = tid; i < K * D; i += T1) out_c[i] = g_centers[i];
        return;
    }

    float w_l = (jl < K) ? __ldg(&g_w[jl]) : 0.f;

    for (int t = 0; t < maxit; t++) {
        float csq_l = (jl < K) ? __ldcg(&g_csq[jl]) : 0.f;
        u64 c_pk[K][4];
        const float4* cb = (const float4*)g_centers;
        #pragma unroll
        for (int j = 0; j < K; j++) {
            float4 c0 = __ldcg(cb + j * 64 + lane);
            float4 c1 = __ldcg(cb + j * 64 + 32 + lane);
            c_pk[j][0] = pk2(c0.x, c0.y); c_pk[j][1] = pk2(c0.z, c0.w);
            c_pk[j][2] = pk2(c1.x, c1.y); c_pk[j][3] = pk2(c1.z, c1.w);
        }
        for (int i = tid; i < K * 64; i += T1) s_acc4[i] = make_float4(0.f, 0.f, 0.f, 0.f);
        if (tid < K) s_cnt[tid] = 0.f;
        __syncthreads();

        u64 acc2[K][4];
        #pragma unroll
        for (int j = 0; j < K; j++) {
            #pragma unroll
            for (int u = 0; u < 4; u++) acc2[j][u] = 0ull;
        }
        float cnt_l = 0.f;

        // ---- main pass: two interleaved rows, group-transpose reduction ----
        int row = bid * NW1 + warp;
        while (row + TOT_W < N) {
            int rA = row, rB = row + TOT_W;
            const float4* xA = (const float4*)x + (size_t)rA * (D / 4);
            const float4* xB = (const float4*)x + (size_t)rB * (D / 4);
            float4 a0A = __ldg(xA + lane);
            float4 a0B = __ldg(xB + lane);
            float4 a1A = __ldg(xA + lane + 32);
            float4 a1B = __ldg(xB + lane + 32);
            float  xsA = __ldg(g_xsq + rA);
            float  xsB = __ldg(g_xsq + rB);
            u64 pA0 = pk2(a0A.x, a0A.y), pA1 = pk2(a0A.z, a0A.w);
            u64 pA2 = pk2(a1A.x, a1A.y), pA3 = pk2(a1A.z, a1A.w);
            u64 pB0 = pk2(a0B.x, a0B.y), pB1 = pk2(a0B.z, a0B.w);
            u64 pB2 = pk2(a1B.x, a1B.y), pB3 = pk2(a1B.z, a1B.w);
            float dpA[K], dpB[K];
            #pragma unroll
            for (int j = 0; j < K; j++) {
                u64 tA = mul2(pA0, c_pk[j][0]);
                u64 tB = mul2(pB0, c_pk[j][0]);
                tA = fma2(pA1, c_pk[j][1], tA);
                tB = fma2(pB1, c_pk[j][1], tB);
                tA = fma2(pA2, c_pk[j][2], tA);
                tB = fma2(pB2, c_pk[j][2], tB);
                tA = fma2(pA3, c_pk[j][3], tA);
                tB = fma2(pB3, c_pk[j][3], tB);
                float loA, hiA, loB, hiB;
                upk2(tA, loA, hiA); upk2(tB, loB, hiB);
                dpA[j] = loA + hiA; dpB[j] = loB + hiB;
            }
            // 3 rounds within 8-lane groups
            #pragma unroll
            for (int m = 4; m; m >>= 1) {
                #pragma unroll
                for (int j = 0; j < K; j++) {
                    dpA[j] += __shfl_xor_sync(0xffffffffu, dpA[j], m);
                    dpB[j] += __shfl_xor_sync(0xffffffffu, dpB[j], m);
                }
            }
            // lane selects its own cluster (jl), 2 cross-group rounds
            float myA = dpA[0], myB = dpB[0];
            #pragma unroll
            for (int j = 1; j < K; j++) {
                bool p = (jl == j);
                myA = p ? dpA[j] : myA;
                myB = p ? dpB[j] : myB;
            }
            myA += __shfl_xor_sync(0xffffffffu, myA, 8);
            myB += __shfl_xor_sync(0xffffffffu, myB, 8);
            myA += __shfl_xor_sync(0xffffffffu, myA, 16);
            myB += __shfl_xor_sync(0xffffffffu, myB, 16);

            float dA = sqrtf(fmaxf(xsA + csq_l - 2.f * myA, 1e-12f));
            float dB = sqrtf(fmaxf(xsB + csq_l - 2.f * myB, 1e-12f));
            float mnA = wmin8((jl < K) ? dA : 3.4e38f);
            float mnB = wmin8((jl < K) ? dB : 3.4e38f);
            float eA = w_l * __expf(mnA - dA);
            float eB = w_l * __expf(mnB - dB);
            float sA = wsum8(eA);
            float sB = wsum8(eB);
            float rvA = __fdividef(eA, sA);
            float rvB = __fdividef(eB, sB);
            if (lane < K) {
                out_r[(size_t)rA * K + lane] = rvA;
                out_r[(size_t)rB * K + lane] = rvB;
            }
            cnt_l += rvA + rvB;   // valid on lane jl; combine reads lanes <K only
            #pragma unroll
            for (int j = 0; j < K; j++) {
                float rbA = __shfl_sync(0xffffffffu, rvA, j);
                float rbB = __shfl_sync(0xffffffffu, rvB, j);
                u64 r2A = pk2(rbA, rbA);
                u64 r2B = pk2(rbB, rbB);
                acc2[j][0] = fma2(r2A, pA0, acc2[j][0]);
                acc2[j][1] = fma2(r2A, pA1, acc2[j][1]);
                acc2[j][2] = fma2(r2A, pA2, acc2[j][2]);
                acc2[j][3] = fma2(r2A, pA3, acc2[j][3]);
                acc2[j][0] = fma2(r2B, pB0, acc2[j][0]);
                acc2[j][1] = fma2(r2B, pB1, acc2[j][1]);
                acc2[j][2] = fma2(r2B, pB2, acc2[j][2]);
                acc2[j][3] = fma2(r2B, pB3, acc2[j][3]);
            }
            row += 2 * TOT_W;
        }
        if (row < N) {  // single-row tail
            const float4* xr = (const float4*)x + (size_t)row * (D / 4);
            float4 a0 = __ldg(xr + lane);
            float4 a1 = __ldg(xr + lane + 32);
            float  xs = __ldg(g_xsq + row);
            u64 p0 = pk2(a0.x, a0.y), p1 = pk2(a0.z, a0.w);
            u64 p2 = pk2(a1.x, a1.y), p3 = pk2(a1.z, a1.w);
            float dp[K];
            #pragma unroll
            for (int j = 0; j < K; j++) {
                u64 tt = mul2(p0, c_pk[j][0]);
                tt = fma2(p1, c_pk[j][1], tt);
                tt = fma2(p2, c_pk[j][2], tt);
                tt = fma2(p3, c_pk[j][3], tt);
                float lo, hi; upk2(tt, lo, hi);
                dp[j] = lo + hi;
            }
            #pragma unroll
            for (int m = 4; m; m >>= 1) {
                #pragma unroll
                for (int j = 0; j < K; j++)
                    dp[j] += __shfl_xor_sync(0xffffffffu, dp[j], m);
            }
            float myv = dp[0];
            #pragma unroll
            for (int j = 1; j < K; j++) myv = (jl == j) ? dp[j] : myv;
            myv += __shfl_xor_sync(0xffffffffu, myv, 8);
            myv += __shfl_xor_sync(0xffffffffu, myv, 16);
            float dval = sqrtf(fmaxf(xs + csq_l - 2.f * myv, 1e-12f));
            float dmn  = wmin8((jl < K) ? dval : 3.4e38f);
            float ev   = w_l * __expf(dmn - dval);
            float ssum = wsum8(ev);
            float rv   = __fdividef(ev, ssum);
            if (lane < K) out_r[(size_t)row * K + lane] = rv;
            cnt_l += rv;
            #pragma unroll
            for (int j = 0; j < K; j++) {
                float rb = __shfl_sync(0xffffffffu, rv, j);
                u64 r2 = pk2(rb, rb);
                acc2[j][0] = fma2(r2, p0, acc2[j][0]);
                acc2[j][1] = fma2(r2, p1, acc2[j][1]);
                acc2[j][2] = fma2(r2, p2, acc2[j][2]);
                acc2[j][3] = fma2(r2, p3, acc2[j][3]);
            }
        }

        // ---- deterministic sequential warp combine ----
        for (int w = 0; w < NW1; w++) {
            if (warp == w) {
                #pragma unroll
                for (int j = 0; j < K; j++) {
                    float lo0, hi0, lo1, hi1;
                    float4 v = s_acc4[j * 64 + lane];
                    upk2(acc2[j][0], lo0, hi0);
                    upk2(acc2[j][1], lo1, hi1);
                    v.x += lo0; v.y += hi0; v.z += lo1; v.w += hi1;
                    s_acc4[j * 64 + lane] = v;
                    v = s_acc4[j * 64 + 32 + lane];
                    upk2(acc2[j][2], lo0, hi0);
                    upk2(acc2[j][3], lo1, hi1);
                    v.x += lo0; v.y += hi0; v.z += lo1; v.w += hi1;
                    s_acc4[j * 64 + 32 + lane] = v;
                }
                if (lane < K) s_cnt[lane] += cnt_l;
            }
            __syncthreads();
        }
        {
            float4* Pb = (float4*)(g_P + (size_t)bid * (KMAX * D));
            for (int i = tid; i < K * 64; i += T1) Pb[i] = s_acc4[i];
            if (tid < K) g_Pc[bid * KMAX + tid] = s_cnt[tid];
        }

        grid_sync();

        // ---- center update: block j < K owns cluster j ----
        if (bid < K) {
            int j = bid;
            double c = (tid < GRID1) ? (double)__ldcg(&g_Pc[tid * KMAX + j]) : 0.0;
            s_red[tid] = c;
            __syncthreads();
            for (int s = 256; s; s >>= 1) {
                if (tid < s && tid + s < T1) s_red[tid] += s_red[tid + s];
                __syncthreads();
            }
            double cnt = s_red[0];
            __syncthreads();

            double v0 = 0.0, v1 = 0.0;
            if (tid < 256) {
                int e = j * D + tid;
                double su[8];
                #pragma unroll
                for (int u = 0; u < 8; u++) su[u] = 0.0;
                int p = 0;
                for (; p + 8 <= GRID1; p += 8) {
                    #pragma unroll
                    for (int u = 0; u < 8; u++)
                        su[u] += (double)__ldcg(&g_P[(size_t)(p + u) * (KMAX * D) + e]);
                }
                for (int u = 0; p < GRID1; p++, u++)
                    su[u] += (double)__ldcg(&g_P[(size_t)p * (KMAX * D) + e]);
                double sum = ((su[0] + su[1]) + (su[2] + su[3]))
                           + ((su[4] + su[5]) + (su[6] + su[7]));
                float ncf = (float)(sum / cnt);
                g_centers[e] = ncf;
                float pvv = g_prev[e];
                g_prev[e] = ncf;
                double df = (double)(ncf - pvv);
                v0 = df * df;
                v1 = (double)ncf * (double)ncf;
            }
            s_red[tid] = v0;
            __syncthreads();
            for (int s = 256; s; s >>= 1) {
                if (tid < s && tid + s < T1) s_red[tid] += s_red[tid + s];
                __syncthreads();
            }
            if (tid == 0) g_shiftp[j] = s_red[0];
            __syncthreads();
            s_red[tid] = v1;
            __syncthreads();
            for (int s = 256; s; s >>= 1) {
                if (tid < s && tid + s < T1) s_red[tid] += s_red[tid + s];
                __syncthreads();
            }
            if (tid == 0) g_csq[j] = (float)s_red[0];
        }

        grid_sync();

        double sh = 0.0;
        #pragma unroll
        for (int j = 0; j < K; j++) sh += __ldcg(&g_shiftp[j]);
        if (sqrt(sh) < TOLV) break;
    }

    if (bid == 0)
        for (int i = tid; i < K * D; i += T1) out_c[i] = __ldcg(&g_centers[i]);
}

// ---------------------------------------------------------------------------
extern "C" void kernel_launch(void* const* d_in, const int* in_sizes, int n_in,
                              void* d_out, int out_size) {
    const float* x      = (const float*)d_in[0];
    const float* logits = (const float*)d_in[1];
    const float* gumbel = (const float*)d_in[2];
    const float* uinit  = (const float*)d_in[3];
    const int*   maxit  = (const int*)d_in[4];

    int N = in_sizes[0] / D;
    int k = out_size / (N + D);
    if (k < 1) k = 1;
    if (k > KMAX) k = KMAX;

    float* out_c = (float*)d_out;
    float* out_r = out_c + (size_t)k * D;

    k_init<<<1, 256>>>(x, logits, gumbel, uinit, maxit, N);
    if (k == 1) {
        k_xsq<<<DB, TM>>>(x, N);
    } else {
        for (int i = 1; i < k; i++) {
            k_dmin<<<DB, TM>>>(x, N, i);           // pass 1 also fills g_xsq
            k_select<<<1, 1024>>>(x, uinit, N, i);
        }
    }
    switch (k) {
        case 1: k_iter<1><<<GRID1, T1>>>(x, out_r, out_c, N); break;
        case 2: k_iter<2><<<GRID1, T1>>>(x, out_r, out_c, N); break;
        case 3: k_iter<3><<<GRID1, T1>>>(x, out_r, out_c, N); break;
        case 4: k_iter<4><<<GRID1, T1>>>(x, out_r, out_c, N); break;
        case 5: k_iter<5><<<GRID1, T1>>>(x, out_r, out_c, N); break;
        default: k_iter<6><<<GRID1, T1>>>(x, out_r, out_c, N); break;
    }
}

// round 11
// speedup vs baseline: 1.5449x; 1.0173x over previous
#include <cuda_runtime.h>
#include <math.h>

// ---------------------------------------------------------------------------
// SoftCluster_adaptiveK — round 11 (= R10 + 2 deltas)
//  * k_dmin: 2-row interleave (latency-bound at 1 row/warp; issue was 21%)
//  * mainloop: constant-shift softmax (S=24) — algebraically identical to the
//    per-row max-shift (normalization cancels), removes the wmin8 chain
// ---------------------------------------------------------------------------

#define D      256
#define KMAX   6
#define GRID1  148
#define T1     384
#define NW1    (T1 / 32)
#define TOT_W  (GRID1 * NW1)
#define DB     592
#define TM     256
#define TOLV   1e-5
#define ESHIFT 24.0f

typedef unsigned long long u64;

// ---- device scratch (static; no allocation anywhere) ----
__device__ float  g_centers[KMAX * D];
__device__ float  g_prev[KMAX * D];
__device__ float  g_csq[KMAX];
__device__ float  g_w[KMAX];
__device__ float  g_P[GRID1 * KMAX * D];
__device__ float  g_Pc[GRID1 * KMAX];
__device__ double g_shiftp[KMAX];
__device__ float  g_dmin[131072];
__device__ float  g_xsq[131072];
__device__ double g_bsum[DB];
__device__ int    g_maxiters;
__device__ int    g_idx;
__device__ int    g_bar_count;
__device__ int    g_bar_phase;

// ---- helpers ----
__device__ __forceinline__ u64 pk2(float lo, float hi) {
    u64 r; asm("mov.b64 %0,{%1,%2};" : "=l"(r) : "f"(lo), "f"(hi)); return r;
}
__device__ __forceinline__ void upk2(u64 v, float& lo, float& hi) {
    asm("mov.b64 {%0,%1},%2;" : "=f"(lo), "=f"(hi) : "l"(v));
}
__device__ __forceinline__ u64 fma2(u64 a, u64 b, u64 c) {
    u64 r; asm("fma.rn.f32x2 %0,%1,%2,%3;" : "=l"(r) : "l"(a), "l"(b), "l"(c)); return r;
}
__device__ __forceinline__ u64 mul2(u64 a, u64 b) {
    u64 r; asm("mul.rn.f32x2 %0,%1,%2;" : "=l"(r) : "l"(a), "l"(b)); return r;
}
__device__ __forceinline__ float wsum(float v) {
    #pragma unroll
    for (int m = 16; m; m >>= 1) v += __shfl_xor_sync(0xffffffffu, v, m);
    return v;
}
__device__ __forceinline__ float wsum8(float v) {
    v += __shfl_xor_sync(0xffffffffu, v, 1);
    v += __shfl_xor_sync(0xffffffffu, v, 2);
    v += __shfl_xor_sync(0xffffffffu, v, 4);
    return v;
}
__device__ __forceinline__ float dot4(float4 a, float4 b) {
    return a.x * b.x + a.y * b.y + a.z * b.z + a.w * b.w;
}

// grid barrier — atomicAdd polling with nanosleep backoff (R5-proven)
__device__ __forceinline__ void grid_sync() {
    __syncthreads();
    if (threadIdx.x == 0) {
        __threadfence();
        int ph = atomicAdd(&g_bar_phase, 0);
        if (atomicAdd(&g_bar_count, 1) == (int)gridDim.x - 1) {
            atomicExch(&g_bar_count, 0);
            __threadfence();
            atomicExch(&g_bar_phase, ph + 1);
        } else {
            while (atomicAdd(&g_bar_phase, 0) == ph) { __nanosleep(64); }
            __threadfence();
        }
    }
    __syncthreads();
}

// ---------------------------------------------------------------------------
__global__ void k_init(const float* __restrict__ x,
                       const float* __restrict__ logits,
                       const float* __restrict__ gumbel,
                       const float* __restrict__ uinit,
                       const int*   __restrict__ maxit,
                       int N) {
    __shared__ double s_sq[256];
    int tid = threadIdx.x;
    if (tid == 0) {
        g_maxiters = maxit[0];
        g_bar_count = 0;
        g_bar_phase = 0;
        float l[KMAX]; float m = -3.4e38f;
        for (int j = 0; j < KMAX; j++) { l[j] = logits[j] + gumbel[j]; m = fmaxf(m, l[j]); }
        float s = 0.f, e[KMAX];
        for (int j = 0; j < KMAX; j++) { e[j] = expf(l[j] - m); s += e[j]; }
        for (int j = 0; j < KMAX; j++) g_w[j] = e[j] / s;
        float f = uinit[0] * (float)N;
        int idx = (int)f;
        if (idx > N - 1) idx = N - 1;
        if (idx < 0) idx = 0;
        g_idx = idx;
    }
    for (int i = tid; i < KMAX * D; i += blockDim.x) g_prev[i] = 0.f;
    __syncthreads();
    int idx = g_idx;
    float v = x[(size_t)idx * D + tid];
    g_centers[tid] = v;
    s_sq[tid] = (double)v * (double)v;
    __syncthreads();
    for (int s = 128; s; s >>= 1) {
        if (tid < s) s_sq[tid] += s_sq[tid + s];
        __syncthreads();
    }
    if (tid == 0) g_csq[0] = (float)s_sq[0];
}

// ---------------------------------------------------------------------------
// xsq only (used when k == 1; for k >= 2 folded into dmin pass 1)
// ---------------------------------------------------------------------------
__global__ void __launch_bounds__(TM) k_xsq(const float* __restrict__ x, int N) {
    int tid = threadIdx.x;
    int lane = tid & 31;
    int gwarp = blockIdx.x * (TM / 32) + (tid >> 5);
    int tot = DB * (TM / 32);
    for (int row = gwarp; row < N; row += tot) {
        const float4* xr = (const float4*)x + (size_t)row * (D / 4);
        float4 a0 = __ldg(xr + lane);
        float4 a1 = __ldg(xr + lane + 32);
        float xs = wsum(dot4(a0, a0) + dot4(a1, a1));
        if (lane == 0) g_xsq[row] = xs;
    }
}

// ---------------------------------------------------------------------------
// k-means++ pass over CONTIGUOUS chunk, 2-row interleaved.
// Pass 1 (i==1) also computes and stores xsq.
// ---------------------------------------------------------------------------
__global__ void __launch_bounds__(TM) k_dmin(const float* __restrict__ x, int N, int i) {
    __shared__ float  s_c[D];
    __shared__ float  s_cs;
    __shared__ double s_ws[TM / 32];
    int tid = threadIdx.x;
    if (tid < D) s_c[tid] = g_centers[(i - 1) * D + tid];
    if (tid == 0) s_cs = g_csq[i - 1];
    if (tid < TM / 32) s_ws[tid] = 0.0;
    __syncthreads();
    int lane = tid & 31;
    int warp = tid >> 5;
    const int STEP = TM / 32;   // 8 warps per block
    int chunk = (N + DB - 1) / DB;
    int st = blockIdx.x * chunk;
    int en = min(st + chunk, N);
    const float4* c4 = (const float4*)s_c;
    float4 c0 = c4[lane], c1 = c4[lane + 32];
    double wsumd = 0.0;

    int row = st + warp;
    while (row + STEP < en) {
        int rA = row, rB = row + STEP;
        const float4* xA = (const float4*)x + (size_t)rA * (D / 4);
        const float4* xB = (const float4*)x + (size_t)rB * (D / 4);
        float4 a0A = __ldg(xA + lane);
        float4 a0B = __ldg(xB + lane);
        float4 a1A = __ldg(xA + lane + 32);
        float4 a1B = __ldg(xB + lane + 32);
        float dpA = dot4(a0A, c0) + dot4(a1A, c1);
        float dpB = dot4(a0B, c0) + dot4(a1B, c1);
        if (i == 1) {
            float xsA = dot4(a0A, a0A) + dot4(a1A, a1A);
            float xsB = dot4(a0B, a0B) + dot4(a1B, a1B);
            #pragma unroll
            for (int m = 16; m; m >>= 1) {
                dpA += __shfl_xor_sync(0xffffffffu, dpA, m);
                dpB += __shfl_xor_sync(0xffffffffu, dpB, m);
                xsA += __shfl_xor_sync(0xffffffffu, xsA, m);
                xsB += __shfl_xor_sync(0xffffffffu, xsB, m);
            }
            if (lane == 0) {
                g_xsq[rA] = xsA;
                g_xsq[rB] = xsB;
                float dA = sqrtf(fmaxf(xsA + s_cs - 2.f * dpA, 1e-12f));
                float dB = sqrtf(fmaxf(xsB + s_cs - 2.f * dpB, 1e-12f));
                g_dmin[rA] = dA;
                g_dmin[rB] = dB;
                wsumd += (double)dA + (double)dB;
            }
        } else {
            #pragma unroll
            for (int m = 16; m; m >>= 1) {
                dpA += __shfl_xor_sync(0xffffffffu, dpA, m);
                dpB += __shfl_xor_sync(0xffffffffu, dpB, m);
            }
            if (lane == 0) {
                float dA = sqrtf(fmaxf(g_xsq[rA] + s_cs - 2.f * dpA, 1e-12f));
                float dB = sqrtf(fmaxf(g_xsq[rB] + s_cs - 2.f * dpB, 1e-12f));
                float nA = fminf(g_dmin[rA], dA);
                float nB = fminf(g_dmin[rB], dB);
                g_dmin[rA] = nA;
                g_dmin[rB] = nB;
                wsumd += (double)nA + (double)nB;
            }
        }
        row += 2 * STEP;
    }
    if (row < en) {   // single-row tail
        const float4* xr = (const float4*)x + (size_t)row * (D / 4);
        float4 a0 = __ldg(xr + lane);
        float4 a1 = __ldg(xr + lane + 32);
        float dp = dot4(a0, c0) + dot4(a1, c1);
        if (i == 1) {
            float xs = dot4(a0, a0) + dot4(a1, a1);
            #pragma unroll
            for (int m = 16; m; m >>= 1) {
                dp += __shfl_xor_sync(0xffffffffu, dp, m);
                xs += __shfl_xor_sync(0xffffffffu, xs, m);
            }
            if (lane == 0) {
                g_xsq[row] = xs;
                float d = sqrtf(fmaxf(xs + s_cs - 2.f * dp, 1e-12f));
                g_dmin[row] = d;
                wsumd += (double)d;
            }
        } else {
            dp = wsum(dp);
            if (lane == 0) {
                float d = sqrtf(fmaxf(g_xsq[row] + s_cs - 2.f * dp, 1e-12f));
                float nd = fminf(g_dmin[row], d);
                g_dmin[row] = nd;
                wsumd += (double)nd;
            }
        }
    }
    if (lane == 0) s_ws[warp] = wsumd;
    __syncthreads();
    if (tid == 0) {
        double s = 0.0;
        #pragma unroll
        for (int w = 0; w < TM / 32; w++) s += s_ws[w];
        g_bsum[blockIdx.x] = s;
    }
}

// ---------------------------------------------------------------------------
// k-means++ select: two-level warp-shuffle scans (1024 threads = 32 warps).
// ---------------------------------------------------------------------------
__global__ void k_select(const float* __restrict__ x,
                         const float* __restrict__ uinit,
                         int N, int i) {
    __shared__ double s_wtot[32];
    __shared__ double s_sq[256];
    __shared__ double s_base;
    __shared__ int    s_pick;
    int tid  = threadIdx.x;
    int lane = tid & 31;
    int warp = tid >> 5;
    int chunk = (N + DB - 1) / DB;

    // ---- level 1: inclusive scan of 592 block sums ----
    double v = (tid < DB) ? g_bsum[tid] : 0.0;
    double s = v;
    #pragma unroll
    for (int off = 1; off < 32; off <<= 1) {
        double n = __shfl_up_sync(0xffffffffu, s, off);
        if (lane >= off) s += n;
    }
    if (lane == 31) s_wtot[warp] = s;
    __syncthreads();
    if (warp == 0) {
        double t = s_wtot[lane];
        #pragma unroll
        for (int off = 1; off < 32; off <<= 1) {
            double n = __shfl_up_sync(0xffffffffu, t, off);
            if (lane >= off) t += n;
        }
        s_wtot[lane] = t;
    }
    __syncthreads();
    double incl  = s + (warp ? s_wtot[warp - 1] : 0.0);
    double total = s_wtot[31];
    double target = (double)uinit[i] * total;
    if (tid == 0) { s_pick = DB - 1; s_base = total - g_bsum[DB - 1]; }
    __syncthreads();
    if (tid < DB) {
        double excl = incl - v;
        if (excl < target && target <= incl) { s_pick = tid; s_base = excl; }
    }
    __syncthreads();
    int    tb    = s_pick;
    double resid = target - s_base;
    int sst = tb * chunk;
    int sen = min(sst + chunk, N);
    int cnt = sen - sst;
    __syncthreads();

    // ---- level 2: scan rows of target chunk (cnt <= 136) ----
    double dv = (tid < cnt) ? (double)g_dmin[sst + tid] : 0.0;
    double s2 = dv;
    #pragma unroll
    for (int off = 1; off < 32; off <<= 1) {
        double n = __shfl_up_sync(0xffffffffu, s2, off);
        if (lane >= off) s2 += n;
    }
    if (lane == 31) s_wtot[warp] = s2;
    __syncthreads();
    if (warp == 0) {
        double t = s_wtot[lane];
        #pragma unroll
        for (int off = 1; off < 32; off <<= 1) {
            double n = __shfl_up_sync(0xffffffffu, t, off);
            if (lane >= off) t += n;
        }
        s_wtot[lane] = t;
    }
    __syncthreads();
    double incl2 = s2 + (warp ? s_wtot[warp - 1] : 0.0);
    if (tid == 0) s_pick = cnt - 1;
    __syncthreads();
    if (tid < cnt) {
        double excl2 = incl2 - dv;
        if (excl2 < resid && resid <= incl2) s_pick = tid;
    }
    __syncthreads();
    int idx = sst + s_pick;
    if (idx > N - 1) idx = N - 1;

    if (tid < D) {
        float cv = x[(size_t)idx * D + tid];
        g_centers[i * D + tid] = cv;
        s_sq[tid] = (double)cv * (double)cv;
    }
    __syncthreads();
    for (int sft = 128; sft; sft >>= 1) {
        if (tid < sft) s_sq[tid] += s_sq[tid + sft];
        __syncthreads();
    }
    if (tid == 0) g_csq[i] = (float)s_sq[0];
}

// ---------------------------------------------------------------------------
// Persistent iteration kernel (R10 frame + constant-shift softmax).
// ---------------------------------------------------------------------------
template <int K>
__global__ void __launch_bounds__(T1) k_iter(const float* __restrict__ x,
                                             float* __restrict__ out_r,
                                             float* __restrict__ out_c,
                                             int N) {
    __shared__ float4 s_acc4[K * 64];
    __shared__ float  s_cnt[K];
    __shared__ double s_red[T1];

    int tid  = threadIdx.x;
    int lane = tid & 31;
    int warp = tid >> 5;
    int bid  = blockIdx.x;
    int jl   = lane & 7;
    int maxit = g_maxiters;

    if (maxit < 1) {
        size_t tot = (size_t)N * K;
        for (size_t i = (size_t)bid * T1 + tid; i < tot; i += (size_t)GRID1 * T1)
            out_r[i] = 0.f;
        if (bid == 0)
            for (int i = tid; i < K * D; i += T1) out_c[i] = g_centers[i];
        return;
    }

    float w_l = (jl < K) ? __ldg(&g_w[jl]) : 0.f;

    for (int t = 0; t < maxit; t++) {
        float csq_l = (jl < K) ? __ldcg(&g_csq[jl]) : 0.f;
        u64 c_pk[K][4];
        const float4* cb = (const float4*)g_centers;
        #pragma unroll
        for (int j = 0; j < K; j++) {
            float4 c0 = __ldcg(cb + j * 64 + lane);
            float4 c1 = __ldcg(cb + j * 64 + 32 + lane);
            c_pk[j][0] = pk2(c0.x, c0.y); c_pk[j][1] = pk2(c0.z, c0.w);
            c_pk[j][2] = pk2(c1.x, c1.y); c_pk[j][3] = pk2(c1.z, c1.w);
        }
        for (int i = tid; i < K * 64; i += T1) s_acc4[i] = make_float4(0.f, 0.f, 0.f, 0.f);
        if (tid < K) s_cnt[tid] = 0.f;
        __syncthreads();

        u64 acc2[K][4];
        #pragma unroll
        for (int j = 0; j < K; j++) {
            #pragma unroll
            for (int u = 0; u < 4; u++) acc2[j][u] = 0ull;
        }
        float cnt_l = 0.f;

        // ---- main pass: two interleaved rows, group-transpose reduction ----
        int row = bid * NW1 + warp;
        while (row + TOT_W < N) {
            int rA = row, rB = row + TOT_W;
            const float4* xA = (const float4*)x + (size_t)rA * (D / 4);
            const float4* xB = (const float4*)x + (size_t)rB * (D / 4);
            float4 a0A = __ldg(xA + lane);
            float4 a0B = __ldg(xB + lane);
            float4 a1A = __ldg(xA + lane + 32);
            float4 a1B = __ldg(xB + lane + 32);
            float  xsA = __ldg(g_xsq + rA);
            float  xsB = __ldg(g_xsq + rB);
            u64 pA0 = pk2(a0A.x, a0A.y), pA1 = pk2(a0A.z, a0A.w);
            u64 pA2 = pk2(a1A.x, a1A.y), pA3 = pk2(a1A.z, a1A.w);
            u64 pB0 = pk2(a0B.x, a0B.y), pB1 = pk2(a0B.z, a0B.w);
            u64 pB2 = pk2(a1B.x, a1B.y), pB3 = pk2(a1B.z, a1B.w);
            float dpA[K], dpB[K];
            #pragma unroll
            for (int j = 0; j < K; j++) {
                u64 tA = mul2(pA0, c_pk[j][0]);
                u64 tB = mul2(pB0, c_pk[j][0]);
                tA = fma2(pA1, c_pk[j][1], tA);
                tB = fma2(pB1, c_pk[j][1], tB);
                tA = fma2(pA2, c_pk[j][2], tA);
                tB = fma2(pB2, c_pk[j][2], tB);
                tA = fma2(pA3, c_pk[j][3], tA);
                tB = fma2(pB3, c_pk[j][3], tB);
                float loA, hiA, loB, hiB;
                upk2(tA, loA, hiA); upk2(tB, loB, hiB);
                dpA[j] = loA + hiA; dpB[j] = loB + hiB;
            }
            // 3 rounds within 8-lane groups
            #pragma unroll
            for (int m = 4; m; m >>= 1) {
                #pragma unroll
                for (int j = 0; j < K; j++) {
                    dpA[j] += __shfl_xor_sync(0xffffffffu, dpA[j], m);
                    dpB[j] += __shfl_xor_sync(0xffffffffu, dpB[j], m);
                }
            }
            // lane selects its own cluster (jl), 2 cross-group rounds
            float myA = dpA[0], myB = dpB[0];
            #pragma unroll
            for (int j = 1; j < K; j++) {
                bool p = (jl == j);
                myA = p ? dpA[j] : myA;
                myB = p ? dpB[j] : myB;
            }
            myA += __shfl_xor_sync(0xffffffffu, myA, 8);
            myB += __shfl_xor_sync(0xffffffffu, myB, 8);
            myA += __shfl_xor_sync(0xffffffffu, myA, 16);
            myB += __shfl_xor_sync(0xffffffffu, myB, 16);

            float dA = sqrtf(fmaxf(xsA + csq_l - 2.f * myA, 1e-12f));
            float dB = sqrtf(fmaxf(xsB + csq_l - 2.f * myB, 1e-12f));
            // constant-shift softmax: identical after normalization
            float eA = w_l * __expf(ESHIFT - dA);
            float eB = w_l * __expf(ESHIFT - dB);
            float sA = wsum8(eA);
            float sB = wsum8(eB);
            float rvA = __fdividef(eA, sA);
            float rvB = __fdividef(eB, sB);
            if (lane < K) {
                out_r[(size_t)rA * K + lane] = rvA;
                out_r[(size_t)rB * K + lane] = rvB;
            }
            cnt_l += rvA + rvB;
            #pragma unroll
            for (int j = 0; j < K; j++) {
                float rbA = __shfl_sync(0xffffffffu, rvA, j);
                float rbB = __shfl_sync(0xffffffffu, rvB, j);
                u64 r2A = pk2(rbA, rbA);
                u64 r2B = pk2(rbB, rbB);
                acc2[j][0] = fma2(r2A, pA0, acc2[j][0]);
                acc2[j][1] = fma2(r2A, pA1, acc2[j][1]);
                acc2[j][2] = fma2(r2A, pA2, acc2[j][2]);
                acc2[j][3] = fma2(r2A, pA3, acc2[j][3]);
                acc2[j][0] = fma2(r2B, pB0, acc2[j][0]);
                acc2[j][1] = fma2(r2B, pB1, acc2[j][1]);
                acc2[j][2] = fma2(r2B, pB2, acc2[j][2]);
                acc2[j][3] = fma2(r2B, pB3, acc2[j][3]);
            }
            row += 2 * TOT_W;
        }
        if (row < N) {  // single-row tail
            const float4* xr = (const float4*)x + (size_t)row * (D / 4);
            float4 a0 = __ldg(xr + lane);
            float4 a1 = __ldg(xr + lane + 32);
            float  xs = __ldg(g_xsq + row);
            u64 p0 = pk2(a0.x, a0.y), p1 = pk2(a0.z, a0.w);
            u64 p2 = pk2(a1.x, a1.y), p3 = pk2(a1.z, a1.w);
            float dp[K];
            #pragma unroll
            for (int j = 0; j < K; j++) {
                u64 tt = mul2(p0, c_pk[j][0]);
                tt = fma2(p1, c_pk[j][1], tt);
                tt = fma2(p2, c_pk[j][2], tt);
                tt = fma2(p3, c_pk[j][3], tt);
                float lo, hi; upk2(tt, lo, hi);
                dp[j] = lo + hi;
            }
            #pragma unroll
            for (int m = 4; m; m >>= 1) {
                #pragma unroll
                for (int j = 0; j < K; j++)
                    dp[j] += __shfl_xor_sync(0xffffffffu, dp[j], m);
            }
            float myv = dp[0];
            #pragma unroll
            for (int j = 1; j < K; j++) myv = (jl == j) ? dp[j] : myv;
            myv += __shfl_xor_sync(0xffffffffu, myv, 8);
            myv += __shfl_xor_sync(0xffffffffu, myv, 16);
            float dval = sqrtf(fmaxf(xs + csq_l - 2.f * myv, 1e-12f));
            float ev   = w_l * __expf(ESHIFT - dval);
            float ssum = wsum8(ev);
            float rv   = __fdividef(ev, ssum);
            if (lane < K) out_r[(size_t)row * K + lane] = rv;
            cnt_l += rv;
            #pragma unroll
            for (int j = 0; j < K; j++) {
                float rb = __shfl_sync(0xffffffffu, rv, j);
                u64 r2 = pk2(rb, rb);
                acc2[j][0] = fma2(r2, p0, acc2[j][0]);
                acc2[j][1] = fma2(r2, p1, acc2[j][1]);
                acc2[j][2] = fma2(r2, p2, acc2[j][2]);
                acc2[j][3] = fma2(r2, p3, acc2[j][3]);
            }
        }

        // ---- deterministic sequential warp combine ----
        for (int w = 0; w < NW1; w++) {
            if (warp == w) {
                #pragma unroll
                for (int j = 0; j < K; j++) {
                    float lo0, hi0, lo1, hi1;
                    float4 v = s_acc4[j * 64 + lane];
                    upk2(acc2[j][0], lo0, hi0);
                    upk2(acc2[j][1], lo1, hi1);
                    v.x += lo0; v.y += hi0; v.z += lo1; v.w += hi1;
                    s_acc4[j * 64 + lane] = v;
                    v = s_acc4[j * 64 + 32 + lane];
                    upk2(acc2[j][2], lo0, hi0);
                    upk2(acc2[j][3], lo1, hi1);
                    v.x += lo0; v.y += hi0; v.z += lo1; v.w += hi1;
                    s_acc4[j * 64 + 32 + lane] = v;
                }
                if (lane < K) s_cnt[lane] += cnt_l;
            }
            __syncthreads();
        }
        {
            float4* Pb = (float4*)(g_P + (size_t)bid * (KMAX * D));
            for (int i = tid; i < K * 64; i += T1) Pb[i] = s_acc4[i];
            if (tid < K) g_Pc[bid * KMAX + tid] = s_cnt[tid];
        }

        grid_sync();

        // ---- center update: block j < K owns cluster j ----
        if (bid < K) {
            int j = bid;
            double c = (tid < GRID1) ? (double)__ldcg(&g_Pc[tid * KMAX + j]) : 0.0;
            s_red[tid] = c;
            __syncthreads();
            for (int s = 256; s; s >>= 1) {
                if (tid < s && tid + s < T1) s_red[tid] += s_red[tid + s];
                __syncthreads();
            }
            double cnt = s_red[0];
            __syncthreads();

            double v0 = 0.0, v1 = 0.0;
            if (tid < 256) {
                int e = j * D + tid;
                double su[8];
                #pragma unroll
                for (int u = 0; u < 8; u++) su[u] = 0.0;
                int p = 0;
                for (; p + 8 <= GRID1; p += 8) {
                    #pragma unroll
                    for (int u = 0; u < 8; u++)
                        su[u] += (double)__ldcg(&g_P[(size_t)(p + u) * (KMAX * D) + e]);
                }
                for (int u = 0; p < GRID1; p++, u++)
                    su[u] += (double)__ldcg(&g_P[(size_t)p * (KMAX * D) + e]);
                double sum = ((su[0] + su[1]) + (su[2] + su[3]))
                           + ((su[4] + su[5]) + (su[6] + su[7]));
                float ncf = (float)(sum / cnt);
                g_centers[e] = ncf;
                float pvv = g_prev[e];
                g_prev[e] = ncf;
                double df = (double)(ncf - pvv);
                v0 = df * df;
                v1 = (double)ncf * (double)ncf;
            }
            s_red[tid] = v0;
            __syncthreads();
            for (int s = 256; s; s >>= 1) {
                if (tid < s && tid + s < T1) s_red[tid] += s_red[tid + s];
                __syncthreads();
            }
            if (tid == 0) g_shiftp[j] = s_red[0];
            __syncthreads();
            s_red[tid] = v1;
            __syncthreads();
            for (int s = 256; s; s >>= 1) {
                if (tid < s && tid + s < T1) s_red[tid] += s_red[tid + s];
                __syncthreads();
            }
            if (tid == 0) g_csq[j] = (float)s_red[0];
        }

        grid_sync();

        double sh = 0.0;
        #pragma unroll
        for (int j = 0; j < K; j++) sh += __ldcg(&g_shiftp[j]);
        if (sqrt(sh) < TOLV) break;
    }

    if (bid == 0)
        for (int i = tid; i < K * D; i += T1) out_c[i] = __ldcg(&g_centers[i]);
}

// ---------------------------------------------------------------------------
extern "C" void kernel_launch(void* const* d_in, const int* in_sizes, int n_in,
                              void* d_out, int out_size) {
    const float* x      = (const float*)d_in[0];
    const float* logits = (const float*)d_in[1];
    const float* gumbel = (const float*)d_in[2];
    const float* uinit  = (const float*)d_in[3];
    const int*   maxit  = (const int*)d_in[4];

    int N = in_sizes[0] / D;
    int k = out_size / (N + D);
    if (k < 1) k = 1;
    if (k > KMAX) k = KMAX;

    float* out_c = (float*)d_out;
    float* out_r = out_c + (size_t)k * D;

    k_init<<<1, 256>>>(x, logits, gumbel, uinit, maxit, N);
    if (k == 1) {
        k_xsq<<<DB, TM>>>(x, N);
    } else {
        for (int i = 1; i < k; i++) {
            k_dmin<<<DB, TM>>>(x, N, i);           // pass 1 also fills g_xsq
            k_select<<<1, 1024>>>(x, uinit, N, i);
        }
    }
    switch (k) {
        case 1: k_iter<1><<<GRID1, T1>>>(x, out_r, out_c, N); break;
        case 2: k_iter<2><<<GRID1, T1>>>(x, out_r, out_c, N); break;
        case 3: k_iter<3><<<GRID1, T1>>>(x, out_r, out_c, N); break;
        case 4: k_iter<4><<<GRID1, T1>>>(x, out_r, out_c, N); break;
        case 5: k_iter<5><<<GRID1, T1>>>(x, out_r, out_c, N); break;
        default: k_iter<6><<<GRID1, T1>>>(x, out_r, out_c, N); break;
    }
}

// round 12
// speedup vs baseline: 1.6151x; 1.0454x over previous
#include <cuda_runtime.h>
#include <math.h>

// ---------------------------------------------------------------------------
// SoftCluster_adaptiveK — round 12 (= R11 + 3 deltas)
//  * update phase: float4 + 4-way-split g_P reduction (MLP-8), concurrent
//    count reduce, warp-shuffle finishes   (~2.5us -> ~0.6us per iter)
//  * grid barrier: poll with ld.global.cg (read-only) instead of atomic RMW
//  * k_dmin: 4-row interleave (was DRAM-BW-limited at 42% with 2 rows)
// ---------------------------------------------------------------------------

#define D      256
#define KMAX   6
#define GRID1  148
#define T1     384
#define NW1    (T1 / 32)
#define TOT_W  (GRID1 * NW1)
#define DB     592
#define TM     256
#define TOLV   1e-5
#define ESHIFT 24.0f

typedef unsigned long long u64;

// ---- device scratch (static; no allocation anywhere) ----
__device__ float  g_centers[KMAX * D];
__device__ float  g_prev[KMAX * D];
__device__ float  g_csq[KMAX];
__device__ float  g_w[KMAX];
__device__ float  g_P[GRID1 * KMAX * D];
__device__ float  g_Pc[GRID1 * KMAX];
__device__ double g_shiftp[KMAX];
__device__ float  g_dmin[131072];
__device__ float  g_xsq[131072];
__device__ double g_bsum[DB];
__device__ int    g_maxiters;
__device__ int    g_idx;
__device__ int    g_bar_count;
__device__ int    g_bar_phase;

// ---- helpers ----
__device__ __forceinline__ u64 pk2(float lo, float hi) {
    u64 r; asm("mov.b64 %0,{%1,%2};" : "=l"(r) : "f"(lo), "f"(hi)); return r;
}
__device__ __forceinline__ void upk2(u64 v, float& lo, float& hi) {
    asm("mov.b64 {%0,%1},%2;" : "=f"(lo), "=f"(hi) : "l"(v));
}
__device__ __forceinline__ u64 fma2(u64 a, u64 b, u64 c) {
    u64 r; asm("fma.rn.f32x2 %0,%1,%2,%3;" : "=l"(r) : "l"(a), "l"(b), "l"(c)); return r;
}
__device__ __forceinline__ u64 mul2(u64 a, u64 b) {
    u64 r; asm("mul.rn.f32x2 %0,%1,%2;" : "=l"(r) : "l"(a), "l"(b)); return r;
}
__device__ __forceinline__ float wsum(float v) {
    #pragma unroll
    for (int m = 16; m; m >>= 1) v += __shfl_xor_sync(0xffffffffu, v, m);
    return v;
}
__device__ __forceinline__ float wsum8(float v) {
    v += __shfl_xor_sync(0xffffffffu, v, 1);
    v += __shfl_xor_sync(0xffffffffu, v, 2);
    v += __shfl_xor_sync(0xffffffffu, v, 4);
    return v;
}
__device__ __forceinline__ float dot4(float4 a, float4 b) {
    return a.x * b.x + a.y * b.y + a.z * b.z + a.w * b.w;
}
__device__ __forceinline__ int ld_cg_i32(const int* p) {
    int v; asm volatile("ld.global.cg.b32 %0, [%1];" : "=r"(v) : "l"(p)); return v;
}

// grid barrier — atomic arrive, READ-ONLY ld.cg polling with nanosleep backoff
__device__ __forceinline__ void grid_sync() {
    __syncthreads();
    if (threadIdx.x == 0) {
        __threadfence();
        int ph = ld_cg_i32(&g_bar_phase);
        if (atomicAdd(&g_bar_count, 1) == (int)gridDim.x - 1) {
            atomicExch(&g_bar_count, 0);
            __threadfence();
            atomicExch(&g_bar_phase, ph + 1);
        } else {
            while (ld_cg_i32(&g_bar_phase) == ph) { __nanosleep(64); }
            __threadfence();
        }
    }
    __syncthreads();
}

// ---------------------------------------------------------------------------
__global__ void k_init(const float* __restrict__ x,
                       const float* __restrict__ logits,
                       const float* __restrict__ gumbel,
                       const float* __restrict__ uinit,
                       const int*   __restrict__ maxit,
                       int N) {
    __shared__ double s_sq[256];
    int tid = threadIdx.x;
    if (tid == 0) {
        g_maxiters = maxit[0];
        g_bar_count = 0;
        g_bar_phase = 0;
        float l[KMAX]; float m = -3.4e38f;
        for (int j = 0; j < KMAX; j++) { l[j] = logits[j] + gumbel[j]; m = fmaxf(m, l[j]); }
        float s = 0.f, e[KMAX];
        for (int j = 0; j < KMAX; j++) { e[j] = expf(l[j] - m); s += e[j]; }
        for (int j = 0; j < KMAX; j++) g_w[j] = e[j] / s;
        float f = uinit[0] * (float)N;
        int idx = (int)f;
        if (idx > N - 1) idx = N - 1;
        if (idx < 0) idx = 0;
        g_idx = idx;
    }
    for (int i = tid; i < KMAX * D; i += blockDim.x) g_prev[i] = 0.f;
    __syncthreads();
    int idx = g_idx;
    float v = x[(size_t)idx * D + tid];
    g_centers[tid] = v;
    s_sq[tid] = (double)v * (double)v;
    __syncthreads();
    for (int s = 128; s; s >>= 1) {
        if (tid < s) s_sq[tid] += s_sq[tid + s];
        __syncthreads();
    }
    if (tid == 0) g_csq[0] = (float)s_sq[0];
}

// ---------------------------------------------------------------------------
// xsq only (used when k == 1)
// ---------------------------------------------------------------------------
__global__ void __launch_bounds__(TM) k_xsq(const float* __restrict__ x, int N) {
    int tid = threadIdx.x;
    int lane = tid & 31;
    int gwarp = blockIdx.x * (TM / 32) + (tid >> 5);
    int tot = DB * (TM / 32);
    for (int row = gwarp; row < N; row += tot) {
        const float4* xr = (const float4*)x + (size_t)row * (D / 4);
        float4 a0 = __ldg(xr + lane);
        float4 a1 = __ldg(xr + lane + 32);
        float xs = wsum(dot4(a0, a0) + dot4(a1, a1));
        if (lane == 0) g_xsq[row] = xs;
    }
}

// ---------------------------------------------------------------------------
// k-means++ pass over CONTIGUOUS chunk, 4-row interleaved (DRAM-BW driven).
// Pass 1 (i==1) also computes and stores xsq.
// ---------------------------------------------------------------------------
__global__ void __launch_bounds__(TM) k_dmin(const float* __restrict__ x, int N, int i) {
    __shared__ float  s_c[D];
    __shared__ float  s_cs;
    __shared__ double s_ws[TM / 32];
    int tid = threadIdx.x;
    if (tid < D) s_c[tid] = g_centers[(i - 1) * D + tid];
    if (tid == 0) s_cs = g_csq[i - 1];
    if (tid < TM / 32) s_ws[tid] = 0.0;
    __syncthreads();
    int lane = tid & 31;
    int warp = tid >> 5;
    const int STEP = TM / 32;
    int chunk = (N + DB - 1) / DB;
    int st = blockIdx.x * chunk;
    int en = min(st + chunk, N);
    const float4* c4 = (const float4*)s_c;
    float4 c0 = c4[lane], c1 = c4[lane + 32];
    double wsumd = 0.0;

    int row = st + warp;
    while (row + 3 * STEP < en) {
        int r0 = row, r1 = row + STEP, r2 = row + 2 * STEP, r3 = row + 3 * STEP;
        const float4* x0 = (const float4*)x + (size_t)r0 * (D / 4);
        const float4* x1 = (const float4*)x + (size_t)r1 * (D / 4);
        const float4* x2 = (const float4*)x + (size_t)r2 * (D / 4);
        const float4* x3 = (const float4*)x + (size_t)r3 * (D / 4);
        float4 a00 = __ldg(x0 + lane),      a10 = __ldg(x1 + lane);
        float4 a20 = __ldg(x2 + lane),      a30 = __ldg(x3 + lane);
        float4 a01 = __ldg(x0 + lane + 32), a11 = __ldg(x1 + lane + 32);
        float4 a21 = __ldg(x2 + lane + 32), a31 = __ldg(x3 + lane + 32);
        float dp0 = dot4(a00, c0) + dot4(a01, c1);
        float dp1 = dot4(a10, c0) + dot4(a11, c1);
        float dp2 = dot4(a20, c0) + dot4(a21, c1);
        float dp3 = dot4(a30, c0) + dot4(a31, c1);
        if (i == 1) {
            float xs0 = dot4(a00, a00) + dot4(a01, a01);
            float xs1 = dot4(a10, a10) + dot4(a11, a11);
            float xs2 = dot4(a20, a20) + dot4(a21, a21);
            float xs3 = dot4(a30, a30) + dot4(a31, a31);
            #pragma unroll
            for (int m = 16; m; m >>= 1) {
                dp0 += __shfl_xor_sync(0xffffffffu, dp0, m);
                dp1 += __shfl_xor_sync(0xffffffffu, dp1, m);
                dp2 += __shfl_xor_sync(0xffffffffu, dp2, m);
                dp3 += __shfl_xor_sync(0xffffffffu, dp3, m);
                xs0 += __shfl_xor_sync(0xffffffffu, xs0, m);
                xs1 += __shfl_xor_sync(0xffffffffu, xs1, m);
                xs2 += __shfl_xor_sync(0xffffffffu, xs2, m);
                xs3 += __shfl_xor_sync(0xffffffffu, xs3, m);
            }
            if (lane == 0) {
                g_xsq[r0] = xs0; g_xsq[r1] = xs1; g_xsq[r2] = xs2; g_xsq[r3] = xs3;
                float d0 = sqrtf(fmaxf(xs0 + s_cs - 2.f * dp0, 1e-12f));
                float d1 = sqrtf(fmaxf(xs1 + s_cs - 2.f * dp1, 1e-12f));
                float d2 = sqrtf(fmaxf(xs2 + s_cs - 2.f * dp2, 1e-12f));
                float d3 = sqrtf(fmaxf(xs3 + s_cs - 2.f * dp3, 1e-12f));
                g_dmin[r0] = d0; g_dmin[r1] = d1; g_dmin[r2] = d2; g_dmin[r3] = d3;
                wsumd += ((double)d0 + (double)d1) + ((double)d2 + (double)d3);
            }
        } else {
            #pragma unroll
            for (int m = 16; m; m >>= 1) {
                dp0 += __shfl_xor_sync(0xffffffffu, dp0, m);
                dp1 += __shfl_xor_sync(0xffffffffu, dp1, m);
                dp2 += __shfl_xor_sync(0xffffffffu, dp2, m);
                dp3 += __shfl_xor_sync(0xffffffffu, dp3, m);
            }
            if (lane == 0) {
                float d0 = sqrtf(fmaxf(g_xsq[r0] + s_cs - 2.f * dp0, 1e-12f));
                float d1 = sqrtf(fmaxf(g_xsq[r1] + s_cs - 2.f * dp1, 1e-12f));
                float d2 = sqrtf(fmaxf(g_xsq[r2] + s_cs - 2.f * dp2, 1e-12f));
                float d3 = sqrtf(fmaxf(g_xsq[r3] + s_cs - 2.f * dp3, 1e-12f));
                float n0 = fminf(g_dmin[r0], d0);
                float n1 = fminf(g_dmin[r1], d1);
                float n2 = fminf(g_dmin[r2], d2);
                float n3 = fminf(g_dmin[r3], d3);
                g_dmin[r0] = n0; g_dmin[r1] = n1; g_dmin[r2] = n2; g_dmin[r3] = n3;
                wsumd += ((double)n0 + (double)n1) + ((double)n2 + (double)n3);
            }
        }
        row += 4 * STEP;
    }
    while (row < en) {   // row tail (stride STEP)
        const float4* xr = (const float4*)x + (size_t)row * (D / 4);
        float4 a0 = __ldg(xr + lane);
        float4 a1 = __ldg(xr + lane + 32);
        float dp = dot4(a0, c0) + dot4(a1, c1);
        if (i == 1) {
            float xs = dot4(a0, a0) + dot4(a1, a1);
            #pragma unroll
            for (int m = 16; m; m >>= 1) {
                dp += __shfl_xor_sync(0xffffffffu, dp, m);
                xs += __shfl_xor_sync(0xffffffffu, xs, m);
            }
            if (lane == 0) {
                g_xsq[row] = xs;
                float d = sqrtf(fmaxf(xs + s_cs - 2.f * dp, 1e-12f));
                g_dmin[row] = d;
                wsumd += (double)d;
            }
        } else {
            dp = wsum(dp);
            if (lane == 0) {
                float d = sqrtf(fmaxf(g_xsq[row] + s_cs - 2.f * dp, 1e-12f));
                float nd = fminf(g_dmin[row], d);
                g_dmin[row] = nd;
                wsumd += (double)nd;
            }
        }
        row += STEP;
    }
    if (lane == 0) s_ws[warp] = wsumd;
    __syncthreads();
    if (tid == 0) {
        double s = 0.0;
        #pragma unroll
        for (int w = 0; w < TM / 32; w++) s += s_ws[w];
        g_bsum[blockIdx.x] = s;
    }
}

// ---------------------------------------------------------------------------
// k-means++ select: two-level warp-shuffle scans (1024 threads = 32 warps).
// ---------------------------------------------------------------------------
__global__ void k_select(const float* __restrict__ x,
                         const float* __restrict__ uinit,
                         int N, int i) {
    __shared__ double s_wtot[32];
    __shared__ double s_sq[256];
    __shared__ double s_base;
    __shared__ int    s_pick;
    int tid  = threadIdx.x;
    int lane = tid & 31;
    int warp = tid >> 5;
    int chunk = (N + DB - 1) / DB;

    double v = (tid < DB) ? g_bsum[tid] : 0.0;
    double s = v;
    #pragma unroll
    for (int off = 1; off < 32; off <<= 1) {
        double n = __shfl_up_sync(0xffffffffu, s, off);
        if (lane >= off) s += n;
    }
    if (lane == 31) s_wtot[warp] = s;
    __syncthreads();
    if (warp == 0) {
        double t = s_wtot[lane];
        #pragma unroll
        for (int off = 1; off < 32; off <<= 1) {
            double n = __shfl_up_sync(0xffffffffu, t, off);
            if (lane >= off) t += n;
        }
        s_wtot[lane] = t;
    }
    __syncthreads();
    double incl  = s + (warp ? s_wtot[warp - 1] : 0.0);
    double total = s_wtot[31];
    double target = (double)uinit[i] * total;
    if (tid == 0) { s_pick = DB - 1; s_base = total - g_bsum[DB - 1]; }
    __syncthreads();
    if (tid < DB) {
        double excl = incl - v;
        if (excl < target && target <= incl) { s_pick = tid; s_base = excl; }
    }
    __syncthreads();
    int    tb    = s_pick;
    double resid = target - s_base;
    int sst = tb * chunk;
    int sen = min(sst + chunk, N);
    int cnt = sen - sst;
    __syncthreads();

    double dv = (tid < cnt) ? (double)g_dmin[sst + tid] : 0.0;
    double s2 = dv;
    #pragma unroll
    for (int off = 1; off < 32; off <<= 1) {
        double n = __shfl_up_sync(0xffffffffu, s2, off);
        if (lane >= off) s2 += n;
    }
    if (lane == 31) s_wtot[warp] = s2;
    __syncthreads();
    if (warp == 0) {
        double t = s_wtot[lane];
        #pragma unroll
        for (int off = 1; off < 32; off <<= 1) {
            double n = __shfl_up_sync(0xffffffffu, t, off);
            if (lane >= off) t += n;
        }
        s_wtot[lane] = t;
    }
    __syncthreads();
    double incl2 = s2 + (warp ? s_wtot[warp - 1] : 0.0);
    if (tid == 0) s_pick = cnt - 1;
    __syncthreads();
    if (tid < cnt) {
        double excl2 = incl2 - dv;
        if (excl2 < resid && resid <= incl2) s_pick = tid;
    }
    __syncthreads();
    int idx = sst + s_pick;
    if (idx > N - 1) idx = N - 1;

    if (tid < D) {
        float cv = x[(size_t)idx * D + tid];
        g_centers[i * D + tid] = cv;
        s_sq[tid] = (double)cv * (double)cv;
    }
    __syncthreads();
    for (int sft = 128; sft; sft >>= 1) {
        if (tid < sft) s_sq[tid] += s_sq[tid + sft];
        __syncthreads();
    }
    if (tid == 0) g_csq[i] = (float)s_sq[0];
}

// ---------------------------------------------------------------------------
// Persistent iteration kernel (R11 mainloop + parallel update phase).
// ---------------------------------------------------------------------------
template <int K>
__global__ void __launch_bounds__(T1) k_iter(const float* __restrict__ x,
                                             float* __restrict__ out_r,
                                             float* __restrict__ out_c,
                                             int N) {
    __shared__ float4 s_acc4[K * 64];
    __shared__ float  s_cnt[K];
    __shared__ double s_part[4][64][4];   // update: 4 p-groups x 64 elem4 x 4 comps
    __shared__ double s_cntv;
    __shared__ double s_v[128];

    int tid  = threadIdx.x;
    int lane = tid & 31;
    int warp = tid >> 5;
    int bid  = blockIdx.x;
    int jl   = lane & 7;
    int maxit = g_maxiters;

    if (maxit < 1) {
        size_t tot = (size_t)N * K;
        for (size_t i = (size_t)bid * T1 + tid; i < tot; i += (size_t)GRID1 * T1)
            out_r[i] = 0.f;
        if (bid == 0)
            for (int i = tid; i < K * D; i += T1) out_c[i] = g_centers[i];
        return;
    }

    float w_l = (jl < K) ? __ldg(&g_w[jl]) : 0.f;

    for (int t = 0; t < maxit; t++) {
        float csq_l = (jl < K) ? __ldcg(&g_csq[jl]) : 0.f;
        u64 c_pk[K][4];
        const float4* cb = (const float4*)g_centers;
        #pragma unroll
        for (int j = 0; j < K; j++) {
            float4 c0 = __ldcg(cb + j * 64 + lane);
            float4 c1 = __ldcg(cb + j * 64 + 32 + lane);
            c_pk[j][0] = pk2(c0.x, c0.y); c_pk[j][1] = pk2(c0.z, c0.w);
            c_pk[j][2] = pk2(c1.x, c1.y); c_pk[j][3] = pk2(c1.z, c1.w);
        }
        for (int i = tid; i < K * 64; i += T1) s_acc4[i] = make_float4(0.f, 0.f, 0.f, 0.f);
        if (tid < K) s_cnt[tid] = 0.f;
        __syncthreads();

        u64 acc2[K][4];
        #pragma unroll
        for (int j = 0; j < K; j++) {
            #pragma unroll
            for (int u = 0; u < 4; u++) acc2[j][u] = 0ull;
        }
        float cnt_l = 0.f;

        // ---- main pass: two interleaved rows, group-transpose reduction ----
        int row = bid * NW1 + warp;
        while (row + TOT_W < N) {
            int rA = row, rB = row + TOT_W;
            const float4* xA = (const float4*)x + (size_t)rA * (D / 4);
            const float4* xB = (const float4*)x + (size_t)rB * (D / 4);
            float4 a0A = __ldg(xA + lane);
            float4 a0B = __ldg(xB + lane);
            float4 a1A = __ldg(xA + lane + 32);
            float4 a1B = __ldg(xB + lane + 32);
            float  xsA = __ldg(g_xsq + rA);
            float  xsB = __ldg(g_xsq + rB);
            u64 pA0 = pk2(a0A.x, a0A.y), pA1 = pk2(a0A.z, a0A.w);
            u64 pA2 = pk2(a1A.x, a1A.y), pA3 = pk2(a1A.z, a1A.w);
            u64 pB0 = pk2(a0B.x, a0B.y), pB1 = pk2(a0B.z, a0B.w);
            u64 pB2 = pk2(a1B.x, a1B.y), pB3 = pk2(a1B.z, a1B.w);
            float dpA[K], dpB[K];
            #pragma unroll
            for (int j = 0; j < K; j++) {
                u64 tA = mul2(pA0, c_pk[j][0]);
                u64 tB = mul2(pB0, c_pk[j][0]);
                tA = fma2(pA1, c_pk[j][1], tA);
                tB = fma2(pB1, c_pk[j][1], tB);
                tA = fma2(pA2, c_pk[j][2], tA);
                tB = fma2(pB2, c_pk[j][2], tB);
                tA = fma2(pA3, c_pk[j][3], tA);
                tB = fma2(pB3, c_pk[j][3], tB);
                float loA, hiA, loB, hiB;
                upk2(tA, loA, hiA); upk2(tB, loB, hiB);
                dpA[j] = loA + hiA; dpB[j] = loB + hiB;
            }
            #pragma unroll
            for (int m = 4; m; m >>= 1) {
                #pragma unroll
                for (int j = 0; j < K; j++) {
                    dpA[j] += __shfl_xor_sync(0xffffffffu, dpA[j], m);
                    dpB[j] += __shfl_xor_sync(0xffffffffu, dpB[j], m);
                }
            }
            float myA = dpA[0], myB = dpB[0];
            #pragma unroll
            for (int j = 1; j < K; j++) {
                bool p = (jl == j);
                myA = p ? dpA[j] : myA;
                myB = p ? dpB[j] : myB;
            }
            myA += __shfl_xor_sync(0xffffffffu, myA, 8);
            myB += __shfl_xor_sync(0xffffffffu, myB, 8);
            myA += __shfl_xor_sync(0xffffffffu, myA, 16);
            myB += __shfl_xor_sync(0xffffffffu, myB, 16);

            float dA = sqrtf(fmaxf(xsA + csq_l - 2.f * myA, 1e-12f));
            float dB = sqrtf(fmaxf(xsB + csq_l - 2.f * myB, 1e-12f));
            float eA = w_l * __expf(ESHIFT - dA);
            float eB = w_l * __expf(ESHIFT - dB);
            float sA = wsum8(eA);
            float sB = wsum8(eB);
            float rvA = __fdividef(eA, sA);
            float rvB = __fdividef(eB, sB);
            if (lane < K) {
                out_r[(size_t)rA * K + lane] = rvA;
                out_r[(size_t)rB * K + lane] = rvB;
            }
            cnt_l += rvA + rvB;
            #pragma unroll
            for (int j = 0; j < K; j++) {
                float rbA = __shfl_sync(0xffffffffu, rvA, j);
                float rbB = __shfl_sync(0xffffffffu, rvB, j);
                u64 r2A = pk2(rbA, rbA);
                u64 r2B = pk2(rbB, rbB);
                acc2[j][0] = fma2(r2A, pA0, acc2[j][0]);
                acc2[j][1] = fma2(r2A, pA1, acc2[j][1]);
                acc2[j][2] = fma2(r2A, pA2, acc2[j][2]);
                acc2[j][3] = fma2(r2A, pA3, acc2[j][3]);
                acc2[j][0] = fma2(r2B, pB0, acc2[j][0]);
                acc2[j][1] = fma2(r2B, pB1, acc2[j][1]);
                acc2[j][2] = fma2(r2B, pB2, acc2[j][2]);
                acc2[j][3] = fma2(r2B, pB3, acc2[j][3]);
            }
            row += 2 * TOT_W;
        }
        if (row < N) {  // single-row tail
            const float4* xr = (const float4*)x + (size_t)row * (D / 4);
            float4 a0 = __ldg(xr + lane);
            float4 a1 = __ldg(xr + lane + 32);
            float  xs = __ldg(g_xsq + row);
            u64 p0 = pk2(a0.x, a0.y), p1 = pk2(a0.z, a0.w);
            u64 p2 = pk2(a1.x, a1.y), p3 = pk2(a1.z, a1.w);
            float dp[K];
            #pragma unroll
            for (int j = 0; j < K; j++) {
                u64 tt = mul2(p0, c_pk[j][0]);
                tt = fma2(p1, c_pk[j][1], tt);
                tt = fma2(p2, c_pk[j][2], tt);
                tt = fma2(p3, c_pk[j][3], tt);
                float lo, hi; upk2(tt, lo, hi);
                dp[j] = lo + hi;
            }
            #pragma unroll
            for (int m = 4; m; m >>= 1) {
                #pragma unroll
                for (int j = 0; j < K; j++)
                    dp[j] += __shfl_xor_sync(0xffffffffu, dp[j], m);
            }
            float myv = dp[0];
            #pragma unroll
            for (int j = 1; j < K; j++) myv = (jl == j) ? dp[j] : myv;
            myv += __shfl_xor_sync(0xffffffffu, myv, 8);
            myv += __shfl_xor_sync(0xffffffffu, myv, 16);
            float dval = sqrtf(fmaxf(xs + csq_l - 2.f * myv, 1e-12f));
            float ev   = w_l * __expf(ESHIFT - dval);
            float ssum = wsum8(ev);
            float rv   = __fdividef(ev, ssum);
            if (lane < K) out_r[(size_t)row * K + lane] = rv;
            cnt_l += rv;
            #pragma unroll
            for (int j = 0; j < K; j++) {
                float rb = __shfl_sync(0xffffffffu, rv, j);
                u64 r2 = pk2(rb, rb);
                acc2[j][0] = fma2(r2, p0, acc2[j][0]);
                acc2[j][1] = fma2(r2, p1, acc2[j][1]);
                acc2[j][2] = fma2(r2, p2, acc2[j][2]);
                acc2[j][3] = fma2(r2, p3, acc2[j][3]);
            }
        }

        // ---- deterministic sequential warp combine ----
        for (int w = 0; w < NW1; w++) {
            if (warp == w) {
                #pragma unroll
                for (int j = 0; j < K; j++) {
                    float lo0, hi0, lo1, hi1;
                    float4 v = s_acc4[j * 64 + lane];
                    upk2(acc2[j][0], lo0, hi0);
                    upk2(acc2[j][1], lo1, hi1);
                    v.x += lo0; v.y += hi0; v.z += lo1; v.w += hi1;
                    s_acc4[j * 64 + lane] = v;
                    v = s_acc4[j * 64 + 32 + lane];
                    upk2(acc2[j][2], lo0, hi0);
                    upk2(acc2[j][3], lo1, hi1);
                    v.x += lo0; v.y += hi0; v.z += lo1; v.w += hi1;
                    s_acc4[j * 64 + 32 + lane] = v;
                }
                if (lane < K) s_cnt[lane] += cnt_l;
            }
            __syncthreads();
        }
        {
            float4* Pb = (float4*)(g_P + (size_t)bid * (KMAX * D));
            for (int i = tid; i < K * 64; i += T1) Pb[i] = s_acc4[i];
            if (tid < K) g_Pc[bid * KMAX + tid] = s_cnt[tid];
        }

        grid_sync();

        // ---- center update: block j < K owns cluster j (parallel version) ----
        if (bid < K) {
            int j = bid;
            // count: warp 8 (threads 256..287), concurrent with P sums
            if (warp == 8) {
                double c = 0.0;
                for (int p = lane; p < GRID1; p += 32)
                    c += (double)__ldcg(&g_Pc[p * KMAX + j]);
                #pragma unroll
                for (int m = 16; m; m >>= 1)
                    c += __shfl_xor_sync(0xffffffffu, c, m);
                if (lane == 0) s_cntv = c;
            }
            // P sums: threads 0..255 = 4 p-groups x 64 float4-elements
            if (tid < 256) {
                int g = tid >> 6, i4 = tid & 63;
                int pst = g * 37;
                int pen = min(GRID1, pst + 37);
                const float4* base = (const float4*)g_P + (size_t)j * (D / 4) + i4;
                const int S4 = KMAX * D / 4;
                double dx = 0.0, dy = 0.0, dz = 0.0, dw = 0.0;
                int p = pst;
                for (; p + 8 <= pen; p += 8) {
                    float4 v0 = __ldcg(base + (size_t)(p + 0) * S4);
                    float4 v1 = __ldcg(base + (size_t)(p + 1) * S4);
                    float4 v2 = __ldcg(base + (size_t)(p + 2) * S4);
                    float4 v3 = __ldcg(base + (size_t)(p + 3) * S4);
                    float4 v4 = __ldcg(base + (size_t)(p + 4) * S4);
                    float4 v5 = __ldcg(base + (size_t)(p + 5) * S4);
                    float4 v6 = __ldcg(base + (size_t)(p + 6) * S4);
                    float4 v7 = __ldcg(base + (size_t)(p + 7) * S4);
                    dx += (((double)v0.x + (double)v1.x) + ((double)v2.x + (double)v3.x))
                        + (((double)v4.x + (double)v5.x) + ((double)v6.x + (double)v7.x));
                    dy += (((double)v0.y + (double)v1.y) + ((double)v2.y + (double)v3.y))
                        + (((double)v4.y + (double)v5.y) + ((double)v6.y + (double)v7.y));
                    dz += (((double)v0.z + (double)v1.z) + ((double)v2.z + (double)v3.z))
                        + (((double)v4.z + (double)v5.z) + ((double)v6.z + (double)v7.z));
                    dw += (((double)v0.w + (double)v1.w) + ((double)v2.w + (double)v3.w))
                        + (((double)v4.w + (double)v5.w) + ((double)v6.w + (double)v7.w));
                }
                for (; p < pen; p++) {
                    float4 v = __ldcg(base + (size_t)p * S4);
                    dx += (double)v.x; dy += (double)v.y;
                    dz += (double)v.z; dw += (double)v.w;
                }
                s_part[g][i4][0] = dx; s_part[g][i4][1] = dy;
                s_part[g][i4][2] = dz; s_part[g][i4][3] = dw;
            }
            __syncthreads();
            if (tid < 64) {
                double cnt = s_cntv;
                double sx = (s_part[0][tid][0] + s_part[1][tid][0])
                          + (s_part[2][tid][0] + s_part[3][tid][0]);
                double sy = (s_part[0][tid][1] + s_part[1][tid][1])
                          + (s_part[2][tid][1] + s_part[3][tid][1]);
                double sz = (s_part[0][tid][2] + s_part[1][tid][2])
                          + (s_part[2][tid][2] + s_part[3][tid][2]);
                double sw = (s_part[0][tid][3] + s_part[1][tid][3])
                          + (s_part[2][tid][3] + s_part[3][tid][3]);
                float n0 = (float)(sx / cnt), n1 = (float)(sy / cnt);
                float n2 = (float)(sz / cnt), n3 = (float)(sw / cnt);
                int e4 = j * (D / 4) + tid;
                ((float4*)g_centers)[e4] = make_float4(n0, n1, n2, n3);
                float4 pv = ((float4*)g_prev)[e4];
                ((float4*)g_prev)[e4] = make_float4(n0, n1, n2, n3);
                double d0 = (double)(n0 - pv.x), d1 = (double)(n1 - pv.y);
                double d2 = (double)(n2 - pv.z), d3 = (double)(n3 - pv.w);
                s_v[tid]      = (d0 * d0 + d1 * d1) + (d2 * d2 + d3 * d3);
                s_v[64 + tid] = ((double)n0 * n0 + (double)n1 * n1)
                              + ((double)n2 * n2 + (double)n3 * n3);
            }
            __syncthreads();
            if (warp == 0) {
                double a = s_v[lane] + s_v[lane + 32];
                #pragma unroll
                for (int m = 16; m; m >>= 1)
                    a += __shfl_xor_sync(0xffffffffu, a, m);
                if (lane == 0) g_shiftp[j] = a;
            } else if (warp == 1) {
                double a = s_v[64 + lane] + s_v[96 + lane];
                #pragma unroll
                for (int m = 16; m; m >>= 1)
                    a += __shfl_xor_sync(0xffffffffu, a, m);
                if (lane == 0) g_csq[j] = (float)a;
            }
        }

        grid_sync();

        double sh = 0.0;
        #pragma unroll
        for (int j = 0; j < K; j++) sh += __ldcg(&g_shiftp[j]);
        if (sqrt(sh) < TOLV) break;
    }

    if (bid == 0)
        for (int i = tid; i < K * D; i += T1) out_c[i] = __ldcg(&g_centers[i]);
}

// ---------------------------------------------------------------------------
extern "C" void kernel_launch(void* const* d_in, const int* in_sizes, int n_in,
                              void* d_out, int out_size) {
    const float* x      = (const float*)d_in[0];
    const float* logits = (const float*)d_in[1];
    const float* gumbel = (const float*)d_in[2];
    const float* uinit  = (const float*)d_in[3];
    const int*   maxit  = (const int*)d_in[4];

    int N = in_sizes[0] / D;
    int k = out_size / (N + D);
    if (k < 1) k = 1;
    if (k > KMAX) k = KMAX;

    float* out_c = (float*)d_out;
    float* out_r = out_c + (size_t)k * D;

    k_init<<<1, 256>>>(x, logits, gumbel, uinit, maxit, N);
    if (k == 1) {
        k_xsq<<<DB, TM>>>(x, N);
    } else {
        for (int i = 1; i < k; i++) {
            k_dmin<<<DB, TM>>>(x, N, i);           // pass 1 also fills g_xsq
            k_select<<<1, 1024>>>(x, uinit, N, i);
        }
    }
    switch (k) {
        case 1: k_iter<1><<<GRID1, T1>>>(x, out_r, out_c, N); break;
        case 2: k_iter<2><<<GRID1, T1>>>(x, out_r, out_c, N); break;
        case 3: k_iter<3><<<GRID1, T1>>>(x, out_r, out_c, N); break;
        case 4: k_iter<4><<<GRID1, T1>>>(x, out_r, out_c, N); break;
        case 5: k_iter<5><<<GRID1, T1>>>(x, out_r, out_c, N); break;
        default: k_iter<6><<<GRID1, T1>>>(x, out_r, out_c, N); break;
    }
}

// round 13
// speedup vs baseline: 1.6359x; 1.0129x over previous
#include <cuda_runtime.h>
#include <math.h>

// ---------------------------------------------------------------------------
// SoftCluster_adaptiveK — round 13 (= R12 + flag-based barrier)
//  * grid barrier replaced by distributed iteration-stamped flags:
//      - each block stamps flag_main[bid] = t+1 (32B-padded, no contention)
//      - ONLY the K updater blocks wait for all 148 main flags
//      - updaters stamp flag_upd[j] = t+1; everyone polls K flags
//    removes the 148-deep atomic serialization (~2us/barrier) of the counter
// ---------------------------------------------------------------------------

#define D      256
#define KMAX   6
#define GRID1  148
#define T1     384
#define NW1    (T1 / 32)
#define TOT_W  (GRID1 * NW1)
#define DB     592
#define TM     256
#define TOLV   1e-5
#define ESHIFT 24.0f
#define FPAD   8

typedef unsigned long long u64;

// ---- device scratch (static; no allocation anywhere) ----
__device__ float  g_centers[KMAX * D];
__device__ float  g_prev[KMAX * D];
__device__ float  g_csq[KMAX];
__device__ float  g_w[KMAX];
__device__ float  g_P[GRID1 * KMAX * D];
__device__ float  g_Pc[GRID1 * KMAX];
__device__ double g_shiftp[KMAX];
__device__ float  g_dmin[131072];
__device__ float  g_xsq[131072];
__device__ double g_bsum[DB];
__device__ int    g_flag_main[GRID1 * FPAD];
__device__ int    g_flag_upd[KMAX * FPAD];
__device__ int    g_maxiters;
__device__ int    g_idx;

// ---- helpers ----
__device__ __forceinline__ u64 pk2(float lo, float hi) {
    u64 r; asm("mov.b64 %0,{%1,%2};" : "=l"(r) : "f"(lo), "f"(hi)); return r;
}
__device__ __forceinline__ void upk2(u64 v, float& lo, float& hi) {
    asm("mov.b64 {%0,%1},%2;" : "=f"(lo), "=f"(hi) : "l"(v));
}
__device__ __forceinline__ u64 fma2(u64 a, u64 b, u64 c) {
    u64 r; asm("fma.rn.f32x2 %0,%1,%2,%3;" : "=l"(r) : "l"(a), "l"(b), "l"(c)); return r;
}
__device__ __forceinline__ u64 mul2(u64 a, u64 b) {
    u64 r; asm("mul.rn.f32x2 %0,%1,%2;" : "=l"(r) : "l"(a), "l"(b)); return r;
}
__device__ __forceinline__ float wsum(float v) {
    #pragma unroll
    for (int m = 16; m; m >>= 1) v += __shfl_xor_sync(0xffffffffu, v, m);
    return v;
}
__device__ __forceinline__ float wsum8(float v) {
    v += __shfl_xor_sync(0xffffffffu, v, 1);
    v += __shfl_xor_sync(0xffffffffu, v, 2);
    v += __shfl_xor_sync(0xffffffffu, v, 4);
    return v;
}
__device__ __forceinline__ float dot4(float4 a, float4 b) {
    return a.x * b.x + a.y * b.y + a.z * b.z + a.w * b.w;
}
__device__ __forceinline__ int ld_cg_i32(const int* p) {
    int v; asm volatile("ld.global.cg.b32 %0, [%1];" : "=r"(v) : "l"(p)); return v;
}
__device__ __forceinline__ void st_cg_i32(int* p, int v) {
    asm volatile("st.global.cg.b32 [%0], %1;" :: "l"(p), "r"(v) : "memory");
}

// ---------------------------------------------------------------------------
__global__ void k_init(const float* __restrict__ x,
                       const float* __restrict__ logits,
                       const float* __restrict__ gumbel,
                       const float* __restrict__ uinit,
                       const int*   __restrict__ maxit,
                       int N) {
    __shared__ double s_sq[256];
    int tid = threadIdx.x;
    if (tid == 0) {
        g_maxiters = maxit[0];
        float l[KMAX]; float m = -3.4e38f;
        for (int j = 0; j < KMAX; j++) { l[j] = logits[j] + gumbel[j]; m = fmaxf(m, l[j]); }
        float s = 0.f, e[KMAX];
        for (int j = 0; j < KMAX; j++) { e[j] = expf(l[j] - m); s += e[j]; }
        for (int j = 0; j < KMAX; j++) g_w[j] = e[j] / s;
        float f = uinit[0] * (float)N;
        int idx = (int)f;
        if (idx > N - 1) idx = N - 1;
        if (idx < 0) idx = 0;
        g_idx = idx;
    }
    for (int i = tid; i < KMAX * D; i += blockDim.x) g_prev[i] = 0.f;
    for (int i = tid; i < GRID1 * FPAD; i += blockDim.x) g_flag_main[i] = 0;
    for (int i = tid; i < KMAX * FPAD; i += blockDim.x) g_flag_upd[i] = 0;
    __syncthreads();
    int idx = g_idx;
    float v = x[(size_t)idx * D + tid];
    g_centers[tid] = v;
    s_sq[tid] = (double)v * (double)v;
    __syncthreads();
    for (int s = 128; s; s >>= 1) {
        if (tid < s) s_sq[tid] += s_sq[tid + s];
        __syncthreads();
    }
    if (tid == 0) g_csq[0] = (float)s_sq[0];
}

// ---------------------------------------------------------------------------
// xsq only (used when k == 1)
// ---------------------------------------------------------------------------
__global__ void __launch_bounds__(TM) k_xsq(const float* __restrict__ x, int N) {
    int tid = threadIdx.x;
    int lane = tid & 31;
    int gwarp = blockIdx.x * (TM / 32) + (tid >> 5);
    int tot = DB * (TM / 32);
    for (int row = gwarp; row < N; row += tot) {
        const float4* xr = (const float4*)x + (size_t)row * (D / 4);
        float4 a0 = __ldg(xr + lane);
        float4 a1 = __ldg(xr + lane + 32);
        float xs = wsum(dot4(a0, a0) + dot4(a1, a1));
        if (lane == 0) g_xsq[row] = xs;
    }
}

// ---------------------------------------------------------------------------
// k-means++ pass over CONTIGUOUS chunk, 4-row interleaved.
// Pass 1 (i==1) also computes and stores xsq.
// ---------------------------------------------------------------------------
__global__ void __launch_bounds__(TM) k_dmin(const float* __restrict__ x, int N, int i) {
    __shared__ float  s_c[D];
    __shared__ float  s_cs;
    __shared__ double s_ws[TM / 32];
    int tid = threadIdx.x;
    if (tid < D) s_c[tid] = g_centers[(i - 1) * D + tid];
    if (tid == 0) s_cs = g_csq[i - 1];
    if (tid < TM / 32) s_ws[tid] = 0.0;
    __syncthreads();
    int lane = tid & 31;
    int warp = tid >> 5;
    const int STEP = TM / 32;
    int chunk = (N + DB - 1) / DB;
    int st = blockIdx.x * chunk;
    int en = min(st + chunk, N);
    const float4* c4 = (const float4*)s_c;
    float4 c0 = c4[lane], c1 = c4[lane + 32];
    double wsumd = 0.0;

    int row = st + warp;
    while (row + 3 * STEP < en) {
        int r0 = row, r1 = row + STEP, r2 = row + 2 * STEP, r3 = row + 3 * STEP;
        const float4* x0 = (const float4*)x + (size_t)r0 * (D / 4);
        const float4* x1 = (const float4*)x + (size_t)r1 * (D / 4);
        const float4* x2 = (const float4*)x + (size_t)r2 * (D / 4);
        const float4* x3 = (const float4*)x + (size_t)r3 * (D / 4);
        float4 a00 = __ldg(x0 + lane),      a10 = __ldg(x1 + lane);
        float4 a20 = __ldg(x2 + lane),      a30 = __ldg(x3 + lane);
        float4 a01 = __ldg(x0 + lane + 32), a11 = __ldg(x1 + lane + 32);
        float4 a21 = __ldg(x2 + lane + 32), a31 = __ldg(x3 + lane + 32);
        float dp0 = dot4(a00, c0) + dot4(a01, c1);
        float dp1 = dot4(a10, c0) + dot4(a11, c1);
        float dp2 = dot4(a20, c0) + dot4(a21, c1);
        float dp3 = dot4(a30, c0) + dot4(a31, c1);
        if (i == 1) {
            float xs0 = dot4(a00, a00) + dot4(a01, a01);
            float xs1 = dot4(a10, a10) + dot4(a11, a11);
            float xs2 = dot4(a20, a20) + dot4(a21, a21);
            float xs3 = dot4(a30, a30) + dot4(a31, a31);
            #pragma unroll
            for (int m = 16; m; m >>= 1) {
                dp0 += __shfl_xor_sync(0xffffffffu, dp0, m);
                dp1 += __shfl_xor_sync(0xffffffffu, dp1, m);
                dp2 += __shfl_xor_sync(0xffffffffu, dp2, m);
                dp3 += __shfl_xor_sync(0xffffffffu, dp3, m);
                xs0 += __shfl_xor_sync(0xffffffffu, xs0, m);
                xs1 += __shfl_xor_sync(0xffffffffu, xs1, m);
                xs2 += __shfl_xor_sync(0xffffffffu, xs2, m);
                xs3 += __shfl_xor_sync(0xffffffffu, xs3, m);
            }
            if (lane == 0) {
                g_xsq[r0] = xs0; g_xsq[r1] = xs1; g_xsq[r2] = xs2; g_xsq[r3] = xs3;
                float d0 = sqrtf(fmaxf(xs0 + s_cs - 2.f * dp0, 1e-12f));
                float d1 = sqrtf(fmaxf(xs1 + s_cs - 2.f * dp1, 1e-12f));
                float d2 = sqrtf(fmaxf(xs2 + s_cs - 2.f * dp2, 1e-12f));
                float d3 = sqrtf(fmaxf(xs3 + s_cs - 2.f * dp3, 1e-12f));
                g_dmin[r0] = d0; g_dmin[r1] = d1; g_dmin[r2] = d2; g_dmin[r3] = d3;
                wsumd += ((double)d0 + (double)d1) + ((double)d2 + (double)d3);
            }
        } else {
            #pragma unroll
            for (int m = 16; m; m >>= 1) {
                dp0 += __shfl_xor_sync(0xffffffffu, dp0, m);
                dp1 += __shfl_xor_sync(0xffffffffu, dp1, m);
                dp2 += __shfl_xor_sync(0xffffffffu, dp2, m);
                dp3 += __shfl_xor_sync(0xffffffffu, dp3, m);
            }
            if (lane == 0) {
                float d0 = sqrtf(fmaxf(g_xsq[r0] + s_cs - 2.f * dp0, 1e-12f));
                float d1 = sqrtf(fmaxf(g_xsq[r1] + s_cs - 2.f * dp1, 1e-12f));
                float d2 = sqrtf(fmaxf(g_xsq[r2] + s_cs - 2.f * dp2, 1e-12f));
                float d3 = sqrtf(fmaxf(g_xsq[r3] + s_cs - 2.f * dp3, 1e-12f));
                float n0 = fminf(g_dmin[r0], d0);
                float n1 = fminf(g_dmin[r1], d1);
                float n2 = fminf(g_dmin[r2], d2);
                float n3 = fminf(g_dmin[r3], d3);
                g_dmin[r0] = n0; g_dmin[r1] = n1; g_dmin[r2] = n2; g_dmin[r3] = n3;
                wsumd += ((double)n0 + (double)n1) + ((double)n2 + (double)n3);
            }
        }
        row += 4 * STEP;
    }
    while (row < en) {
        const float4* xr = (const float4*)x + (size_t)row * (D / 4);
        float4 a0 = __ldg(xr + lane);
        float4 a1 = __ldg(xr + lane + 32);
        float dp = dot4(a0, c0) + dot4(a1, c1);
        if (i == 1) {
            float xs = dot4(a0, a0) + dot4(a1, a1);
            #pragma unroll
            for (int m = 16; m; m >>= 1) {
                dp += __shfl_xor_sync(0xffffffffu, dp, m);
                xs += __shfl_xor_sync(0xffffffffu, xs, m);
            }
            if (lane == 0) {
                g_xsq[row] = xs;
                float d = sqrtf(fmaxf(xs + s_cs - 2.f * dp, 1e-12f));
                g_dmin[row] = d;
                wsumd += (double)d;
            }
        } else {
            dp = wsum(dp);
            if (lane == 0) {
                float d = sqrtf(fmaxf(g_xsq[row] + s_cs - 2.f * dp, 1e-12f));
                float nd = fminf(g_dmin[row], d);
                g_dmin[row] = nd;
                wsumd += (double)nd;
            }
        }
        row += STEP;
    }
    if (lane == 0) s_ws[warp] = wsumd;
    __syncthreads();
    if (tid == 0) {
        double s = 0.0;
        #pragma unroll
        for (int w = 0; w < TM / 32; w++) s += s_ws[w];
        g_bsum[blockIdx.x] = s;
    }
}

// ---------------------------------------------------------------------------
// k-means++ select: two-level warp-shuffle scans (1024 threads = 32 warps).
// ---------------------------------------------------------------------------
__global__ void k_select(const float* __restrict__ x,
                         const float* __restrict__ uinit,
                         int N, int i) {
    __shared__ double s_wtot[32];
    __shared__ double s_sq[256];
    __shared__ double s_base;
    __shared__ int    s_pick;
    int tid  = threadIdx.x;
    int lane = tid & 31;
    int warp = tid >> 5;
    int chunk = (N + DB - 1) / DB;

    double v = (tid < DB) ? g_bsum[tid] : 0.0;
    double s = v;
    #pragma unroll
    for (int off = 1; off < 32; off <<= 1) {
        double n = __shfl_up_sync(0xffffffffu, s, off);
        if (lane >= off) s += n;
    }
    if (lane == 31) s_wtot[warp] = s;
    __syncthreads();
    if (warp == 0) {
        double t = s_wtot[lane];
        #pragma unroll
        for (int off = 1; off < 32; off <<= 1) {
            double n = __shfl_up_sync(0xffffffffu, t, off);
            if (lane >= off) t += n;
        }
        s_wtot[lane] = t;
    }
    __syncthreads();
    double incl  = s + (warp ? s_wtot[warp - 1] : 0.0);
    double total = s_wtot[31];
    double target = (double)uinit[i] * total;
    if (tid == 0) { s_pick = DB - 1; s_base = total - g_bsum[DB - 1]; }
    __syncthreads();
    if (tid < DB) {
        double excl = incl - v;
        if (excl < target && target <= incl) { s_pick = tid; s_base = excl; }
    }
    __syncthreads();
    int    tb    = s_pick;
    double resid = target - s_base;
    int sst = tb * chunk;
    int sen = min(sst + chunk, N);
    int cnt = sen - sst;
    __syncthreads();

    double dv = (tid < cnt) ? (double)g_dmin[sst + tid] : 0.0;
    double s2 = dv;
    #pragma unroll
    for (int off = 1; off < 32; off <<= 1) {
        double n = __shfl_up_sync(0xffffffffu, s2, off);
        if (lane >= off) s2 += n;
    }
    if (lane == 31) s_wtot[warp] = s2;
    __syncthreads();
    if (warp == 0) {
        double t = s_wtot[lane];
        #pragma unroll
        for (int off = 1; off < 32; off <<= 1) {
            double n = __shfl_up_sync(0xffffffffu, t, off);
            if (lane >= off) t += n;
        }
        s_wtot[lane] = t;
    }
    __syncthreads();
    double incl2 = s2 + (warp ? s_wtot[warp - 1] : 0.0);
    if (tid == 0) s_pick = cnt - 1;
    __syncthreads();
    if (tid < cnt) {
        double excl2 = incl2 - dv;
        if (excl2 < resid && resid <= incl2) s_pick = tid;
    }
    __syncthreads();
    int idx = sst + s_pick;
    if (idx > N - 1) idx = N - 1;

    if (tid < D) {
        float cv = x[(size_t)idx * D + tid];
        g_centers[i * D + tid] = cv;
        s_sq[tid] = (double)cv * (double)cv;
    }
    __syncthreads();
    for (int sft = 128; sft; sft >>= 1) {
        if (tid < sft) s_sq[tid] += s_sq[tid + sft];
        __syncthreads();
    }
    if (tid == 0) g_csq[i] = (float)s_sq[0];
}

// ---------------------------------------------------------------------------
// Persistent iteration kernel (R12 frame + flag-based barriers).
// ---------------------------------------------------------------------------
template <int K>
__global__ void __launch_bounds__(T1) k_iter(const float* __restrict__ x,
                                             float* __restrict__ out_r,
                                             float* __restrict__ out_c,
                                             int N) {
    __shared__ float4 s_acc4[K * 64];
    __shared__ float  s_cnt[K];
    __shared__ double s_part[4][64][4];
    __shared__ double s_cntv;
    __shared__ double s_v[128];

    int tid  = threadIdx.x;
    int lane = tid & 31;
    int warp = tid >> 5;
    int bid  = blockIdx.x;
    int jl   = lane & 7;
    int maxit = g_maxiters;

    if (maxit < 1) {
        size_t tot = (size_t)N * K;
        for (size_t i = (size_t)bid * T1 + tid; i < tot; i += (size_t)GRID1 * T1)
            out_r[i] = 0.f;
        if (bid == 0)
            for (int i = tid; i < K * D; i += T1) out_c[i] = g_centers[i];
        return;
    }

    float w_l = (jl < K) ? __ldg(&g_w[jl]) : 0.f;

    for (int t = 0; t < maxit; t++) {
        float csq_l = (jl < K) ? __ldcg(&g_csq[jl]) : 0.f;
        u64 c_pk[K][4];
        const float4* cb = (const float4*)g_centers;
        #pragma unroll
        for (int j = 0; j < K; j++) {
            float4 c0 = __ldcg(cb + j * 64 + lane);
            float4 c1 = __ldcg(cb + j * 64 + 32 + lane);
            c_pk[j][0] = pk2(c0.x, c0.y); c_pk[j][1] = pk2(c0.z, c0.w);
            c_pk[j][2] = pk2(c1.x, c1.y); c_pk[j][3] = pk2(c1.z, c1.w);
        }
        for (int i = tid; i < K * 64; i += T1) s_acc4[i] = make_float4(0.f, 0.f, 0.f, 0.f);
        if (tid < K) s_cnt[tid] = 0.f;
        __syncthreads();

        u64 acc2[K][4];
        #pragma unroll
        for (int j = 0; j < K; j++) {
            #pragma unroll
            for (int u = 0; u < 4; u++) acc2[j][u] = 0ull;
        }
        float cnt_l = 0.f;

        // ---- main pass: two interleaved rows, group-transpose reduction ----
        int row = bid * NW1 + warp;
        while (row + TOT_W < N) {
            int rA = row, rB = row + TOT_W;
            const float4* xA = (const float4*)x + (size_t)rA * (D / 4);
            const float4* xB = (const float4*)x + (size_t)rB * (D / 4);
            float4 a0A = __ldg(xA + lane);
            float4 a0B = __ldg(xB + lane);
            float4 a1A = __ldg(xA + lane + 32);
            float4 a1B = __ldg(xB + lane + 32);
            float  xsA = __ldg(g_xsq + rA);
            float  xsB = __ldg(g_xsq + rB);
            u64 pA0 = pk2(a0A.x, a0A.y), pA1 = pk2(a0A.z, a0A.w);
            u64 pA2 = pk2(a1A.x, a1A.y), pA3 = pk2(a1A.z, a1A.w);
            u64 pB0 = pk2(a0B.x, a0B.y), pB1 = pk2(a0B.z, a0B.w);
            u64 pB2 = pk2(a1B.x, a1B.y), pB3 = pk2(a1B.z, a1B.w);
            float dpA[K], dpB[K];
            #pragma unroll
            for (int j = 0; j < K; j++) {
                u64 tA = mul2(pA0, c_pk[j][0]);
                u64 tB = mul2(pB0, c_pk[j][0]);
                tA = fma2(pA1, c_pk[j][1], tA);
                tB = fma2(pB1, c_pk[j][1], tB);
                tA = fma2(pA2, c_pk[j][2], tA);
                tB = fma2(pB2, c_pk[j][2], tB);
                tA = fma2(pA3, c_pk[j][3], tA);
                tB = fma2(pB3, c_pk[j][3], tB);
                float loA, hiA, loB, hiB;
                upk2(tA, loA, hiA); upk2(tB, loB, hiB);
                dpA[j] = loA + hiA; dpB[j] = loB + hiB;
            }
            #pragma unroll
            for (int m = 4; m; m >>= 1) {
                #pragma unroll
                for (int j = 0; j < K; j++) {
                    dpA[j] += __shfl_xor_sync(0xffffffffu, dpA[j], m);
                    dpB[j] += __shfl_xor_sync(0xffffffffu, dpB[j], m);
                }
            }
            float myA = dpA[0], myB = dpB[0];
            #pragma unroll
            for (int j = 1; j < K; j++) {
                bool p = (jl == j);
                myA = p ? dpA[j] : myA;
                myB = p ? dpB[j] : myB;
            }
            myA += __shfl_xor_sync(0xffffffffu, myA, 8);
            myB += __shfl_xor_sync(0xffffffffu, myB, 8);
            myA += __shfl_xor_sync(0xffffffffu, myA, 16);
            myB += __shfl_xor_sync(0xffffffffu, myB, 16);

            float dA = sqrtf(fmaxf(xsA + csq_l - 2.f * myA, 1e-12f));
            float dB = sqrtf(fmaxf(xsB + csq_l - 2.f * myB, 1e-12f));
            float eA = w_l * __expf(ESHIFT - dA);
            float eB = w_l * __expf(ESHIFT - dB);
            float sA = wsum8(eA);
            float sB = wsum8(eB);
            float rvA = __fdividef(eA, sA);
            float rvB = __fdividef(eB, sB);
            if (lane < K) {
                out_r[(size_t)rA * K + lane] = rvA;
                out_r[(size_t)rB * K + lane] = rvB;
            }
            cnt_l += rvA + rvB;
            #pragma unroll
            for (int j = 0; j < K; j++) {
                float rbA = __shfl_sync(0xffffffffu, rvA, j);
                float rbB = __shfl_sync(0xffffffffu, rvB, j);
                u64 r2A = pk2(rbA, rbA);
                u64 r2B = pk2(rbB, rbB);
                acc2[j][0] = fma2(r2A, pA0, acc2[j][0]);
                acc2[j][1] = fma2(r2A, pA1, acc2[j][1]);
                acc2[j][2] = fma2(r2A, pA2, acc2[j][2]);
                acc2[j][3] = fma2(r2A, pA3, acc2[j][3]);
                acc2[j][0] = fma2(r2B, pB0, acc2[j][0]);
                acc2[j][1] = fma2(r2B, pB1, acc2[j][1]);
                acc2[j][2] = fma2(r2B, pB2, acc2[j][2]);
                acc2[j][3] = fma2(r2B, pB3, acc2[j][3]);
            }
            row += 2 * TOT_W;
        }
        if (row < N) {
            const float4* xr = (const float4*)x + (size_t)row * (D / 4);
            float4 a0 = __ldg(xr + lane);
            float4 a1 = __ldg(xr + lane + 32);
            float  xs = __ldg(g_xsq + row);
            u64 p0 = pk2(a0.x, a0.y), p1 = pk2(a0.z, a0.w);
            u64 p2 = pk2(a1.x, a1.y), p3 = pk2(a1.z, a1.w);
            float dp[K];
            #pragma unroll
            for (int j = 0; j < K; j++) {
                u64 tt = mul2(p0, c_pk[j][0]);
                tt = fma2(p1, c_pk[j][1], tt);
                tt = fma2(p2, c_pk[j][2], tt);
                tt = fma2(p3, c_pk[j][3], tt);
                float lo, hi; upk2(tt, lo, hi);
                dp[j] = lo + hi;
            }
            #pragma unroll
            for (int m = 4; m; m >>= 1) {
                #pragma unroll
                for (int j = 0; j < K; j++)
                    dp[j] += __shfl_xor_sync(0xffffffffu, dp[j], m);
            }
            float myv = dp[0];
            #pragma unroll
            for (int j = 1; j < K; j++) myv = (jl == j) ? dp[j] : myv;
            myv += __shfl_xor_sync(0xffffffffu, myv, 8);
            myv += __shfl_xor_sync(0xffffffffu, myv, 16);
            float dval = sqrtf(fmaxf(xs + csq_l - 2.f * myv, 1e-12f));
            float ev   = w_l * __expf(ESHIFT - dval);
            float ssum = wsum8(ev);
            float rv   = __fdividef(ev, ssum);
            if (lane < K) out_r[(size_t)row * K + lane] = rv;
            cnt_l += rv;
            #pragma unroll
            for (int j = 0; j < K; j++) {
                float rb = __shfl_sync(0xffffffffu, rv, j);
                u64 r2 = pk2(rb, rb);
                acc2[j][0] = fma2(r2, p0, acc2[j][0]);
                acc2[j][1] = fma2(r2, p1, acc2[j][1]);
                acc2[j][2] = fma2(r2, p2, acc2[j][2]);
                acc2[j][3] = fma2(r2, p3, acc2[j][3]);
            }
        }

        // ---- deterministic sequential warp combine ----
        for (int w = 0; w < NW1; w++) {
            if (warp == w) {
                #pragma unroll
                for (int j = 0; j < K; j++) {
                    float lo0, hi0, lo1, hi1;
                    float4 v = s_acc4[j * 64 + lane];
                    upk2(acc2[j][0], lo0, hi0);
                    upk2(acc2[j][1], lo1, hi1);
                    v.x += lo0; v.y += hi0; v.z += lo1; v.w += hi1;
                    s_acc4[j * 64 + lane] = v;
                    v = s_acc4[j * 64 + 32 + lane];
                    upk2(acc2[j][2], lo0, hi0);
                    upk2(acc2[j][3], lo1, hi1);
                    v.x += lo0; v.y += hi0; v.z += lo1; v.w += hi1;
                    s_acc4[j * 64 + 32 + lane] = v;
                }
                if (lane < K) s_cnt[lane] += cnt_l;
            }
            __syncthreads();
        }
        {
            float4* Pb = (float4*)(g_P + (size_t)bid * (KMAX * D));
            for (int i = tid; i < K * 64; i += T1) Pb[i] = s_acc4[i];
            if (tid < K) g_Pc[bid * KMAX + tid] = s_cnt[tid];
        }

        // ---- barrier 1 (flag-based): stamp own flag; only updaters wait ----
        __syncthreads();
        __threadfence();
        if (tid == 0) st_cg_i32(&g_flag_main[bid * FPAD], t + 1);

        if (bid < K) {
            if (warp == 0) {
                int need = t + 1;
                bool done_poll = false;
                while (!done_poll) {
                    bool ok = true;
                    for (int p = lane; p < GRID1; p += 32)
                        ok &= (ld_cg_i32(&g_flag_main[p * FPAD]) >= need);
                    done_poll = __all_sync(0xffffffffu, ok);
                    if (!done_poll) __nanosleep(64);
                }
                __threadfence();
            }
            __syncthreads();

            // ---- center update: block j owns cluster j (parallel) ----
            int j = bid;
            if (warp == 8) {
                double c = 0.0;
                for (int p = lane; p < GRID1; p += 32)
                    c += (double)__ldcg(&g_Pc[p * KMAX + j]);
                #pragma unroll
                for (int m = 16; m; m >>= 1)
                    c += __shfl_xor_sync(0xffffffffu, c, m);
                if (lane == 0) s_cntv = c;
            }
            if (tid < 256) {
                int g = tid >> 6, i4 = tid & 63;
                int pst = g * 37;
                int pen = min(GRID1, pst + 37);
                const float4* base = (const float4*)g_P + (size_t)j * (D / 4) + i4;
                const int S4 = KMAX * D / 4;
                double dx = 0.0, dy = 0.0, dz = 0.0, dw = 0.0;
                int p = pst;
                for (; p + 8 <= pen; p += 8) {
                    float4 v0 = __ldcg(base + (size_t)(p + 0) * S4);
                    float4 v1 = __ldcg(base + (size_t)(p + 1) * S4);
                    float4 v2 = __ldcg(base + (size_t)(p + 2) * S4);
                    float4 v3 = __ldcg(base + (size_t)(p + 3) * S4);
                    float4 v4 = __ldcg(base + (size_t)(p + 4) * S4);
                    float4 v5 = __ldcg(base + (size_t)(p + 5) * S4);
                    float4 v6 = __ldcg(base + (size_t)(p + 6) * S4);
                    float4 v7 = __ldcg(base + (size_t)(p + 7) * S4);
                    dx += (((double)v0.x + (double)v1.x) + ((double)v2.x + (double)v3.x))
                        + (((double)v4.x + (double)v5.x) + ((double)v6.x + (double)v7.x));
                    dy += (((double)v0.y + (double)v1.y) + ((double)v2.y + (double)v3.y))
                        + (((double)v4.y + (double)v5.y) + ((double)v6.y + (double)v7.y));
                    dz += (((double)v0.z + (double)v1.z) + ((double)v2.z + (double)v3.z))
                        + (((double)v4.z + (double)v5.z) + ((double)v6.z + (double)v7.z));
                    dw += (((double)v0.w + (double)v1.w) + ((double)v2.w + (double)v3.w))
                        + (((double)v4.w + (double)v5.w) + ((double)v6.w + (double)v7.w));
                }
                for (; p < pen; p++) {
                    float4 v = __ldcg(base + (size_t)p * S4);
                    dx += (double)v.x; dy += (double)v.y;
                    dz += (double)v.z; dw += (double)v.w;
                }
                s_part[g][i4][0] = dx; s_part[g][i4][1] = dy;
                s_part[g][i4][2] = dz; s_part[g][i4][3] = dw;
            }
            __syncthreads();
            if (tid < 64) {
                double cnt = s_cntv;
                double sx = (s_part[0][tid][0] + s_part[1][tid][0])
                          + (s_part[2][tid][0] + s_part[3][tid][0]);
                double sy = (s_part[0][tid][1] + s_part[1][tid][1])
                          + (s_part[2][tid][1] + s_part[3][tid][1]);
                double sz = (s_part[0][tid][2] + s_part[1][tid][2])
                          + (s_part[2][tid][2] + s_part[3][tid][2]);
                double sw = (s_part[0][tid][3] + s_part[1][tid][3])
                          + (s_part[2][tid][3] + s_part[3][tid][3]);
                float n0 = (float)(sx / cnt), n1 = (float)(sy / cnt);
                float n2 = (float)(sz / cnt), n3 = (float)(sw / cnt);
                int e4 = j * (D / 4) + tid;
                ((float4*)g_centers)[e4] = make_float4(n0, n1, n2, n3);
                float4 pv = ((float4*)g_prev)[e4];
                ((float4*)g_prev)[e4] = make_float4(n0, n1, n2, n3);
                double d0 = (double)(n0 - pv.x), d1 = (double)(n1 - pv.y);
                double d2 = (double)(n2 - pv.z), d3 = (double)(n3 - pv.w);
                s_v[tid]      = (d0 * d0 + d1 * d1) + (d2 * d2 + d3 * d3);
                s_v[64 + tid] = ((double)n0 * n0 + (double)n1 * n1)
                              + ((double)n2 * n2 + (double)n3 * n3);
            }
            __syncthreads();
            if (warp == 0) {
                double a = s_v[lane] + s_v[lane + 32];
                #pragma unroll
                for (int m = 16; m; m >>= 1)
                    a += __shfl_xor_sync(0xffffffffu, a, m);
                if (lane == 0) g_shiftp[j] = a;
            } else if (warp == 1) {
                double a = s_v[64 + lane] + s_v[96 + lane];
                #pragma unroll
                for (int m = 16; m; m >>= 1)
                    a += __shfl_xor_sync(0xffffffffu, a, m);
                if (lane == 0) g_csq[j] = (float)a;
            }
            __syncthreads();
            __threadfence();
            if (tid == 0) st_cg_i32(&g_flag_upd[j * FPAD], t + 1);
        }

        // ---- barrier 2 (flag-based): everyone waits for the K upd flags ----
        if (warp == 0) {
            int need = t + 1;
            bool done_poll = false;
            while (!done_poll) {
                bool ok = (lane >= K) || (ld_cg_i32(&g_flag_upd[lane * FPAD]) >= need);
                done_poll = __all_sync(0xffffffffu, ok);
                if (!done_poll) __nanosleep(64);
            }
            __threadfence();
        }
        __syncthreads();

        double sh = 0.0;
        #pragma unroll
        for (int j = 0; j < K; j++) sh += __ldcg(&g_shiftp[j]);
        if (sqrt(sh) < TOLV) break;
    }

    if (bid == 0)
        for (int i = tid; i < K * D; i += T1) out_c[i] = __ldcg(&g_centers[i]);
}

// ---------------------------------------------------------------------------
extern "C" void kernel_launch(void* const* d_in, const int* in_sizes, int n_in,
                              void* d_out, int out_size) {
    const float* x      = (const float*)d_in[0];
    const float* logits = (const float*)d_in[1];
    const float* gumbel = (const float*)d_in[2];
    const float* uinit  = (const float*)d_in[3];
    const int*   maxit  = (const int*)d_in[4];

    int N = in_sizes[0] / D;
    int k = out_size / (N + D);
    if (k < 1) k = 1;
    if (k > KMAX) k = KMAX;

    float* out_c = (float*)d_out;
    float* out_r = out_c + (size_t)k * D;

    k_init<<<1, 256>>>(x, logits, gumbel, uinit, maxit, N);
    if (k == 1) {
        k_xsq<<<DB, TM>>>(x, N);
    } else {
        for (int i = 1; i < k; i++) {
            k_dmin<<<DB, TM>>>(x, N, i);           // pass 1 also fills g_xsq
            k_select<<<1, 1024>>>(x, uinit, N, i);
        }
    }
    switch (k) {
        case 1: k_iter<1><<<GRID1, T1>>>(x, out_r, out_c, N); break;
        case 2: k_iter<2><<<GRID1, T1>>>(x, out_r, out_c, N); break;
        case 3: k_iter<3><<<GRID1, T1>>>(x, out_r, out_c, N); break;
        case 4: k_iter<4><<<GRID1, T1>>>(x, out_r, out_c, N); break;
        case 5: k_iter<5><<<GRID1, T1>>>(x, out_r, out_c, N); break;
        default: k_iter<6><<<GRID1, T1>>>(x, out_r, out_c, N); break;
    }
}

// round 15
// speedup vs baseline: 1.6422x; 1.0039x over previous
#include <cuda_runtime.h>
#include <math.h>

// ---------------------------------------------------------------------------
// SoftCluster_adaptiveK — round 15 (= R14 + addressing fix)
//  * FIX: ulonglong2 row stride is D/4 (16B elements = 4 floats), not D/8.
//    R14 read overlapping half-rows -> rel_err 1.0.
//  * x loaded as ulonglong2 (packed f32x2 pairs direct from LDG.128)
//  * K<=4: 4-lane-group transpose reduction + wsum4 softmax denominator
// ---------------------------------------------------------------------------

#define D      256
#define KMAX   6
#define GRID1  148
#define T1     384
#define NW1    (T1 / 32)
#define TOT_W  (GRID1 * NW1)
#define DB     592
#define TM     256
#define TOLV   1e-5
#define ESHIFT 24.0f
#define FPAD   8

typedef unsigned long long u64;

// ---- device scratch (static; no allocation anywhere) ----
__device__ float  g_centers[KMAX * D];
__device__ float  g_prev[KMAX * D];
__device__ float  g_csq[KMAX];
__device__ float  g_w[KMAX];
__device__ float  g_P[GRID1 * KMAX * D];
__device__ float  g_Pc[GRID1 * KMAX];
__device__ double g_shiftp[KMAX];
__device__ float  g_dmin[131072];
__device__ float  g_xsq[131072];
__device__ double g_bsum[DB];
__device__ int    g_flag_main[GRID1 * FPAD];
__device__ int    g_flag_upd[KMAX * FPAD];
__device__ int    g_maxiters;
__device__ int    g_idx;

// ---- helpers ----
__device__ __forceinline__ u64 pk2(float lo, float hi) {
    u64 r; asm("mov.b64 %0,{%1,%2};" : "=l"(r) : "f"(lo), "f"(hi)); return r;
}
__device__ __forceinline__ void upk2(u64 v, float& lo, float& hi) {
    asm("mov.b64 {%0,%1},%2;" : "=f"(lo), "=f"(hi) : "l"(v));
}
__device__ __forceinline__ u64 fma2(u64 a, u64 b, u64 c) {
    u64 r; asm("fma.rn.f32x2 %0,%1,%2,%3;" : "=l"(r) : "l"(a), "l"(b), "l"(c)); return r;
}
__device__ __forceinline__ u64 mul2(u64 a, u64 b) {
    u64 r; asm("mul.rn.f32x2 %0,%1,%2;" : "=l"(r) : "l"(a), "l"(b)); return r;
}
__device__ __forceinline__ float wsum(float v) {
    #pragma unroll
    for (int m = 16; m; m >>= 1) v += __shfl_xor_sync(0xffffffffu, v, m);
    return v;
}
__device__ __forceinline__ float dot4(float4 a, float4 b) {
    return a.x * b.x + a.y * b.y + a.z * b.z + a.w * b.w;
}
__device__ __forceinline__ int ld_cg_i32(const int* p) {
    int v; asm volatile("ld.global.cg.b32 %0, [%1];" : "=r"(v) : "l"(p)); return v;
}
__device__ __forceinline__ void st_cg_i32(int* p, int v) {
    asm volatile("st.global.cg.b32 [%0], %1;" :: "l"(p), "r"(v) : "memory");
}

// ---------------------------------------------------------------------------
__global__ void k_init(const float* __restrict__ x,
                       const float* __restrict__ logits,
                       const float* __restrict__ gumbel,
                       const float* __restrict__ uinit,
                       const int*   __restrict__ maxit,
                       int N) {
    __shared__ double s_sq[256];
    int tid = threadIdx.x;
    if (tid == 0) {
        g_maxiters = maxit[0];
        float l[KMAX]; float m = -3.4e38f;
        for (int j = 0; j < KMAX; j++) { l[j] = logits[j] + gumbel[j]; m = fmaxf(m, l[j]); }
        float s = 0.f, e[KMAX];
        for (int j = 0; j < KMAX; j++) { e[j] = expf(l[j] - m); s += e[j]; }
        for (int j = 0; j < KMAX; j++) g_w[j] = e[j] / s;
        float f = uinit[0] * (float)N;
        int idx = (int)f;
        if (idx > N - 1) idx = N - 1;
        if (idx < 0) idx = 0;
        g_idx = idx;
    }
    for (int i = tid; i < KMAX * D; i += blockDim.x) g_prev[i] = 0.f;
    for (int i = tid; i < GRID1 * FPAD; i += blockDim.x) g_flag_main[i] = 0;
    for (int i = tid; i < KMAX * FPAD; i += blockDim.x) g_flag_upd[i] = 0;
    __syncthreads();
    int idx = g_idx;
    float v = x[(size_t)idx * D + tid];
    g_centers[tid] = v;
    s_sq[tid] = (double)v * (double)v;
    __syncthreads();
    for (int s = 128; s; s >>= 1) {
        if (tid < s) s_sq[tid] += s_sq[tid + s];
        __syncthreads();
    }
    if (tid == 0) g_csq[0] = (float)s_sq[0];
}

// ---------------------------------------------------------------------------
// xsq only (used when k == 1)
// ---------------------------------------------------------------------------
__global__ void __launch_bounds__(TM) k_xsq(const float* __restrict__ x, int N) {
    int tid = threadIdx.x;
    int lane = tid & 31;
    int gwarp = blockIdx.x * (TM / 32) + (tid >> 5);
    int tot = DB * (TM / 32);
    for (int row = gwarp; row < N; row += tot) {
        const float4* xr = (const float4*)x + (size_t)row * (D / 4);
        float4 a0 = __ldg(xr + lane);
        float4 a1 = __ldg(xr + lane + 32);
        float xs = wsum(dot4(a0, a0) + dot4(a1, a1));
        if (lane == 0) g_xsq[row] = xs;
    }
}

// ---------------------------------------------------------------------------
// k-means++ pass over CONTIGUOUS chunk, 4-row interleaved.
// Pass 1 (i==1) also computes and stores xsq.
// ---------------------------------------------------------------------------
__global__ void __launch_bounds__(TM) k_dmin(const float* __restrict__ x, int N, int i) {
    __shared__ float  s_c[D];
    __shared__ float  s_cs;
    __shared__ double s_ws[TM / 32];
    int tid = threadIdx.x;
    if (tid < D) s_c[tid] = g_centers[(i - 1) * D + tid];
    if (tid == 0) s_cs = g_csq[i - 1];
    if (tid < TM / 32) s_ws[tid] = 0.0;
    __syncthreads();
    int lane = tid & 31;
    int warp = tid >> 5;
    const int STEP = TM / 32;
    int chunk = (N + DB - 1) / DB;
    int st = blockIdx.x * chunk;
    int en = min(st + chunk, N);
    const float4* c4 = (const float4*)s_c;
    float4 c0 = c4[lane], c1 = c4[lane + 32];
    double wsumd = 0.0;

    int row = st + warp;
    while (row + 3 * STEP < en) {
        int r0 = row, r1 = row + STEP, r2 = row + 2 * STEP, r3 = row + 3 * STEP;
        const float4* x0 = (const float4*)x + (size_t)r0 * (D / 4);
        const float4* x1 = (const float4*)x + (size_t)r1 * (D / 4);
        const float4* x2 = (const float4*)x + (size_t)r2 * (D / 4);
        const float4* x3 = (const float4*)x + (size_t)r3 * (D / 4);
        float4 a00 = __ldg(x0 + lane),      a10 = __ldg(x1 + lane);
        float4 a20 = __ldg(x2 + lane),      a30 = __ldg(x3 + lane);
        float4 a01 = __ldg(x0 + lane + 32), a11 = __ldg(x1 + lane + 32);
        float4 a21 = __ldg(x2 + lane + 32), a31 = __ldg(x3 + lane + 32);
        float dp0 = dot4(a00, c0) + dot4(a01, c1);
        float dp1 = dot4(a10, c0) + dot4(a11, c1);
        float dp2 = dot4(a20, c0) + dot4(a21, c1);
        float dp3 = dot4(a30, c0) + dot4(a31, c1);
        if (i == 1) {
            float xs0 = dot4(a00, a00) + dot4(a01, a01);
            float xs1 = dot4(a10, a10) + dot4(a11, a11);
            float xs2 = dot4(a20, a20) + dot4(a21, a21);
            float xs3 = dot4(a30, a30) + dot4(a31, a31);
            #pragma unroll
            for (int m = 16; m; m >>= 1) {
                dp0 += __shfl_xor_sync(0xffffffffu, dp0, m);
                dp1 += __shfl_xor_sync(0xffffffffu, dp1, m);
                dp2 += __shfl_xor_sync(0xffffffffu, dp2, m);
                dp3 += __shfl_xor_sync(0xffffffffu, dp3, m);
                xs0 += __shfl_xor_sync(0xffffffffu, xs0, m);
                xs1 += __shfl_xor_sync(0xffffffffu, xs1, m);
                xs2 += __shfl_xor_sync(0xffffffffu, xs2, m);
                xs3 += __shfl_xor_sync(0xffffffffu, xs3, m);
            }
            if (lane == 0) {
                g_xsq[r0] = xs0; g_xsq[r1] = xs1; g_xsq[r2] = xs2; g_xsq[r3] = xs3;
                float d0 = sqrtf(fmaxf(xs0 + s_cs - 2.f * dp0, 1e-12f));
                float d1 = sqrtf(fmaxf(xs1 + s_cs - 2.f * dp1, 1e-12f));
                float d2 = sqrtf(fmaxf(xs2 + s_cs - 2.f * dp2, 1e-12f));
                float d3 = sqrtf(fmaxf(xs3 + s_cs - 2.f * dp3, 1e-12f));
                g_dmin[r0] = d0; g_dmin[r1] = d1; g_dmin[r2] = d2; g_dmin[r3] = d3;
                wsumd += ((double)d0 + (double)d1) + ((double)d2 + (double)d3);
            }
        } else {
            #pragma unroll
            for (int m = 16; m; m >>= 1) {
                dp0 += __shfl_xor_sync(0xffffffffu, dp0, m);
                dp1 += __shfl_xor_sync(0xffffffffu, dp1, m);
                dp2 += __shfl_xor_sync(0xffffffffu, dp2, m);
                dp3 += __shfl_xor_sync(0xffffffffu, dp3, m);
            }
            if (lane == 0) {
                float d0 = sqrtf(fmaxf(g_xsq[r0] + s_cs - 2.f * dp0, 1e-12f));
                float d1 = sqrtf(fmaxf(g_xsq[r1] + s_cs - 2.f * dp1, 1e-12f));
                float d2 = sqrtf(fmaxf(g_xsq[r2] + s_cs - 2.f * dp2, 1e-12f));
                float d3 = sqrtf(fmaxf(g_xsq[r3] + s_cs - 2.f * dp3, 1e-12f));
                float n0 = fminf(g_dmin[r0], d0);
                float n1 = fminf(g_dmin[r1], d1);
                float n2 = fminf(g_dmin[r2], d2);
                float n3 = fminf(g_dmin[r3], d3);
                g_dmin[r0] = n0; g_dmin[r1] = n1; g_dmin[r2] = n2; g_dmin[r3] = n3;
                wsumd += ((double)n0 + (double)n1) + ((double)n2 + (double)n3);
            }
        }
        row += 4 * STEP;
    }
    while (row < en) {
        const float4* xr = (const float4*)x + (size_t)row * (D / 4);
        float4 a0 = __ldg(xr + lane);
        float4 a1 = __ldg(xr + lane + 32);
        float dp = dot4(a0, c0) + dot4(a1, c1);
        if (i == 1) {
            float xs = dot4(a0, a0) + dot4(a1, a1);
            #pragma unroll
            for (int m = 16; m; m >>= 1) {
                dp += __shfl_xor_sync(0xffffffffu, dp, m);
                xs += __shfl_xor_sync(0xffffffffu, xs, m);
            }
            if (lane == 0) {
                g_xsq[row] = xs;
                float d = sqrtf(fmaxf(xs + s_cs - 2.f * dp, 1e-12f));
                g_dmin[row] = d;
                wsumd += (double)d;
            }
        } else {
            dp = wsum(dp);
            if (lane == 0) {
                float d = sqrtf(fmaxf(g_xsq[row] + s_cs - 2.f * dp, 1e-12f));
                float nd = fminf(g_dmin[row], d);
                g_dmin[row] = nd;
                wsumd += (double)nd;
            }
        }
        row += STEP;
    }
    if (lane == 0) s_ws[warp] = wsumd;
    __syncthreads();
    if (tid == 0) {
        double s = 0.0;
        #pragma unroll
        for (int w = 0; w < TM / 32; w++) s += s_ws[w];
        g_bsum[blockIdx.x] = s;
    }
}

// ---------------------------------------------------------------------------
// k-means++ select: two-level warp-shuffle scans (1024 threads = 32 warps).
// ---------------------------------------------------------------------------
__global__ void k_select(const float* __restrict__ x,
                         const float* __restrict__ uinit,
                         int N, int i) {
    __shared__ double s_wtot[32];
    __shared__ double s_sq[256];
    __shared__ double s_base;
    __shared__ int    s_pick;
    int tid  = threadIdx.x;
    int lane = tid & 31;
    int warp = tid >> 5;
    int chunk = (N + DB - 1) / DB;

    double v = (tid < DB) ? g_bsum[tid] : 0.0;
    double s = v;
    #pragma unroll
    for (int off = 1; off < 32; off <<= 1) {
        double n = __shfl_up_sync(0xffffffffu, s, off);
        if (lane >= off) s += n;
    }
    if (lane == 31) s_wtot[warp] = s;
    __syncthreads();
    if (warp == 0) {
        double t = s_wtot[lane];
        #pragma unroll
        for (int off = 1; off < 32; off <<= 1) {
            double n = __shfl_up_sync(0xffffffffu, t, off);
            if (lane >= off) t += n;
        }
        s_wtot[lane] = t;
    }
    __syncthreads();
    double incl  = s + (warp ? s_wtot[warp - 1] : 0.0);
    double total = s_wtot[31];
    double target = (double)uinit[i] * total;
    if (tid == 0) { s_pick = DB - 1; s_base = total - g_bsum[DB - 1]; }
    __syncthreads();
    if (tid < DB) {
        double excl = incl - v;
        if (excl < target && target <= incl) { s_pick = tid; s_base = excl; }
    }
    __syncthreads();
    int    tb    = s_pick;
    double resid = target - s_base;
    int sst = tb * chunk;
    int sen = min(sst + chunk, N);
    int cnt = sen - sst;
    __syncthreads();

    double dv = (tid < cnt) ? (double)g_dmin[sst + tid] : 0.0;
    double s2 = dv;
    #pragma unroll
    for (int off = 1; off < 32; off <<= 1) {
        double n = __shfl_up_sync(0xffffffffu, s2, off);
        if (lane >= off) s2 += n;
    }
    if (lane == 31) s_wtot[warp] = s2;
    __syncthreads();
    if (warp == 0) {
        double t = s_wtot[lane];
        #pragma unroll
        for (int off = 1; off < 32; off <<= 1) {
            double n = __shfl_up_sync(0xffffffffu, t, off);
            if (lane >= off) t += n;
        }
        s_wtot[lane] = t;
    }
    __syncthreads();
    double incl2 = s2 + (warp ? s_wtot[warp - 1] : 0.0);
    if (tid == 0) s_pick = cnt - 1;
    __syncthreads();
    if (tid < cnt) {
        double excl2 = incl2 - dv;
        if (excl2 < resid && resid <= incl2) s_pick = tid;
    }
    __syncthreads();
    int idx = sst + s_pick;
    if (idx > N - 1) idx = N - 1;

    if (tid < D) {
        float cv = x[(size_t)idx * D + tid];
        g_centers[i * D + tid] = cv;
        s_sq[tid] = (double)cv * (double)cv;
    }
    __syncthreads();
    for (int sft = 128; sft; sft >>= 1) {
        if (tid < sft) s_sq[tid] += s_sq[tid + sft];
        __syncthreads();
    }
    if (tid == 0) g_csq[i] = (float)s_sq[0];
}

// ---------------------------------------------------------------------------
// Persistent iteration kernel (ulonglong2 loads, 4-lane groups for K<=4).
// ---------------------------------------------------------------------------
template <int K>
__global__ void __launch_bounds__(T1) k_iter(const float* __restrict__ x,
                                             float* __restrict__ out_r,
                                             float* __restrict__ out_c,
                                             int N) {
    constexpr int G = (K <= 4) ? 4 : 8;   // reduction group size
    __shared__ float4 s_acc4[K * 64];
    __shared__ float  s_cnt[K];
    __shared__ double s_part[4][64][4];
    __shared__ double s_cntv;
    __shared__ double s_v[128];

    int tid  = threadIdx.x;
    int lane = tid & 31;
    int warp = tid >> 5;
    int bid  = blockIdx.x;
    int jl   = lane & (G - 1);
    int maxit = g_maxiters;

    if (maxit < 1) {
        size_t tot = (size_t)N * K;
        for (size_t i = (size_t)bid * T1 + tid; i < tot; i += (size_t)GRID1 * T1)
            out_r[i] = 0.f;
        if (bid == 0)
            for (int i = tid; i < K * D; i += T1) out_c[i] = g_centers[i];
        return;
    }

    float w_l = (jl < K) ? __ldg(&g_w[jl]) : 0.f;

    for (int t = 0; t < maxit; t++) {
        float csq_l = (jl < K) ? __ldcg(&g_csq[jl]) : 0.f;
        u64 c_pk[K][4];
        const float4* cb = (const float4*)g_centers;
        #pragma unroll
        for (int j = 0; j < K; j++) {
            float4 c0 = __ldcg(cb + j * 64 + lane);
            float4 c1 = __ldcg(cb + j * 64 + 32 + lane);
            c_pk[j][0] = pk2(c0.x, c0.y); c_pk[j][1] = pk2(c0.z, c0.w);
            c_pk[j][2] = pk2(c1.x, c1.y); c_pk[j][3] = pk2(c1.z, c1.w);
        }
        for (int i = tid; i < K * 64; i += T1) s_acc4[i] = make_float4(0.f, 0.f, 0.f, 0.f);
        if (tid < K) s_cnt[tid] = 0.f;
        __syncthreads();

        u64 acc2[K][4];
        #pragma unroll
        for (int j = 0; j < K; j++) {
            #pragma unroll
            for (int u = 0; u < 4; u++) acc2[j][u] = 0ull;
        }
        float cnt_l = 0.f;

        // ---- main pass: two interleaved rows; x as packed u64 pairs ----
        // NOTE: ulonglong2 = 16B = 4 floats -> row stride = D/4 elements.
        int row = bid * NW1 + warp;
        while (row + TOT_W < N) {
            int rA = row, rB = row + TOT_W;
            const ulonglong2* xA = (const ulonglong2*)x + (size_t)rA * (D / 4);
            const ulonglong2* xB = (const ulonglong2*)x + (size_t)rB * (D / 4);
            ulonglong2 vA0 = __ldg(xA + lane);
            ulonglong2 vB0 = __ldg(xB + lane);
            ulonglong2 vA1 = __ldg(xA + lane + 32);
            ulonglong2 vB1 = __ldg(xB + lane + 32);
            float  xsA = __ldg(g_xsq + rA);
            float  xsB = __ldg(g_xsq + rB);
            u64 pA0 = vA0.x, pA1 = vA0.y, pA2 = vA1.x, pA3 = vA1.y;
            u64 pB0 = vB0.x, pB1 = vB0.y, pB2 = vB1.x, pB3 = vB1.y;
            float dpA[K], dpB[K];
            #pragma unroll
            for (int j = 0; j < K; j++) {
                u64 tA = mul2(pA0, c_pk[j][0]);
                u64 tB = mul2(pB0, c_pk[j][0]);
                tA = fma2(pA1, c_pk[j][1], tA);
                tB = fma2(pB1, c_pk[j][1], tB);
                tA = fma2(pA2, c_pk[j][2], tA);
                tB = fma2(pB2, c_pk[j][2], tB);
                tA = fma2(pA3, c_pk[j][3], tA);
                tB = fma2(pB3, c_pk[j][3], tB);
                float loA, hiA, loB, hiB;
                upk2(tA, loA, hiA); upk2(tB, loB, hiB);
                dpA[j] = loA + hiA; dpB[j] = loB + hiB;
            }
            // in-group rounds (G-lane groups)
            #pragma unroll
            for (int m = G / 2; m; m >>= 1) {
                #pragma unroll
                for (int j = 0; j < K; j++) {
                    dpA[j] += __shfl_xor_sync(0xffffffffu, dpA[j], m);
                    dpB[j] += __shfl_xor_sync(0xffffffffu, dpB[j], m);
                }
            }
            // lane selects its own cluster (jl), cross-group rounds
            float myA = dpA[0], myB = dpB[0];
            #pragma unroll
            for (int j = 1; j < K; j++) {
                bool p = (jl == j);
                myA = p ? dpA[j] : myA;
                myB = p ? dpB[j] : myB;
            }
            #pragma unroll
            for (int m = G; m < 32; m <<= 1) {
                myA += __shfl_xor_sync(0xffffffffu, myA, m);
                myB += __shfl_xor_sync(0xffffffffu, myB, m);
            }

            float dA = sqrtf(fmaxf(xsA + csq_l - 2.f * myA, 1e-12f));
            float dB = sqrtf(fmaxf(xsB + csq_l - 2.f * myB, 1e-12f));
            float eA = w_l * __expf(ESHIFT - dA);
            float eB = w_l * __expf(ESHIFT - dB);
            float sA = eA, sB = eB;
            #pragma unroll
            for (int m = 1; m < G; m <<= 1) {
                sA += __shfl_xor_sync(0xffffffffu, sA, m);
                sB += __shfl_xor_sync(0xffffffffu, sB, m);
            }
            float rvA = __fdividef(eA, sA);
            float rvB = __fdividef(eB, sB);
            if (lane < K) {
                out_r[(size_t)rA * K + lane] = rvA;
                out_r[(size_t)rB * K + lane] = rvB;
            }
            cnt_l += rvA + rvB;
            #pragma unroll
            for (int j = 0; j < K; j++) {
                float rbA = __shfl_sync(0xffffffffu, rvA, j);
                float rbB = __shfl_sync(0xffffffffu, rvB, j);
                u64 r2A = pk2(rbA, rbA);
                u64 r2B = pk2(rbB, rbB);
                acc2[j][0] = fma2(r2A, pA0, acc2[j][0]);
                acc2[j][1] = fma2(r2A, pA1, acc2[j][1]);
                acc2[j][2] = fma2(r2A, pA2, acc2[j][2]);
                acc2[j][3] = fma2(r2A, pA3, acc2[j][3]);
                acc2[j][0] = fma2(r2B, pB0, acc2[j][0]);
                acc2[j][1] = fma2(r2B, pB1, acc2[j][1]);
                acc2[j][2] = fma2(r2B, pB2, acc2[j][2]);
                acc2[j][3] = fma2(r2B, pB3, acc2[j][3]);
            }
            row += 2 * TOT_W;
        }
        if (row < N) {  // single-row tail
            const ulonglong2* xr = (const ulonglong2*)x + (size_t)row * (D / 4);
            ulonglong2 v0 = __ldg(xr + lane);
            ulonglong2 v1 = __ldg(xr + lane + 32);
            float  xs = __ldg(g_xsq + row);
            u64 p0 = v0.x, p1 = v0.y, p2 = v1.x, p3 = v1.y;
            float dp[K];
            #pragma unroll
            for (int j = 0; j < K; j++) {
                u64 tt = mul2(p0, c_pk[j][0]);
                tt = fma2(p1, c_pk[j][1], tt);
                tt = fma2(p2, c_pk[j][2], tt);
                tt = fma2(p3, c_pk[j][3], tt);
                float lo, hi; upk2(tt, lo, hi);
                dp[j] = lo + hi;
            }
            #pragma unroll
            for (int m = G / 2; m; m >>= 1) {
                #pragma unroll
                for (int j = 0; j < K; j++)
                    dp[j] += __shfl_xor_sync(0xffffffffu, dp[j], m);
            }
            float myv = dp[0];
            #pragma unroll
            for (int j = 1; j < K; j++) myv = (jl == j) ? dp[j] : myv;
            #pragma unroll
            for (int m = G; m < 32; m <<= 1)
                myv += __shfl_xor_sync(0xffffffffu, myv, m);
            float dval = sqrtf(fmaxf(xs + csq_l - 2.f * myv, 1e-12f));
            float ev   = w_l * __expf(ESHIFT - dval);
            float ssum = ev;
            #pragma unroll
            for (int m = 1; m < G; m <<= 1)
                ssum += __shfl_xor_sync(0xffffffffu, ssum, m);
            float rv = __fdividef(ev, ssum);
            if (lane < K) out_r[(size_t)row * K + lane] = rv;
            cnt_l += rv;
            #pragma unroll
            for (int j = 0; j < K; j++) {
                float rb = __shfl_sync(0xffffffffu, rv, j);
                u64 r2 = pk2(rb, rb);
                acc2[j][0] = fma2(r2, p0, acc2[j][0]);
                acc2[j][1] = fma2(r2, p1, acc2[j][1]);
                acc2[j][2] = fma2(r2, p2, acc2[j][2]);
                acc2[j][3] = fma2(r2, p3, acc2[j][3]);
            }
        }

        // ---- deterministic sequential warp combine ----
        for (int w = 0; w < NW1; w++) {
            if (warp == w) {
                #pragma unroll
                for (int j = 0; j < K; j++) {
                    float lo0, hi0, lo1, hi1;
                    float4 v = s_acc4[j * 64 + lane];
                    upk2(acc2[j][0], lo0, hi0);
                    upk2(acc2[j][1], lo1, hi1);
                    v.x += lo0; v.y += hi0; v.z += lo1; v.w += hi1;
                    s_acc4[j * 64 + lane] = v;
                    v = s_acc4[j * 64 + 32 + lane];
                    upk2(acc2[j][2], lo0, hi0);
                    upk2(acc2[j][3], lo1, hi1);
                    v.x += lo0; v.y += hi0; v.z += lo1; v.w += hi1;
                    s_acc4[j * 64 + 32 + lane] = v;
                }
                if (lane < K) s_cnt[lane] += cnt_l;
            }
            __syncthreads();
        }
        {
            float4* Pb = (float4*)(g_P + (size_t)bid * (KMAX * D));
            for (int i = tid; i < K * 64; i += T1) Pb[i] = s_acc4[i];
            if (tid < K) g_Pc[bid * KMAX + tid] = s_cnt[tid];
        }

        // ---- barrier 1 (flag-based): stamp own flag; only updaters wait ----
        __syncthreads();
        __threadfence();
        if (tid == 0) st_cg_i32(&g_flag_main[bid * FPAD], t + 1);

        if (bid < K) {
            if (warp == 0) {
                int need = t + 1;
                bool done_poll = false;
                while (!done_poll) {
                    bool ok = true;
                    for (int p = lane; p < GRID1; p += 32)
                        ok &= (ld_cg_i32(&g_flag_main[p * FPAD]) >= need);
                    done_poll = __all_sync(0xffffffffu, ok);
                    if (!done_poll) __nanosleep(64);
                }
                __threadfence();
            }
            __syncthreads();

            int j = bid;
            if (warp == 8) {
                double c = 0.0;
                for (int p = lane; p < GRID1; p += 32)
                    c += (double)__ldcg(&g_Pc[p * KMAX + j]);
                #pragma unroll
                for (int m = 16; m; m >>= 1)
                    c += __shfl_xor_sync(0xffffffffu, c, m);
                if (lane == 0) s_cntv = c;
            }
            if (tid < 256) {
                int g = tid >> 6, i4 = tid & 63;
                int pst = g * 37;
                int pen = min(GRID1, pst + 37);
                const float4* base = (const float4*)g_P + (size_t)j * (D / 4) + i4;
                const int S4 = KMAX * D / 4;
                double dx = 0.0, dy = 0.0, dz = 0.0, dw = 0.0;
                int p = pst;
                for (; p + 8 <= pen; p += 8) {
                    float4 v0 = __ldcg(base + (size_t)(p + 0) * S4);
                    float4 v1 = __ldcg(base + (size_t)(p + 1) * S4);
                    float4 v2 = __ldcg(base + (size_t)(p + 2) * S4);
                    float4 v3 = __ldcg(base + (size_t)(p + 3) * S4);
                    float4 v4 = __ldcg(base + (size_t)(p + 4) * S4);
                    float4 v5 = __ldcg(base + (size_t)(p + 5) * S4);
                    float4 v6 = __ldcg(base + (size_t)(p + 6) * S4);
                    float4 v7 = __ldcg(base + (size_t)(p + 7) * S4);
                    dx += (((double)v0.x + (double)v1.x) + ((double)v2.x + (double)v3.x))
                        + (((double)v4.x + (double)v5.x) + ((double)v6.x + (double)v7.x));
                    dy += (((double)v0.y + (double)v1.y) + ((double)v2.y + (double)v3.y))
                        + (((double)v4.y + (double)v5.y) + ((double)v6.y + (double)v7.y));
                    dz += (((double)v0.z + (double)v1.z) + ((double)v2.z + (double)v3.z))
                        + (((double)v4.z + (double)v5.z) + ((double)v6.z + (double)v7.z));
                    dw += (((double)v0.w + (double)v1.w) + ((double)v2.w + (double)v3.w))
                        + (((double)v4.w + (double)v5.w) + ((double)v6.w + (double)v7.w));
                }
                for (; p < pen; p++) {
                    float4 v = __ldcg(base + (size_t)p * S4);
                    dx += (double)v.x; dy += (double)v.y;
                    dz += (double)v.z; dw += (double)v.w;
                }
                s_part[g][i4][0] = dx; s_part[g][i4][1] = dy;
                s_part[g][i4][2] = dz; s_part[g][i4][3] = dw;
            }
            __syncthreads();
            if (tid < 64) {
                double cnt = s_cntv;
                double sx = (s_part[0][tid][0] + s_part[1][tid][0])
                          + (s_part[2][tid][0] + s_part[3][tid][0]);
                double sy = (s_part[0][tid][1] + s_part[1][tid][1])
                          + (s_part[2][tid][1] + s_part[3][tid][1]);
                double sz = (s_part[0][tid][2] + s_part[1][tid][2])
                          + (s_part[2][tid][2] + s_part[3][tid][2]);
                double sw = (s_part[0][tid][3] + s_part[1][tid][3])
                          + (s_part[2][tid][3] + s_part[3][tid][3]);
                float n0 = (float)(sx / cnt), n1 = (float)(sy / cnt);
                float n2 = (float)(sz / cnt), n3 = (float)(sw / cnt);
                int e4 = j * (D / 4) + tid;
                ((float4*)g_centers)[e4] = make_float4(n0, n1, n2, n3);
                float4 pv = ((float4*)g_prev)[e4];
                ((float4*)g_prev)[e4] = make_float4(n0, n1, n2, n3);
                double d0 = (double)(n0 - pv.x), d1 = (double)(n1 - pv.y);
                double d2 = (double)(n2 - pv.z), d3 = (double)(n3 - pv.w);
                s_v[tid]      = (d0 * d0 + d1 * d1) + (d2 * d2 + d3 * d3);
                s_v[64 + tid] = ((double)n0 * n0 + (double)n1 * n1)
                              + ((double)n2 * n2 + (double)n3 * n3);
            }
            __syncthreads();
            if (warp == 0) {
                double a = s_v[lane] + s_v[lane + 32];
                #pragma unroll
                for (int m = 16; m; m >>= 1)
                    a += __shfl_xor_sync(0xffffffffu, a, m);
                if (lane == 0) g_shiftp[j] = a;
            } else if (warp == 1) {
                double a = s_v[64 + lane] + s_v[96 + lane];
                #pragma unroll
                for (int m = 16; m; m >>= 1)
                    a += __shfl_xor_sync(0xffffffffu, a, m);
                if (lane == 0) g_csq[j] = (float)a;
            }
            __syncthreads();
            __threadfence();
            if (tid == 0) st_cg_i32(&g_flag_upd[j * FPAD], t + 1);
        }

        // ---- barrier 2 (flag-based): everyone waits for the K upd flags ----
        if (warp == 0) {
            int need = t + 1;
            bool done_poll = false;
            while (!done_poll) {
                bool ok = (lane >= K) || (ld_cg_i32(&g_flag_upd[lane * FPAD]) >= need);
                done_poll = __all_sync(0xffffffffu, ok);
                if (!done_poll) __nanosleep(64);
            }
            __threadfence();
        }
        __syncthreads();

        double sh = 0.0;
        #pragma unroll
        for (int j = 0; j < K; j++) sh += __ldcg(&g_shiftp[j]);
        if (sqrt(sh) < TOLV) break;
    }

    if (bid == 0)
        for (int i = tid; i < K * D; i += T1) out_c[i] = __ldcg(&g_centers[i]);
}

// ---------------------------------------------------------------------------
extern "C" void kernel_launch(void* const* d_in, const int* in_sizes, int n_in,
                              void* d_out, int out_size) {
    const float* x      = (const float*)d_in[0];
    const float* logits = (const float*)d_in[1];
    const float* gumbel = (const float*)d_in[2];
    const float* uinit  = (const float*)d_in[3];
    const int*   maxit  = (const int*)d_in[4];

    int N = in_sizes[0] / D;
    int k = out_size / (N + D);
    if (k < 1) k = 1;
    if (k > KMAX) k = KMAX;

    float* out_c = (float*)d_out;
    float* out_r = out_c + (size_t)k * D;

    k_init<<<1, 256>>>(x, logits, gumbel, uinit, maxit, N);
    if (k == 1) {
        k_xsq<<<DB, TM>>>(x, N);
    } else {
        for (int i = 1; i < k; i++) {
            k_dmin<<<DB, TM>>>(x, N, i);           // pass 1 also fills g_xsq
            k_select<<<1, 1024>>>(x, uinit, N, i);
        }
    }
    switch (k) {
        case 1: k_iter<1><<<GRID1, T1>>>(x, out_r, out_c, N); break;
        case 2: k_iter<2><<<GRID1, T1>>>(x, out_r, out_c, N); break;
        case 3: k_iter<3><<<GRID1, T1>>>(x, out_r, out_c, N); break;
        case 4: k_iter<4><<<GRID1, T1>>>(x, out_r, out_c, N); break;
        case 5: k_iter<5><<<GRID1, T1>>>(x, out_r, out_c, N); break;
        default: k_iter<6><<<GRID1, T1>>>(x, out_r, out_c, N); break;
    }
}

// round 16
// speedup vs baseline: 1.6579x; 1.0095x over previous
#include <cuda_runtime.h>
#include <math.h>

// ---------------------------------------------------------------------------
// SoftCluster_adaptiveK — round 16 (= R15 + updater offload + tree combine)
//  * contiguous per-block row chunks; updater blocks (0..K-1) get 56 fewer
//    rows to hide their ~1us center-update on the critical path
//  * log-tree warp combine 12->6->3->1 (7 syncs, was 12)
// ---------------------------------------------------------------------------

#define D      256
#define KMAX   6
#define GRID1  148
#define T1     384
#define NW1    (T1 / 32)
#define DB     592
#define TM     256
#define TOLV   1e-5
#define ESHIFT 24.0f
#define FPAD   8
#define OFFL   56

typedef unsigned long long u64;

// ---- device scratch (static; no allocation anywhere) ----
__device__ float  g_centers[KMAX * D];
__device__ float  g_prev[KMAX * D];
__device__ float  g_csq[KMAX];
__device__ float  g_w[KMAX];
__device__ float  g_P[GRID1 * KMAX * D];
__device__ float  g_Pc[GRID1 * KMAX];
__device__ double g_shiftp[KMAX];
__device__ float  g_dmin[131072];
__device__ float  g_xsq[131072];
__device__ double g_bsum[DB];
__device__ int    g_flag_main[GRID1 * FPAD];
__device__ int    g_flag_upd[KMAX * FPAD];
__device__ int    g_maxiters;
__device__ int    g_idx;

// ---- helpers ----
__device__ __forceinline__ u64 pk2(float lo, float hi) {
    u64 r; asm("mov.b64 %0,{%1,%2};" : "=l"(r) : "f"(lo), "f"(hi)); return r;
}
__device__ __forceinline__ void upk2(u64 v, float& lo, float& hi) {
    asm("mov.b64 {%0,%1},%2;" : "=f"(lo), "=f"(hi) : "l"(v));
}
__device__ __forceinline__ u64 fma2(u64 a, u64 b, u64 c) {
    u64 r; asm("fma.rn.f32x2 %0,%1,%2,%3;" : "=l"(r) : "l"(a), "l"(b), "l"(c)); return r;
}
__device__ __forceinline__ u64 mul2(u64 a, u64 b) {
    u64 r; asm("mul.rn.f32x2 %0,%1,%2;" : "=l"(r) : "l"(a), "l"(b)); return r;
}
__device__ __forceinline__ float wsum(float v) {
    #pragma unroll
    for (int m = 16; m; m >>= 1) v += __shfl_xor_sync(0xffffffffu, v, m);
    return v;
}
__device__ __forceinline__ float dot4(float4 a, float4 b) {
    return a.x * b.x + a.y * b.y + a.z * b.z + a.w * b.w;
}
__device__ __forceinline__ int ld_cg_i32(const int* p) {
    int v; asm volatile("ld.global.cg.b32 %0, [%1];" : "=r"(v) : "l"(p)); return v;
}
__device__ __forceinline__ void st_cg_i32(int* p, int v) {
    asm volatile("st.global.cg.b32 [%0], %1;" :: "l"(p), "r"(v) : "memory");
}

// ---------------------------------------------------------------------------
__global__ void k_init(const float* __restrict__ x,
                       const float* __restrict__ logits,
                       const float* __restrict__ gumbel,
                       const float* __restrict__ uinit,
                       const int*   __restrict__ maxit,
                       int N) {
    __shared__ double s_sq[256];
    int tid = threadIdx.x;
    if (tid == 0) {
        g_maxiters = maxit[0];
        float l[KMAX]; float m = -3.4e38f;
        for (int j = 0; j < KMAX; j++) { l[j] = logits[j] + gumbel[j]; m = fmaxf(m, l[j]); }
        float s = 0.f, e[KMAX];
        for (int j = 0; j < KMAX; j++) { e[j] = expf(l[j] - m); s += e[j]; }
        for (int j = 0; j < KMAX; j++) g_w[j] = e[j] / s;
        float f = uinit[0] * (float)N;
        int idx = (int)f;
        if (idx > N - 1) idx = N - 1;
        if (idx < 0) idx = 0;
        g_idx = idx;
    }
    for (int i = tid; i < KMAX * D; i += blockDim.x) g_prev[i] = 0.f;
    for (int i = tid; i < GRID1 * FPAD; i += blockDim.x) g_flag_main[i] = 0;
    for (int i = tid; i < KMAX * FPAD; i += blockDim.x) g_flag_upd[i] = 0;
    __syncthreads();
    int idx = g_idx;
    float v = x[(size_t)idx * D + tid];
    g_centers[tid] = v;
    s_sq[tid] = (double)v * (double)v;
    __syncthreads();
    for (int s = 128; s; s >>= 1) {
        if (tid < s) s_sq[tid] += s_sq[tid + s];
        __syncthreads();
    }
    if (tid == 0) g_csq[0] = (float)s_sq[0];
}

// ---------------------------------------------------------------------------
// xsq only (used when k == 1)
// ---------------------------------------------------------------------------
__global__ void __launch_bounds__(TM) k_xsq(const float* __restrict__ x, int N) {
    int tid = threadIdx.x;
    int lane = tid & 31;
    int gwarp = blockIdx.x * (TM / 32) + (tid >> 5);
    int tot = DB * (TM / 32);
    for (int row = gwarp; row < N; row += tot) {
        const float4* xr = (const float4*)x + (size_t)row * (D / 4);
        float4 a0 = __ldg(xr + lane);
        float4 a1 = __ldg(xr + lane + 32);
        float xs = wsum(dot4(a0, a0) + dot4(a1, a1));
        if (lane == 0) g_xsq[row] = xs;
    }
}

// ---------------------------------------------------------------------------
// k-means++ pass over CONTIGUOUS chunk, 4-row interleaved.
// Pass 1 (i==1) also computes and stores xsq.
// ---------------------------------------------------------------------------
__global__ void __launch_bounds__(TM) k_dmin(const float* __restrict__ x, int N, int i) {
    __shared__ float  s_c[D];
    __shared__ float  s_cs;
    __shared__ double s_ws[TM / 32];
    int tid = threadIdx.x;
    if (tid < D) s_c[tid] = g_centers[(i - 1) * D + tid];
    if (tid == 0) s_cs = g_csq[i - 1];
    if (tid < TM / 32) s_ws[tid] = 0.0;
    __syncthreads();
    int lane = tid & 31;
    int warp = tid >> 5;
    const int STEP = TM / 32;
    int chunk = (N + DB - 1) / DB;
    int st = blockIdx.x * chunk;
    int en = min(st + chunk, N);
    const float4* c4 = (const float4*)s_c;
    float4 c0 = c4[lane], c1 = c4[lane + 32];
    double wsumd = 0.0;

    int row = st + warp;
    while (row + 3 * STEP < en) {
        int r0 = row, r1 = row + STEP, r2 = row + 2 * STEP, r3 = row + 3 * STEP;
        const float4* x0 = (const float4*)x + (size_t)r0 * (D / 4);
        const float4* x1 = (const float4*)x + (size_t)r1 * (D / 4);
        const float4* x2 = (const float4*)x + (size_t)r2 * (D / 4);
        const float4* x3 = (const float4*)x + (size_t)r3 * (D / 4);
        float4 a00 = __ldg(x0 + lane),      a10 = __ldg(x1 + lane);
        float4 a20 = __ldg(x2 + lane),      a30 = __ldg(x3 + lane);
        float4 a01 = __ldg(x0 + lane + 32), a11 = __ldg(x1 + lane + 32);
        float4 a21 = __ldg(x2 + lane + 32), a31 = __ldg(x3 + lane + 32);
        float dp0 = dot4(a00, c0) + dot4(a01, c1);
        float dp1 = dot4(a10, c0) + dot4(a11, c1);
        float dp2 = dot4(a20, c0) + dot4(a21, c1);
        float dp3 = dot4(a30, c0) + dot4(a31, c1);
        if (i == 1) {
            float xs0 = dot4(a00, a00) + dot4(a01, a01);
            float xs1 = dot4(a10, a10) + dot4(a11, a11);
            float xs2 = dot4(a20, a20) + dot4(a21, a21);
            float xs3 = dot4(a30, a30) + dot4(a31, a31);
            #pragma unroll
            for (int m = 16; m; m >>= 1) {
                dp0 += __shfl_xor_sync(0xffffffffu, dp0, m);
                dp1 += __shfl_xor_sync(0xffffffffu, dp1, m);
                dp2 += __shfl_xor_sync(0xffffffffu, dp2, m);
                dp3 += __shfl_xor_sync(0xffffffffu, dp3, m);
                xs0 += __shfl_xor_sync(0xffffffffu, xs0, m);
                xs1 += __shfl_xor_sync(0xffffffffu, xs1, m);
                xs2 += __shfl_xor_sync(0xffffffffu, xs2, m);
                xs3 += __shfl_xor_sync(0xffffffffu, xs3, m);
            }
            if (lane == 0) {
                g_xsq[r0] = xs0; g_xsq[r1] = xs1; g_xsq[r2] = xs2; g_xsq[r3] = xs3;
                float d0 = sqrtf(fmaxf(xs0 + s_cs - 2.f * dp0, 1e-12f));
                float d1 = sqrtf(fmaxf(xs1 + s_cs - 2.f * dp1, 1e-12f));
                float d2 = sqrtf(fmaxf(xs2 + s_cs - 2.f * dp2, 1e-12f));
                float d3 = sqrtf(fmaxf(xs3 + s_cs - 2.f * dp3, 1e-12f));
                g_dmin[r0] = d0; g_dmin[r1] = d1; g_dmin[r2] = d2; g_dmin[r3] = d3;
                wsumd += ((double)d0 + (double)d1) + ((double)d2 + (double)d3);
            }
        } else {
            #pragma unroll
            for (int m = 16; m; m >>= 1) {
                dp0 += __shfl_xor_sync(0xffffffffu, dp0, m);
                dp1 += __shfl_xor_sync(0xffffffffu, dp1, m);
                dp2 += __shfl_xor_sync(0xffffffffu, dp2, m);
                dp3 += __shfl_xor_sync(0xffffffffu, dp3, m);
            }
            if (lane == 0) {
                float d0 = sqrtf(fmaxf(g_xsq[r0] + s_cs - 2.f * dp0, 1e-12f));
                float d1 = sqrtf(fmaxf(g_xsq[r1] + s_cs - 2.f * dp1, 1e-12f));
                float d2 = sqrtf(fmaxf(g_xsq[r2] + s_cs - 2.f * dp2, 1e-12f));
                float d3 = sqrtf(fmaxf(g_xsq[r3] + s_cs - 2.f * dp3, 1e-12f));
                float n0 = fminf(g_dmin[r0], d0);
                float n1 = fminf(g_dmin[r1], d1);
                float n2 = fminf(g_dmin[r2], d2);
                float n3 = fminf(g_dmin[r3], d3);
                g_dmin[r0] = n0; g_dmin[r1] = n1; g_dmin[r2] = n2; g_dmin[r3] = n3;
                wsumd += ((double)n0 + (double)n1) + ((double)n2 + (double)n3);
            }
        }
        row += 4 * STEP;
    }
    while (row < en) {
        const float4* xr = (const float4*)x + (size_t)row * (D / 4);
        float4 a0 = __ldg(xr + lane);
        float4 a1 = __ldg(xr + lane + 32);
        float dp = dot4(a0, c0) + dot4(a1, c1);
        if (i == 1) {
            float xs = dot4(a0, a0) + dot4(a1, a1);
            #pragma unroll
            for (int m = 16; m; m >>= 1) {
                dp += __shfl_xor_sync(0xffffffffu, dp, m);
                xs += __shfl_xor_sync(0xffffffffu, xs, m);
            }
            if (lane == 0) {
                g_xsq[row] = xs;
                float d = sqrtf(fmaxf(xs + s_cs - 2.f * dp, 1e-12f));
                g_dmin[row] = d;
                wsumd += (double)d;
            }
        } else {
            dp = wsum(dp);
            if (lane == 0) {
                float d = sqrtf(fmaxf(g_xsq[row] + s_cs - 2.f * dp, 1e-12f));
                float nd = fminf(g_dmin[row], d);
                g_dmin[row] = nd;
                wsumd += (double)nd;
            }
        }
        row += STEP;
    }
    if (lane == 0) s_ws[warp] = wsumd;
    __syncthreads();
    if (tid == 0) {
        double s = 0.0;
        #pragma unroll
        for (int w = 0; w < TM / 32; w++) s += s_ws[w];
        g_bsum[blockIdx.x] = s;
    }
}

// ---------------------------------------------------------------------------
// k-means++ select: two-level warp-shuffle scans (1024 threads = 32 warps).
// ---------------------------------------------------------------------------
__global__ void k_select(const float* __restrict__ x,
                         const float* __restrict__ uinit,
                         int N, int i) {
    __shared__ double s_wtot[32];
    __shared__ double s_sq[256];
    __shared__ double s_base;
    __shared__ int    s_pick;
    int tid  = threadIdx.x;
    int lane = tid & 31;
    int warp = tid >> 5;
    int chunk = (N + DB - 1) / DB;

    double v = (tid < DB) ? g_bsum[tid] : 0.0;
    double s = v;
    #pragma unroll
    for (int off = 1; off < 32; off <<= 1) {
        double n = __shfl_up_sync(0xffffffffu, s, off);
        if (lane >= off) s += n;
    }
    if (lane == 31) s_wtot[warp] = s;
    __syncthreads();
    if (warp == 0) {
        double t = s_wtot[lane];
        #pragma unroll
        for (int off = 1; off < 32; off <<= 1) {
            double n = __shfl_up_sync(0xffffffffu, t, off);
            if (lane >= off) t += n;
        }
        s_wtot[lane] = t;
    }
    __syncthreads();
    double incl  = s + (warp ? s_wtot[warp - 1] : 0.0);
    double total = s_wtot[31];
    double target = (double)uinit[i] * total;
    if (tid == 0) { s_pick = DB - 1; s_base = total - g_bsum[DB - 1]; }
    __syncthreads();
    if (tid < DB) {
        double excl = incl - v;
        if (excl < target && target <= incl) { s_pick = tid; s_base = excl; }
    }
    __syncthreads();
    int    tb    = s_pick;
    double resid = target - s_base;
    int sst = tb * chunk;
    int sen = min(sst + chunk, N);
    int cnt = sen - sst;
    __syncthreads();

    double dv = (tid < cnt) ? (double)g_dmin[sst + tid] : 0.0;
    double s2 = dv;
    #pragma unroll
    for (int off = 1; off < 32; off <<= 1) {
        double n = __shfl_up_sync(0xffffffffu, s2, off);
        if (lane >= off) s2 += n;
    }
    if (lane == 31) s_wtot[warp] = s2;
    __syncthreads();
    if (warp == 0) {
        double t = s_wtot[lane];
        #pragma unroll
        for (int off = 1; off < 32; off <<= 1) {
            double n = __shfl_up_sync(0xffffffffu, t, off);
            if (lane >= off) t += n;
        }
        s_wtot[lane] = t;
    }
    __syncthreads();
    double incl2 = s2 + (warp ? s_wtot[warp - 1] : 0.0);
    if (tid == 0) s_pick = cnt - 1;
    __syncthreads();
    if (tid < cnt) {
        double excl2 = incl2 - dv;
        if (excl2 < resid && resid <= incl2) s_pick = tid;
    }
    __syncthreads();
    int idx = sst + s_pick;
    if (idx > N - 1) idx = N - 1;

    if (tid < D) {
        float cv = x[(size_t)idx * D + tid];
        g_centers[i * D + tid] = cv;
        s_sq[tid] = (double)cv * (double)cv;
    }
    __syncthreads();
    for (int sft = 128; sft; sft >>= 1) {
        if (tid < sft) s_sq[tid] += s_sq[tid + sft];
        __syncthreads();
    }
    if (tid == 0) g_csq[i] = (float)s_sq[0];
}

// ---------------------------------------------------------------------------
// Persistent iteration kernel: contiguous chunks with updater offload,
// log-tree combine, flag barriers.
// ---------------------------------------------------------------------------
template <int K>
__global__ void __launch_bounds__(T1) k_iter(const float* __restrict__ x,
                                             float* __restrict__ out_r,
                                             float* __restrict__ out_c,
                                             int N) {
    constexpr int G = (K <= 4) ? 4 : 8;
    __shared__ float4 s_slot[6][K * 64];
    __shared__ float  s_cntw[NW1][8];
    __shared__ double s_part[4][64][4];
    __shared__ double s_cntv;
    __shared__ double s_v[128];

    int tid  = threadIdx.x;
    int lane = tid & 31;
    int warp = tid >> 5;
    int bid  = blockIdx.x;
    int jl   = lane & (G - 1);
    int maxit = g_maxiters;

    if (maxit < 1) {
        size_t tot = (size_t)N * K;
        for (size_t i = (size_t)bid * T1 + tid; i < tot; i += (size_t)GRID1 * T1)
            out_r[i] = 0.f;
        if (bid == 0)
            for (int i = tid; i < K * D; i += T1) out_c[i] = g_centers[i];
        return;
    }

    // contiguous chunk; updater blocks (bid < K) get OFFL fewer rows
    int Cb = (N + K * OFFL + GRID1 - 1) / GRID1;
    int Cs = Cb - OFFL;
    int st0 = (bid < K) ? bid * Cs : K * Cs + (bid - K) * Cb;
    int sz  = (bid < K) ? Cs : Cb;
    int cst = min(st0, N);
    int cen = min(st0 + sz, N);

    float w_l = (jl < K) ? __ldg(&g_w[jl]) : 0.f;

    for (int t = 0; t < maxit; t++) {
        float csq_l = (jl < K) ? __ldcg(&g_csq[jl]) : 0.f;
        u64 c_pk[K][4];
        const float4* cb = (const float4*)g_centers;
        #pragma unroll
        for (int j = 0; j < K; j++) {
            float4 c0 = __ldcg(cb + j * 64 + lane);
            float4 c1 = __ldcg(cb + j * 64 + 32 + lane);
            c_pk[j][0] = pk2(c0.x, c0.y); c_pk[j][1] = pk2(c0.z, c0.w);
            c_pk[j][2] = pk2(c1.x, c1.y); c_pk[j][3] = pk2(c1.z, c1.w);
        }
        u64 acc2[K][4];
        #pragma unroll
        for (int j = 0; j < K; j++) {
            #pragma unroll
            for (int u = 0; u < 4; u++) acc2[j][u] = 0ull;
        }
        float cnt_l = 0.f;

        // ---- main pass: two interleaved rows within own contiguous chunk ----
        int row = cst + warp;
        while (row + NW1 < cen) {
            int rA = row, rB = row + NW1;
            const ulonglong2* xA = (const ulonglong2*)x + (size_t)rA * (D / 4);
            const ulonglong2* xB = (const ulonglong2*)x + (size_t)rB * (D / 4);
            ulonglong2 vA0 = __ldg(xA + lane);
            ulonglong2 vB0 = __ldg(xB + lane);
            ulonglong2 vA1 = __ldg(xA + lane + 32);
            ulonglong2 vB1 = __ldg(xB + lane + 32);
            float  xsA = __ldg(g_xsq + rA);
            float  xsB = __ldg(g_xsq + rB);
            u64 pA0 = vA0.x, pA1 = vA0.y, pA2 = vA1.x, pA3 = vA1.y;
            u64 pB0 = vB0.x, pB1 = vB0.y, pB2 = vB1.x, pB3 = vB1.y;
            float dpA[K], dpB[K];
            #pragma unroll
            for (int j = 0; j < K; j++) {
                u64 tA = mul2(pA0, c_pk[j][0]);
                u64 tB = mul2(pB0, c_pk[j][0]);
                tA = fma2(pA1, c_pk[j][1], tA);
                tB = fma2(pB1, c_pk[j][1], tB);
                tA = fma2(pA2, c_pk[j][2], tA);
                tB = fma2(pB2, c_pk[j][2], tB);
                tA = fma2(pA3, c_pk[j][3], tA);
                tB = fma2(pB3, c_pk[j][3], tB);
                float loA, hiA, loB, hiB;
                upk2(tA, loA, hiA); upk2(tB, loB, hiB);
                dpA[j] = loA + hiA; dpB[j] = loB + hiB;
            }
            #pragma unroll
            for (int m = G / 2; m; m >>= 1) {
                #pragma unroll
                for (int j = 0; j < K; j++) {
                    dpA[j] += __shfl_xor_sync(0xffffffffu, dpA[j], m);
                    dpB[j] += __shfl_xor_sync(0xffffffffu, dpB[j], m);
                }
            }
            float myA = dpA[0], myB = dpB[0];
            #pragma unroll
            for (int j = 1; j < K; j++) {
                bool p = (jl == j);
                myA = p ? dpA[j] : myA;
                myB = p ? dpB[j] : myB;
            }
            #pragma unroll
            for (int m = G; m < 32; m <<= 1) {
                myA += __shfl_xor_sync(0xffffffffu, myA, m);
                myB += __shfl_xor_sync(0xffffffffu, myB, m);
            }

            float dA = sqrtf(fmaxf(xsA + csq_l - 2.f * myA, 1e-12f));
            float dB = sqrtf(fmaxf(xsB + csq_l - 2.f * myB, 1e-12f));
            float eA = w_l * __expf(ESHIFT - dA);
            float eB = w_l * __expf(ESHIFT - dB);
            float sA = eA, sB = eB;
            #pragma unroll
            for (int m = 1; m < G; m <<= 1) {
                sA += __shfl_xor_sync(0xffffffffu, sA, m);
                sB += __shfl_xor_sync(0xffffffffu, sB, m);
            }
            float rvA = __fdividef(eA, sA);
            float rvB = __fdividef(eB, sB);
            if (lane < K) {
                out_r[(size_t)rA * K + lane] = rvA;
                out_r[(size_t)rB * K + lane] = rvB;
            }
            cnt_l += rvA + rvB;
            #pragma unroll
            for (int j = 0; j < K; j++) {
                float rbA = __shfl_sync(0xffffffffu, rvA, j);
                float rbB = __shfl_sync(0xffffffffu, rvB, j);
                u64 r2A = pk2(rbA, rbA);
                u64 r2B = pk2(rbB, rbB);
                acc2[j][0] = fma2(r2A, pA0, acc2[j][0]);
                acc2[j][1] = fma2(r2A, pA1, acc2[j][1]);
                acc2[j][2] = fma2(r2A, pA2, acc2[j][2]);
                acc2[j][3] = fma2(r2A, pA3, acc2[j][3]);
                acc2[j][0] = fma2(r2B, pB0, acc2[j][0]);
                acc2[j][1] = fma2(r2B, pB1, acc2[j][1]);
                acc2[j][2] = fma2(r2B, pB2, acc2[j][2]);
                acc2[j][3] = fma2(r2B, pB3, acc2[j][3]);
            }
            row += 2 * NW1;
        }
        if (row < cen) {  // single-row tail
            const ulonglong2* xr = (const ulonglong2*)x + (size_t)row * (D / 4);
            ulonglong2 v0 = __ldg(xr + lane);
            ulonglong2 v1 = __ldg(xr + lane + 32);
            float  xs = __ldg(g_xsq + row);
            u64 p0 = v0.x, p1 = v0.y, p2 = v1.x, p3 = v1.y;
            float dp[K];
            #pragma unroll
            for (int j = 0; j < K; j++) {
                u64 tt = mul2(p0, c_pk[j][0]);
                tt = fma2(p1, c_pk[j][1], tt);
                tt = fma2(p2, c_pk[j][2], tt);
                tt = fma2(p3, c_pk[j][3], tt);
                float lo, hi; upk2(tt, lo, hi);
                dp[j] = lo + hi;
            }
            #pragma unroll
            for (int m = G / 2; m; m >>= 1) {
                #pragma unroll
                for (int j = 0; j < K; j++)
                    dp[j] += __shfl_xor_sync(0xffffffffu, dp[j], m);
            }
            float myv = dp[0];
            #pragma unroll
            for (int j = 1; j < K; j++) myv = (jl == j) ? dp[j] : myv;
            #pragma unroll
            for (int m = G; m < 32; m <<= 1)
                myv += __shfl_xor_sync(0xffffffffu, myv, m);
            float dval = sqrtf(fmaxf(xs + csq_l - 2.f * myv, 1e-12f));
            float ev   = w_l * __expf(ESHIFT - dval);
            float ssum = ev;
            #pragma unroll
            for (int m = 1; m < G; m <<= 1)
                ssum += __shfl_xor_sync(0xffffffffu, ssum, m);
            float rv = __fdividef(ev, ssum);
            if (lane < K) out_r[(size_t)row * K + lane] = rv;
            cnt_l += rv;
            #pragma unroll
            for (int j = 0; j < K; j++) {
                float rb = __shfl_sync(0xffffffffu, rv, j);
                u64 r2 = pk2(rb, rb);
                acc2[j][0] = fma2(r2, p0, acc2[j][0]);
                acc2[j][1] = fma2(r2, p1, acc2[j][1]);
                acc2[j][2] = fma2(r2, p2, acc2[j][2]);
                acc2[j][3] = fma2(r2, p3, acc2[j][3]);
            }
        }

        // ---- per-warp counts ----
        if (lane < K) s_cntw[warp][lane] = cnt_l;

        // ---- unpack accumulators ----
        float a[K][8];
        #pragma unroll
        for (int j = 0; j < K; j++) {
            upk2(acc2[j][0], a[j][0], a[j][1]);
            upk2(acc2[j][1], a[j][2], a[j][3]);
            upk2(acc2[j][2], a[j][4], a[j][5]);
            upk2(acc2[j][3], a[j][6], a[j][7]);
        }

        // ---- log-tree combine: 12 -> 6 -> 3 -> 1 (deterministic pairing) ----
        // round 1
        if (warp >= 6) {
            float4* dst = s_slot[warp - 6];
            #pragma unroll
            for (int j = 0; j < K; j++) {
                dst[j * 64 + lane]      = make_float4(a[j][0], a[j][1], a[j][2], a[j][3]);
                dst[j * 64 + 32 + lane] = make_float4(a[j][4], a[j][5], a[j][6], a[j][7]);
            }
        }
        __syncthreads();
        if (warp < 6) {
            const float4* src = s_slot[warp];
            #pragma unroll
            for (int j = 0; j < K; j++) {
                float4 v0 = src[j * 64 + lane];
                float4 v1 = src[j * 64 + 32 + lane];
                a[j][0] += v0.x; a[j][1] += v0.y; a[j][2] += v0.z; a[j][3] += v0.w;
                a[j][4] += v1.x; a[j][5] += v1.y; a[j][6] += v1.z; a[j][7] += v1.w;
            }
        }
        __syncthreads();
        // round 2
        if (warp >= 3 && warp < 6) {
            float4* dst = s_slot[warp - 3];
            #pragma unroll
            for (int j = 0; j < K; j++) {
                dst[j * 64 + lane]      = make_float4(a[j][0], a[j][1], a[j][2], a[j][3]);
                dst[j * 64 + 32 + lane] = make_float4(a[j][4], a[j][5], a[j][6], a[j][7]);
            }
        }
        __syncthreads();
        if (warp < 3) {
            const float4* src = s_slot[warp];
            #pragma unroll
            for (int j = 0; j < K; j++) {
                float4 v0 = src[j * 64 + lane];
                float4 v1 = src[j * 64 + 32 + lane];
                a[j][0] += v0.x; a[j][1] += v0.y; a[j][2] += v0.z; a[j][3] += v0.w;
                a[j][4] += v1.x; a[j][5] += v1.y; a[j][6] += v1.z; a[j][7] += v1.w;
            }
        }
        __syncthreads();
        // round 3 (3 -> 1): warps 1,2 -> slots 0,1; warp 0 adds both
        if (warp == 1 || warp == 2) {
            float4* dst = s_slot[warp - 1];
            #pragma unroll
            for (int j = 0; j < K; j++) {
                dst[j * 64 + lane]      = make_float4(a[j][0], a[j][1], a[j][2], a[j][3]);
                dst[j * 64 + 32 + lane] = make_float4(a[j][4], a[j][5], a[j][6], a[j][7]);
            }
        }
        __syncthreads();
        if (warp == 0) {
            #pragma unroll
            for (int sl = 0; sl < 2; sl++) {
                const float4* src = s_slot[sl];
                #pragma unroll
                for (int j = 0; j < K; j++) {
                    float4 v0 = src[j * 64 + lane];
                    float4 v1 = src[j * 64 + 32 + lane];
                    a[j][0] += v0.x; a[j][1] += v0.y; a[j][2] += v0.z; a[j][3] += v0.w;
                    a[j][4] += v1.x; a[j][5] += v1.y; a[j][6] += v1.z; a[j][7] += v1.w;
                }
            }
            float4* Pb = (float4*)(g_P + (size_t)bid * (KMAX * D));
            #pragma unroll
            for (int j = 0; j < K; j++) {
                Pb[j * 64 + lane]      = make_float4(a[j][0], a[j][1], a[j][2], a[j][3]);
                Pb[j * 64 + 32 + lane] = make_float4(a[j][4], a[j][5], a[j][6], a[j][7]);
            }
        }
        if (tid < K) {
            float s = 0.f;
            #pragma unroll
            for (int w = 0; w < NW1; w++) s += s_cntw[w][tid];
            g_Pc[bid * KMAX + tid] = s;
        }

        // ---- barrier 1 (flag-based): stamp own flag; only updaters wait ----
        __syncthreads();
        __threadfence();
        if (tid == 0) st_cg_i32(&g_flag_main[bid * FPAD], t + 1);

        if (bid < K) {
            if (warp == 0) {
                int need = t + 1;
                bool done_poll = false;
                while (!done_poll) {
                    bool ok = true;
                    for (int p = lane; p < GRID1; p += 32)
                        ok &= (ld_cg_i32(&g_flag_main[p * FPAD]) >= need);
                    done_poll = __all_sync(0xffffffffu, ok);
                    if (!done_poll) __nanosleep(64);
                }
                __threadfence();
            }
            __syncthreads();

            int j = bid;
            if (warp == 8) {
                double c = 0.0;
                for (int p = lane; p < GRID1; p += 32)
                    c += (double)__ldcg(&g_Pc[p * KMAX + j]);
                #pragma unroll
                for (int m = 16; m; m >>= 1)
                    c += __shfl_xor_sync(0xffffffffu, c, m);
                if (lane == 0) s_cntv = c;
            }
            if (tid < 256) {
                int g = tid >> 6, i4 = tid & 63;
                int pst = g * 37;
                int pen = min(GRID1, pst + 37);
                const float4* base = (const float4*)g_P + (size_t)j * (D / 4) + i4;
                const int S4 = KMAX * D / 4;
                double dx = 0.0, dy = 0.0, dz = 0.0, dw = 0.0;
                int p = pst;
                for (; p + 8 <= pen; p += 8) {
                    float4 v0 = __ldcg(base + (size_t)(p + 0) * S4);
                    float4 v1 = __ldcg(base + (size_t)(p + 1) * S4);
                    float4 v2 = __ldcg(base + (size_t)(p + 2) * S4);
                    float4 v3 = __ldcg(base + (size_t)(p + 3) * S4);
                    float4 v4 = __ldcg(base + (size_t)(p + 4) * S4);
                    float4 v5 = __ldcg(base + (size_t)(p + 5) * S4);
                    float4 v6 = __ldcg(base + (size_t)(p + 6) * S4);
                    float4 v7 = __ldcg(base + (size_t)(p + 7) * S4);
                    dx += (((double)v0.x + (double)v1.x) + ((double)v2.x + (double)v3.x))
                        + (((double)v4.x + (double)v5.x) + ((double)v6.x + (double)v7.x));
                    dy += (((double)v0.y + (double)v1.y) + ((double)v2.y + (double)v3.y))
                        + (((double)v4.y + (double)v5.y) + ((double)v6.y + (double)v7.y));
                    dz += (((double)v0.z + (double)v1.z) + ((double)v2.z + (double)v3.z))
                        + (((double)v4.z + (double)v5.z) + ((double)v6.z + (double)v7.z));
                    dw += (((double)v0.w + (double)v1.w) + ((double)v2.w + (double)v3.w))
                        + (((double)v4.w + (double)v5.w) + ((double)v6.w + (double)v7.w));
                }
                for (; p < pen; p++) {
                    float4 v = __ldcg(base + (size_t)p * S4);
                    dx += (double)v.x; dy += (double)v.y;
                    dz += (double)v.z; dw += (double)v.w;
                }
                s_part[g][i4][0] = dx; s_part[g][i4][1] = dy;
                s_part[g][i4][2] = dz; s_part[g][i4][3] = dw;
            }
            __syncthreads();
            if (tid < 64) {
                double cnt = s_cntv;
                double sx = (s_part[0][tid][0] + s_part[1][tid][0])
                          + (s_part[2][tid][0] + s_part[3][tid][0]);
                double sy = (s_part[0][tid][1] + s_part[1][tid][1])
                          + (s_part[2][tid][1] + s_part[3][tid][1]);
                double sz = (s_part[0][tid][2] + s_part[1][tid][2])
                          + (s_part[2][tid][2] + s_part[3][tid][2]);
                double sw = (s_part[0][tid][3] + s_part[1][tid][3])
                          + (s_part[2][tid][3] + s_part[3][tid][3]);
                float n0 = (float)(sx / cnt), n1 = (float)(sy / cnt);
                float n2 = (float)(sz / cnt), n3 = (float)(sw / cnt);
                int e4 = j * (D / 4) + tid;
                ((float4*)g_centers)[e4] = make_float4(n0, n1, n2, n3);
                float4 pv = ((float4*)g_prev)[e4];
                ((float4*)g_prev)[e4] = make_float4(n0, n1, n2, n3);
                double d0 = (double)(n0 - pv.x), d1 = (double)(n1 - pv.y);
                double d2 = (double)(n2 - pv.z), d3 = (double)(n3 - pv.w);
                s_v[tid]      = (d0 * d0 + d1 * d1) + (d2 * d2 + d3 * d3);
                s_v[64 + tid] = ((double)n0 * n0 + (double)n1 * n1)
                              + ((double)n2 * n2 + (double)n3 * n3);
            }
            __syncthreads();
            if (warp == 0) {
                double aa = s_v[lane] + s_v[lane + 32];
                #pragma unroll
                for (int m = 16; m; m >>= 1)
                    aa += __shfl_xor_sync(0xffffffffu, aa, m);
                if (lane == 0) g_shiftp[j] = aa;
            } else if (warp == 1) {
                double aa = s_v[64 + lane] + s_v[96 + lane];
                #pragma unroll
                for (int m = 16; m; m >>= 1)
                    aa += __shfl_xor_sync(0xffffffffu, aa, m);
                if (lane == 0) g_csq[j] = (float)aa;
            }
            __syncthreads();
            __threadfence();
            if (tid == 0) st_cg_i32(&g_flag_upd[j * FPAD], t + 1);
        }

        // ---- barrier 2 (flag-based): everyone waits for the K upd flags ----
        if (warp == 0) {
            int need = t + 1;
            bool done_poll = false;
            while (!done_poll) {
                bool ok = (lane >= K) || (ld_cg_i32(&g_flag_upd[lane * FPAD]) >= need);
                done_poll = __all_sync(0xffffffffu, ok);
                if (!done_poll) __nanosleep(64);
            }
            __threadfence();
        }
        __syncthreads();

        double sh = 0.0;
        #pragma unroll
        for (int j = 0; j < K; j++) sh += __ldcg(&g_shiftp[j]);
        if (sqrt(sh) < TOLV) break;
    }

    if (bid == 0)
        for (int i = tid; i < K * D; i += T1) out_c[i] = __ldcg(&g_centers[i]);
}

// ---------------------------------------------------------------------------
extern "C" void kernel_launch(void* const* d_in, const int* in_sizes, int n_in,
                              void* d_out, int out_size) {
    const float* x      = (const float*)d_in[0];
    const float* logits = (const float*)d_in[1];
    const float* gumbel = (const float*)d_in[2];
    const float* uinit  = (const float*)d_in[3];
    const int*   maxit  = (const int*)d_in[4];

    int N = in_sizes[0] / D;
    int k = out_size / (N + D);
    if (k < 1) k = 1;
    if (k > KMAX) k = KMAX;

    float* out_c = (float*)d_out;
    float* out_r = out_c + (size_t)k * D;

    k_init<<<1, 256>>>(x, logits, gumbel, uinit, maxit, N);
    if (k == 1) {
        k_xsq<<<DB, TM>>>(x, N);
    } else {
        for (int i = 1; i < k; i++) {
            k_dmin<<<DB, TM>>>(x, N, i);           // pass 1 also fills g_xsq
            k_select<<<1, 1024>>>(x, uinit, N, i);
        }
    }
    switch (k) {
        case 1: k_iter<1><<<GRID1, T1>>>(x, out_r, out_c, N); break;
        case 2: k_iter<2><<<GRID1, T1>>>(x, out_r, out_c, N); break;
        case 3: k_iter<3><<<GRID1, T1>>>(x, out_r, out_c, N); break;
        case 4: k_iter<4><<<GRID1, T1>>>(x, out_r, out_c, N); break;
        case 5: k_iter<5><<<GRID1, T1>>>(x, out_r, out_c, N); break;
        default: k_iter<6><<<GRID1, T1>>>(x, out_r, out_c, N); break;
    }
}